// round 2
// baseline (speedup 1.0000x reference)
#include <cuda_runtime.h>

#define NP   4096
#define NN   50
#define NE   250
#define NEM  65536
#define IND  32
#define PHD  512
#define ROD  64
#define HIDD 256
#define RHD  128
#define OUTD 15

// ---------------- persistent device scratch (no allocs allowed) ----------------
__device__ float g_readout[NP * ROD];     // 1 MB
__device__ float g_degi[NP], g_dego[NP], g_nim[NP], g_nom[NP];
__device__ float g_magg1[NP * ROD];       // 1 MB
__device__ float g_h1m[NP * HIDD];        // 4 MB
__device__ float g_magg2[NP * HIDD];      // 4 MB
__device__ float g_r[RHD];
__device__ int   g_poff[NN + 1];
__device__ int   g_peid[NE];

// ---------------- patch kernel shared-memory layout ----------------
// NOTE: eoff padded to 52 ints so that h1 lands 8-byte aligned (float2 access).
struct PS {
    int   src[NE];           // 1000 B
    int   dst[NE];           // 1000 B
    int   eoff[NN + 2];      // 208 B  (51 used + 1 pad)
    int   eid[NE];           // 1000 B
    float coef[NE];          // 1000 B
    float ni[NN];            // 200 B
    float no_[NN];           // 200 B
    float x[NN * IND];       // 6400 B  input features
    float agg[NN * IND];     // 6400 B  layer-1 aggregated + ni-scaled
    float y[NN * ROD];       // 12800 B h1 @ W2p
    float agg2v[NN * ROD];   // 12800 B relu(ni*agg(y)+b2p)
    float h1[25 * PHD];      // 51200 B layer-1 activations / layer-2 partials (8B-aligned)
};
// sizeof(PS) = 94208 B -> 2 CTAs/SM

// ---------------- misc small kernels ----------------
__global__ void k_zero() {
    int i = blockIdx.x * 256 + threadIdx.x;
    if (i < NP * HIDD) g_magg2[i] = 0.f;
    if (i < NP * ROD)  g_magg1[i] = 0.f;
    if (i < NP) { g_degi[i] = 0.f; g_dego[i] = 0.f; }
    if (i < RHD) g_r[i] = 0.f;
}

// deterministic CSR build (patch topology identical for all patches)
__global__ void k_csr(const int* __restrict__ pedges) {
    if (threadIdx.x != 0 || blockIdx.x != 0) return;
    int cnt[NN];
    for (int n = 0; n < NN; n++) cnt[n] = 0;
    for (int e = 0; e < NE; e++) cnt[pedges[2 * e + 1]]++;
    int off = 0;
    for (int n = 0; n < NN; n++) { g_poff[n] = off; off += cnt[n]; cnt[n] = g_poff[n]; }
    g_poff[NN] = off;
    for (int e = 0; e < NE; e++) { int d = pedges[2 * e + 1]; g_peid[cnt[d]++] = e; }
}

// ---------------- fused per-patch GNN (the hot kernel) ----------------
__global__ void __launch_bounds__(256, 2)
k_patch(const float* __restrict__ feats, const float* __restrict__ pew,
        const int* __restrict__ pedges,
        const float* __restrict__ W1p, const float* __restrict__ b1p,
        const float* __restrict__ W2p, const float* __restrict__ b2p)
{
    extern __shared__ char sraw[];
    PS* S = (PS*)sraw;
    const int tid = threadIdx.x;
    const int p   = blockIdx.x;

    for (int i = tid; i < NE; i += 256) {
        S->src[i]  = pedges[2 * i];
        S->dst[i]  = pedges[2 * i + 1];
        S->coef[i] = pew[p * NE + i];      // raw w for now
        S->eid[i]  = g_peid[i];
    }
    for (int i = tid; i <= NN; i += 256) S->eoff[i] = g_poff[i];
    for (int i = tid; i < NN; i += 256) { S->ni[i] = 0.f; S->no_[i] = 0.f; }
    for (int i = tid; i < NN * IND; i += 256) S->x[i] = feats[p * NN * IND + i];
    __syncthreads();

    // degrees via smem atomics (tiny)
    for (int i = tid; i < NE; i += 256) {
        float w = S->coef[i];
        atomicAdd(&S->ni[S->dst[i]], w);
        atomicAdd(&S->no_[S->src[i]], w);
    }
    __syncthreads();
    if (tid < NN) {
        float a = S->ni[tid], b = S->no_[tid];
        S->ni[tid]  = (a > 0.f) ? rsqrtf(a) : 1.f;
        S->no_[tid] = (b > 0.f) ? rsqrtf(b) : 1.f;
    }
    __syncthreads();
    for (int i = tid; i < NE; i += 256) S->coef[i] *= S->no_[S->src[i]];
    __syncthreads();

    // layer-1 aggregation by CSR gather (ni folded in)
    for (int i = tid; i < NN * IND; i += 256) {
        int n = i >> 5, d = i & 31;
        int b = S->eoff[n], e = S->eoff[n + 1];
        float s = 0.f;
        for (int q = b; q < e; q++) {
            int ed = S->eid[q];
            s += S->x[S->src[ed] * IND + d] * S->coef[ed];
        }
        S->agg[i] = s * S->ni[n];
    }
    __syncthreads();

    const int   j0  = tid * 2;                      // layer-1: 2 of 512 cols
    const float2 b1v = *(const float2*)&b1p[j0];
    const int   jc  = 2 * (tid & 31);               // layer-2: 2 of 64 cols
    const int   kr  = tid >> 5;                     // layer-2: k-range id (8 ranges)
    const int   k0  = kr * 64;

    for (int c = 0; c < 2; c++) {                   // node chunks of 25
        const int n0 = c * 25;

        // ---- layer 1: h1 = relu(z @ W1p + b1p),  M=25 K=32 N=512 ----
        float a0[25], a1[25];
        #pragma unroll
        for (int n = 0; n < 25; n++) { a0[n] = 0.f; a1[n] = 0.f; }
        #pragma unroll 4
        for (int k = 0; k < IND; k++) {
            float2 wv = *(const float2*)&W1p[k * PHD + j0];
            #pragma unroll
            for (int n = 0; n < 25; n++) {
                float z = S->agg[(n0 + n) * IND + k];   // smem broadcast
                a0[n] = fmaf(z, wv.x, a0[n]);
                a1[n] = fmaf(z, wv.y, a1[n]);
            }
        }
        #pragma unroll
        for (int n = 0; n < 25; n++) {
            float2 h = make_float2(fmaxf(a0[n] + b1v.x, 0.f),
                                   fmaxf(a1[n] + b1v.y, 0.f));
            *(float2*)&S->h1[n * PHD + j0] = h;
        }
        __syncthreads();

        // ---- layer 2 (GEMM-first): y = h1 @ W2p,  M=25 K=512 N=64, k split 8-way ----
        float c0[25], c1[25];
        #pragma unroll
        for (int n = 0; n < 25; n++) { c0[n] = 0.f; c1[n] = 0.f; }
        #pragma unroll 4
        for (int kk = 0; kk < 64; kk++) {
            int k = k0 + kk;
            float2 wv = *(const float2*)&W2p[k * ROD + jc];
            #pragma unroll
            for (int n = 0; n < 25; n++) {
                float h = S->h1[n * PHD + k];           // smem broadcast
                c0[n] = fmaf(h, wv.x, c0[n]);
                c1[n] = fmaf(h, wv.y, c1[n]);
            }
        }
        __syncthreads();                 // all h1 reads done -> reuse as partial buf
        float* part = S->h1;             // [8][25][64] = 12800 floats, exact fit
        #pragma unroll
        for (int n = 0; n < 25; n++)
            *(float2*)&part[(kr * 25 + n) * ROD + jc] = make_float2(c0[n], c1[n]);
        __syncthreads();
        for (int i = tid; i < 25 * ROD; i += 256) {
            int n = i >> 6, j = i & 63;
            float s = 0.f;
            #pragma unroll
            for (int g = 0; g < 8; g++) s += part[(g * 25 + n) * ROD + j];
            S->y[(n0 + n) * ROD + j] = s;
        }
        __syncthreads();
    }

    // layer-2 aggregation by CSR gather + bias + relu
    for (int i = tid; i < NN * ROD; i += 256) {
        int n = i >> 6, d = i & 63;
        int b = S->eoff[n], e = S->eoff[n + 1];
        float s = 0.f;
        for (int q = b; q < e; q++) {
            int ed = S->eid[q];
            s += S->y[S->src[ed] * ROD + d] * S->coef[ed];
        }
        S->agg2v[i] = fmaxf(S->ni[n] * s + b2p[d], 0.f);
    }
    __syncthreads();

    // readout = mean over nodes
    if (tid < ROD) {
        float s = 0.f;
        #pragma unroll 10
        for (int n = 0; n < NN; n++) s += S->agg2v[n * ROD + tid];
        g_readout[p * ROD + tid] = s * (1.f / NN);
    }
}

// ---------------- mesh stage ----------------
__global__ void k_deg(const float* __restrict__ mew, const int* __restrict__ med) {
    int e = blockIdx.x * 256 + threadIdx.x;
    if (e < NEM) {
        float w = mew[e];
        atomicAdd(&g_degi[med[2 * e + 1]], w);
        atomicAdd(&g_dego[med[2 * e]], w);
    }
}

__global__ void k_norm() {
    int i = blockIdx.x * 256 + threadIdx.x;
    if (i < NP) {
        float a = g_degi[i], b = g_dego[i];
        g_nim[i] = (a > 0.f) ? rsqrtf(a) : 1.f;
        g_nom[i] = (b > 0.f) ? rsqrtf(b) : 1.f;
    }
}

__global__ void k_magg1(const float* __restrict__ mew, const int* __restrict__ med) {
    int i = blockIdx.x * 256 + threadIdx.x;  // NEM*ROD exact
    int e = i >> 6, d = i & 63;
    int s = med[2 * e], t = med[2 * e + 1];
    float c = mew[e] * g_nom[s];
    atomicAdd(&g_magg1[t * ROD + d], g_readout[s * ROD + d] * c);
}

__global__ void k_magg2(const float* __restrict__ mew, const int* __restrict__ med) {
    int i = blockIdx.x * 256 + threadIdx.x;  // NEM*HIDD exact
    int e = i >> 8, d = i & 255;
    int s = med[2 * e], t = med[2 * e + 1];
    float c = mew[e] * g_nom[s];
    atomicAdd(&g_magg2[t * HIDD + d], g_h1m[s * HIDD + d] * c);
}

// h1m = relu(ni*agg1 @ W1m + b1m)  (M=4096,K=64,N=256), 16 rows/CTA
__global__ void k_mgc1(const float* __restrict__ W1m, const float* __restrict__ b1m) {
    extern __shared__ float sm[];
    float* sW = sm;                  // 64*256
    float* sA = sm + ROD * HIDD;     // 16*64
    int tid = threadIdx.x, p0 = blockIdx.x * 16;
    for (int i = tid; i < ROD * HIDD; i += 256) sW[i] = W1m[i];
    for (int i = tid; i < 16 * ROD; i += 256)
        sA[i] = g_magg1[p0 * ROD + i] * g_nim[p0 + (i >> 6)];
    __syncthreads();
    float acc[16];
    #pragma unroll
    for (int r = 0; r < 16; r++) acc[r] = 0.f;
    #pragma unroll 2
    for (int k = 0; k < ROD; k++) {
        float wv = sW[k * HIDD + tid];
        #pragma unroll
        for (int r = 0; r < 16; r++) acc[r] = fmaf(sA[r * ROD + k], wv, acc[r]);
    }
    float bb = b1m[tid];
    #pragma unroll
    for (int r = 0; r < 16; r++)
        g_h1m[(p0 + r) * HIDD + tid] = fmaxf(acc[r] + bb, 0.f);
}

// fused: h2 = relu(ni*agg2 @ W2m + b2m); u = relu(h2 @ Wu1 + bu1); r += colsum(u)
__global__ void k_mgc2(const float* __restrict__ W2m, const float* __restrict__ b2m,
                       const float* __restrict__ Wu1, const float* __restrict__ bu1) {
    extern __shared__ float sm[];
    float* sA = sm;              // 16*256
    float* sH = sm + 16 * HIDD;  // 16*256
    int tid = threadIdx.x, p0 = blockIdx.x * 16;
    for (int i = tid; i < 16 * HIDD; i += 256)
        sA[i] = g_magg2[p0 * HIDD + i] * g_nim[p0 + (i >> 8)];
    __syncthreads();
    {
        float acc[16];
        #pragma unroll
        for (int r = 0; r < 16; r++) acc[r] = 0.f;
        #pragma unroll 2
        for (int k = 0; k < HIDD; k++) {
            float wv = __ldg(&W2m[k * HIDD + tid]);
            #pragma unroll
            for (int r = 0; r < 16; r++) acc[r] = fmaf(sA[r * HIDD + k], wv, acc[r]);
        }
        float bb = b2m[tid];
        #pragma unroll
        for (int r = 0; r < 16; r++) sH[r * HIDD + tid] = fmaxf(acc[r] + bb, 0.f);
    }
    __syncthreads();
    {
        int m = tid & 127, grp = tid >> 7;   // 2 groups x 8 rows
        float acc[8];
        #pragma unroll
        for (int r = 0; r < 8; r++) acc[r] = 0.f;
        #pragma unroll 2
        for (int k = 0; k < HIDD; k++) {
            float wv = __ldg(&Wu1[k * RHD + m]);
            #pragma unroll
            for (int r = 0; r < 8; r++)
                acc[r] = fmaf(sH[(grp * 8 + r) * HIDD + k], wv, acc[r]);
        }
        float bb = bu1[m];
        float s = 0.f;
        #pragma unroll
        for (int r = 0; r < 8; r++) s += fmaxf(acc[r] + bb, 0.f);
        atomicAdd(&g_r[m], s);
    }
}

__global__ void k_final(const float* __restrict__ Wout, const float* __restrict__ bout,
                        float* __restrict__ out) {
    int o = threadIdx.x;
    if (o < OUTD) {
        float s = bout[o];
        for (int j = 0; j < RHD; j++) s = fmaf(g_r[j], Wout[j * OUTD + o], s);
        out[o] = s;
    }
}

// ---------------- launch ----------------
extern "C" void kernel_launch(void* const* d_in, const int* in_sizes, int n_in,
                              void* d_out, int out_size) {
    const float* feats = (const float*)d_in[0];
    const float* pew   = (const float*)d_in[1];
    const float* mew   = (const float*)d_in[2];
    const float* W1p   = (const float*)d_in[3];
    const float* b1p   = (const float*)d_in[4];
    const float* W2p   = (const float*)d_in[5];
    const float* b2p   = (const float*)d_in[6];
    const float* W1m   = (const float*)d_in[7];
    const float* b1m   = (const float*)d_in[8];
    const float* W2m   = (const float*)d_in[9];
    const float* b2m   = (const float*)d_in[10];
    const float* Wu1   = (const float*)d_in[11];
    const float* bu1   = (const float*)d_in[12];
    const float* Wout  = (const float*)d_in[13];
    const float* bout  = (const float*)d_in[14];
    const int*   pedg  = (const int*)d_in[15];
    const int*   medg  = (const int*)d_in[16];

    cudaFuncSetAttribute(k_patch, cudaFuncAttributeMaxDynamicSharedMemorySize,
                         (int)sizeof(PS));
    cudaFuncSetAttribute(k_mgc1, cudaFuncAttributeMaxDynamicSharedMemorySize, 69632);

    k_zero<<<4096, 256>>>();
    k_csr<<<1, 1>>>(pedg);
    k_patch<<<NP, 256, sizeof(PS)>>>(feats, pew, pedg, W1p, b1p, W2p, b2p);
    k_deg<<<NEM / 256, 256>>>(mew, medg);
    k_norm<<<NP / 256, 256>>>();
    k_magg1<<<(NEM * ROD) / 256, 256>>>(mew, medg);
    k_mgc1<<<NP / 16, 256, 69632>>>(W1m, b1m);
    k_magg2<<<(NEM * HIDD) / 256, 256>>>(mew, medg);
    k_mgc2<<<NP / 16, 256, 32768>>>(W2m, b2m, Wu1, bu1);
    k_final<<<1, 32>>>(Wout, bout, (float*)d_out);
}

// round 3
// speedup vs baseline: 1.0162x; 1.0162x over previous
#include <cuda_runtime.h>

#define NP   4096
#define NN   50
#define NE   250
#define NEM  65536
#define IND  32
#define PHD  512
#define ROD  64
#define HIDD 256
#define RHD  128
#define OUTD 15

#define CH    14      // nodes per chunk in patch GEMMs
#define NCH   4       // chunks (14*4 = 56 padded nodes)
#define NPAD  56

// ---------------- persistent device scratch ----------------
__device__ float g_readout[NP * ROD];
__device__ float g_degi[NP], g_dego[NP], g_nim[NP], g_nom[NP];
__device__ float g_h1m[NP * HIDD];
__device__ float g_r[RHD];
__device__ int   g_poff[NN + 1];
__device__ int   g_peid[NE];
// mesh CSR
__device__ int   g_mcnt[NP];
__device__ int   g_moff[NP + 1];
__device__ int   g_meid[NEM];
__device__ int   g_msrc[NEM];
__device__ float g_mcoef[NEM];

// ---------------- f32x2 helpers ----------------
__device__ __forceinline__ void ffma2(unsigned long long& acc,
                                      unsigned long long a, unsigned long long b) {
    asm("fma.rn.f32x2 %0, %1, %2, %0;" : "+l"(acc) : "l"(a), "l"(b));
}
__device__ __forceinline__ unsigned long long bcast2(float x) {
    unsigned long long r; unsigned u = __float_as_uint(x);
    asm("mov.b64 %0, {%1, %1};" : "=l"(r) : "r"(u));
    return r;
}
__device__ __forceinline__ float2 unpack2(unsigned long long v) {
    unsigned lo, hi;
    asm("mov.b64 {%0, %1}, %2;" : "=r"(lo), "=r"(hi) : "l"(v));
    return make_float2(__uint_as_float(lo), __uint_as_float(hi));
}

// ---------------- patch kernel shared memory ----------------
struct PS {
    int   src[NE];             // 1000
    int   dst[NE];             // 1000
    int   eoff[NN + 2];        // 208
    int   eid[NE];             // 1000
    float coef[NE];            // 1000
    float ni[NN];              // 200
    float no_[NN];             // 200
    float x[NN * IND];         // 6400   [n][k]
    float agg_t[IND * NPAD];   // 7168   [k][n] (nodes padded, pairs 8B-aligned)
    float y_t[ROD * 57];       // 14592  [col][node] (stride 57: conflict-free)
    float agg2v[NN * ROD];     // 12800
    float h1t[PHD * CH];       // 28672  [j][n] per chunk; reused as k-split partials
};
// sizeof(PS) = 74240 -> 2 CTAs/SM

// ---------------- small setup kernels ----------------
__global__ void k_zero0() {
    int i = blockIdx.x * 256 + threadIdx.x;   // grid 16 -> 4096
    g_mcnt[i] = 0; g_degi[i] = 0.f; g_dego[i] = 0.f;
    if (i < RHD) g_r[i] = 0.f;
}

__global__ void k_csr(const int* __restrict__ pedges) {
    if (threadIdx.x != 0 || blockIdx.x != 0) return;
    int cnt[NN];
    for (int n = 0; n < NN; n++) cnt[n] = 0;
    for (int e = 0; e < NE; e++) cnt[pedges[2 * e + 1]]++;
    int off = 0;
    for (int n = 0; n < NN; n++) { g_poff[n] = off; off += cnt[n]; cnt[n] = g_poff[n]; }
    g_poff[NN] = off;
    for (int e = 0; e < NE; e++) { int d = pedges[2 * e + 1]; g_peid[cnt[d]++] = e; }
}

__global__ void k_mcount(const float* __restrict__ mew, const int* __restrict__ med) {
    int e = blockIdx.x * 256 + threadIdx.x;
    if (e < NEM) {
        int s = med[2 * e], d = med[2 * e + 1];
        float w = mew[e];
        atomicAdd(&g_mcnt[d], 1);
        atomicAdd(&g_degi[d], w);
        atomicAdd(&g_dego[s], w);
    }
}

__global__ void k_mscan() {       // 1 block x 256
    __shared__ int sp[256];
    int t = threadIdx.x, base = t * 16;
    int s = 0;
    #pragma unroll
    for (int i = 0; i < 16; i++) s += g_mcnt[base + i];
    sp[t] = s; __syncthreads();
    if (t == 0) { int run = 0; for (int i = 0; i < 256; i++) { int v = sp[i]; sp[i] = run; run += v; } }
    __syncthreads();
    int run = sp[t];
    #pragma unroll
    for (int i = 0; i < 16; i++) {
        int v = g_mcnt[base + i];
        g_moff[base + i] = run; g_mcnt[base + i] = run; run += v;
    }
    if (t == 255) g_moff[NP] = NEM;
}

__global__ void k_norm() {
    int i = blockIdx.x * 256 + threadIdx.x;
    if (i < NP) {
        float a = g_degi[i], b = g_dego[i];
        g_nim[i] = (a > 0.f) ? rsqrtf(a) : 1.f;
        g_nom[i] = (b > 0.f) ? rsqrtf(b) : 1.f;
    }
}

__global__ void k_mscatter(const int* __restrict__ med) {
    int e = blockIdx.x * 256 + threadIdx.x;
    if (e < NEM) {
        int d = med[2 * e + 1];
        int pos = atomicAdd(&g_mcnt[d], 1);
        g_meid[pos] = e;
    }
}

__global__ void k_mprep(const float* __restrict__ mew, const int* __restrict__ med) {
    int q = blockIdx.x * 256 + threadIdx.x;
    if (q < NEM) {
        int e = g_meid[q];
        int s = med[2 * e];
        g_msrc[q] = s;
        g_mcoef[q] = mew[e] * g_nom[s];
    }
}

// ---------------- fused per-patch GNN (hot kernel, f32x2) ----------------
__global__ void __launch_bounds__(256, 2)
k_patch(const float* __restrict__ feats, const float* __restrict__ pew,
        const int* __restrict__ pedges,
        const float* __restrict__ W1p, const float* __restrict__ b1p,
        const float* __restrict__ W2p, const float* __restrict__ b2p)
{
    extern __shared__ char sraw[];
    PS* S = (PS*)sraw;
    const int tid = threadIdx.x;
    const int p   = blockIdx.x;

    for (int i = tid; i < NE; i += 256) {
        S->src[i]  = pedges[2 * i];
        S->dst[i]  = pedges[2 * i + 1];
        S->coef[i] = pew[p * NE + i];
        S->eid[i]  = g_peid[i];
    }
    for (int i = tid; i <= NN; i += 256) S->eoff[i] = g_poff[i];
    for (int i = tid; i < NN; i += 256) { S->ni[i] = 0.f; S->no_[i] = 0.f; }
    for (int i = tid; i < NN * IND; i += 256) S->x[i] = feats[p * NN * IND + i];
    for (int i = tid; i < IND * NPAD; i += 256) S->agg_t[i] = 0.f;   // pads stay 0
    __syncthreads();

    for (int i = tid; i < NE; i += 256) {
        float w = S->coef[i];
        atomicAdd(&S->ni[S->dst[i]], w);
        atomicAdd(&S->no_[S->src[i]], w);
    }
    __syncthreads();
    if (tid < NN) {
        float a = S->ni[tid], b = S->no_[tid];
        S->ni[tid]  = (a > 0.f) ? rsqrtf(a) : 1.f;
        S->no_[tid] = (b > 0.f) ? rsqrtf(b) : 1.f;
    }
    __syncthreads();
    for (int i = tid; i < NE; i += 256) S->coef[i] *= S->no_[S->src[i]];
    __syncthreads();

    // layer-1 aggregation -> transposed agg_t[k][n]
    for (int i = tid; i < NN * IND; i += 256) {
        int n = i >> 5, d = i & 31;
        int b = S->eoff[n], e = S->eoff[n + 1];
        float s = 0.f;
        for (int q = b; q < e; q++) {
            int ed = S->eid[q];
            s += S->x[S->src[ed] * IND + d] * S->coef[ed];
        }
        S->agg_t[d * NPAD + n] = s * S->ni[n];
    }
    __syncthreads();

    const int   j0  = tid * 2;            // layer-1 cols
    const float b1a = b1p[j0], b1b = b1p[j0 + 1];
    const int   jc  = 2 * (tid & 31);     // layer-2 cols
    const int   kr  = tid >> 5;           // layer-2 k range (8 x 64)

    for (int c = 0; c < NCH; c++) {
        const int n0 = c * CH;

        // ---- layer 1: node-pair packed, M=14 K=32 N=512 ----
        unsigned long long accA[7], accB[7];
        #pragma unroll
        for (int i = 0; i < 7; i++) { accA[i] = 0ull; accB[i] = 0ull; }
        #pragma unroll 4
        for (int k = 0; k < IND; k++) {
            float2 w = *(const float2*)&W1p[k * PHD + j0];
            unsigned long long wa = bcast2(w.x), wb = bcast2(w.y);
            #pragma unroll
            for (int i = 0; i < 7; i++) {
                unsigned long long z =
                    *(const unsigned long long*)&S->agg_t[k * NPAD + n0 + 2 * i];
                ffma2(accA[i], z, wa);
                ffma2(accB[i], z, wb);
            }
        }
        #pragma unroll
        for (int i = 0; i < 7; i++) {
            float2 a = unpack2(accA[i]);
            *(float2*)&S->h1t[j0 * CH + 2 * i] =
                make_float2(fmaxf(a.x + b1a, 0.f), fmaxf(a.y + b1a, 0.f));
            float2 b = unpack2(accB[i]);
            *(float2*)&S->h1t[(j0 + 1) * CH + 2 * i] =
                make_float2(fmaxf(b.x + b1b, 0.f), fmaxf(b.y + b1b, 0.f));
        }
        __syncthreads();

        // ---- layer 2: M=14 K=512(8-way split) N=64 ----
        unsigned long long cA[7], cB[7];
        #pragma unroll
        for (int i = 0; i < 7; i++) { cA[i] = 0ull; cB[i] = 0ull; }
        #pragma unroll 4
        for (int kk = 0; kk < 64; kk++) {
            int k = kr * 64 + kk;
            float2 w = *(const float2*)&W2p[k * ROD + jc];
            unsigned long long wa = bcast2(w.x), wb = bcast2(w.y);
            #pragma unroll
            for (int i = 0; i < 7; i++) {
                unsigned long long h =
                    *(const unsigned long long*)&S->h1t[k * CH + 2 * i];
                ffma2(cA[i], h, wa);
                ffma2(cB[i], h, wb);
            }
        }
        __syncthreads();                 // h1t reads done -> reuse as partials
        float* part = S->h1t;            // [kr][col][n] = 8*64*14 floats, exact fit
        #pragma unroll
        for (int i = 0; i < 7; i++) {
            *(unsigned long long*)&part[(kr * ROD + jc) * CH + 2 * i]       = cA[i];
            *(unsigned long long*)&part[(kr * ROD + jc + 1) * CH + 2 * i]   = cB[i];
        }
        __syncthreads();
        for (int i = tid; i < ROD * CH; i += 256) {
            int col = i / CH, n = i - col * CH;
            float s = 0.f;
            #pragma unroll
            for (int g = 0; g < 8; g++) s += part[(g * ROD + col) * CH + n];
            S->y_t[col * 57 + n0 + n] = s;
        }
        __syncthreads();
    }

    // layer-2 aggregation + bias + relu
    for (int i = tid; i < NN * ROD; i += 256) {
        int n = i >> 6, d = i & 63;
        int b = S->eoff[n], e = S->eoff[n + 1];
        float s = 0.f;
        for (int q = b; q < e; q++) {
            int ed = S->eid[q];
            s += S->y_t[d * 57 + S->src[ed]] * S->coef[ed];
        }
        S->agg2v[i] = fmaxf(S->ni[n] * s + b2p[d], 0.f);
    }
    __syncthreads();

    if (tid < ROD) {
        float s = 0.f;
        #pragma unroll 10
        for (int n = 0; n < NN; n++) s += S->agg2v[n * ROD + tid];
        g_readout[p * ROD + tid] = s * (1.f / NN);
    }
}

// ---------------- mesh stage (gather-fused, no global atomics) ----------------
// h1m = relu( (nim * gather(readout)) @ W1m + b1m ), 16 rows/CTA
__global__ void k_mgc1(const float* __restrict__ W1m, const float* __restrict__ b1m) {
    extern __shared__ float sm[];
    float* sW = sm;                  // 64*256
    float* sA = sm + ROD * HIDD;     // 16*64
    int tid = threadIdx.x, p0 = blockIdx.x * 16;
    for (int i = tid; i < ROD * HIDD; i += 256) sW[i] = W1m[i];
    for (int i = tid; i < 16 * ROD; i += 256) sA[i] = 0.f;
    __syncthreads();

    int d = tid & 63, qo = tid >> 6;     // 4-way edge split
    for (int r = 0; r < 16; r++) {
        int t = p0 + r;
        int b = g_moff[t], en = g_moff[t + 1];
        float acc = 0.f;
        for (int q = b + qo; q < en; q += 4)
            acc += g_readout[g_msrc[q] * ROD + d] * g_mcoef[q];
        atomicAdd(&sA[r * ROD + d], acc);
    }
    __syncthreads();
    for (int i = tid; i < 16 * ROD; i += 256) sA[i] *= g_nim[p0 + (i >> 6)];
    __syncthreads();

    float acc[16];
    #pragma unroll
    for (int r = 0; r < 16; r++) acc[r] = 0.f;
    #pragma unroll 2
    for (int k = 0; k < ROD; k++) {
        float wv = sW[k * HIDD + tid];
        #pragma unroll
        for (int r = 0; r < 16; r++) acc[r] = fmaf(sA[r * ROD + k], wv, acc[r]);
    }
    float bb = b1m[tid];
    #pragma unroll
    for (int r = 0; r < 16; r++)
        g_h1m[(p0 + r) * HIDD + tid] = fmaxf(acc[r] + bb, 0.f);
}

// fused: gather h1m -> h2 = relu(@W2m+b2m) -> u = relu(@Wu1+bu1) -> r += colsum(u)
__global__ void k_mgc2(const float* __restrict__ W2m, const float* __restrict__ b2m,
                       const float* __restrict__ Wu1, const float* __restrict__ bu1) {
    extern __shared__ float sm[];
    float* sA = sm;              // 16*256
    float* sH = sm + 16 * HIDD;  // 16*256
    int tid = threadIdx.x, p0 = blockIdx.x * 16;

    for (int r = 0; r < 16; r++) {
        int t = p0 + r;
        int b = g_moff[t], en = g_moff[t + 1];
        float acc = 0.f;
        for (int q = b; q < en; q++)
            acc += g_h1m[g_msrc[q] * HIDD + tid] * g_mcoef[q];
        sA[r * HIDD + tid] = acc * g_nim[t];
    }
    __syncthreads();
    {
        float acc[16];
        #pragma unroll
        for (int r = 0; r < 16; r++) acc[r] = 0.f;
        #pragma unroll 2
        for (int k = 0; k < HIDD; k++) {
            float wv = __ldg(&W2m[k * HIDD + tid]);
            #pragma unroll
            for (int r = 0; r < 16; r++) acc[r] = fmaf(sA[r * HIDD + k], wv, acc[r]);
        }
        float bb = b2m[tid];
        #pragma unroll
        for (int r = 0; r < 16; r++) sH[r * HIDD + tid] = fmaxf(acc[r] + bb, 0.f);
    }
    __syncthreads();
    {
        int m = tid & 127, grp = tid >> 7;
        float acc[8];
        #pragma unroll
        for (int r = 0; r < 8; r++) acc[r] = 0.f;
        #pragma unroll 2
        for (int k = 0; k < HIDD; k++) {
            float wv = __ldg(&Wu1[k * RHD + m]);
            #pragma unroll
            for (int r = 0; r < 8; r++)
                acc[r] = fmaf(sH[(grp * 8 + r) * HIDD + k], wv, acc[r]);
        }
        float bb = bu1[m];
        float s = 0.f;
        #pragma unroll
        for (int r = 0; r < 8; r++) s += fmaxf(acc[r] + bb, 0.f);
        atomicAdd(&g_r[m], s);
    }
}

__global__ void k_final(const float* __restrict__ Wout, const float* __restrict__ bout,
                        float* __restrict__ out) {
    int o = threadIdx.x;
    if (o < OUTD) {
        float s = bout[o];
        for (int j = 0; j < RHD; j++) s = fmaf(g_r[j], Wout[j * OUTD + o], s);
        out[o] = s;
    }
}

// ---------------- launch ----------------
extern "C" void kernel_launch(void* const* d_in, const int* in_sizes, int n_in,
                              void* d_out, int out_size) {
    const float* feats = (const float*)d_in[0];
    const float* pew   = (const float*)d_in[1];
    const float* mew   = (const float*)d_in[2];
    const float* W1p   = (const float*)d_in[3];
    const float* b1p   = (const float*)d_in[4];
    const float* W2p   = (const float*)d_in[5];
    const float* b2p   = (const float*)d_in[6];
    const float* W1m   = (const float*)d_in[7];
    const float* b1m   = (const float*)d_in[8];
    const float* W2m   = (const float*)d_in[9];
    const float* b2m   = (const float*)d_in[10];
    const float* Wu1   = (const float*)d_in[11];
    const float* bu1   = (const float*)d_in[12];
    const float* Wout  = (const float*)d_in[13];
    const float* bout  = (const float*)d_in[14];
    const int*   pedg  = (const int*)d_in[15];
    const int*   medg  = (const int*)d_in[16];

    cudaFuncSetAttribute(k_patch, cudaFuncAttributeMaxDynamicSharedMemorySize,
                         (int)sizeof(PS));
    cudaFuncSetAttribute(k_mgc1, cudaFuncAttributeMaxDynamicSharedMemorySize, 69632);

    k_zero0<<<16, 256>>>();
    k_csr<<<1, 1>>>(pedg);
    k_mcount<<<NEM / 256, 256>>>(mew, medg);
    k_patch<<<NP, 256, sizeof(PS)>>>(feats, pew, pedg, W1p, b1p, W2p, b2p);  // launch #4 (ncu slot)
    k_mscan<<<1, 256>>>();
    k_norm<<<NP / 256, 256>>>();
    k_mscatter<<<NEM / 256, 256>>>(medg);
    k_mprep<<<NEM / 256, 256>>>(mew, medg);
    k_mgc1<<<NP / 16, 256, 69632>>>(W1m, b1m);
    k_mgc2<<<NP / 16, 256, 32768>>>(W2m, b2m, Wu1, bu1);
    k_final<<<1, 32>>>(Wout, bout, (float*)d_out);
}

// round 5
// speedup vs baseline: 1.0261x; 1.0098x over previous
#include <cuda_runtime.h>

#define NP   4096
#define NN   50
#define NE   250
#define NEM  65536
#define IND  32
#define PHD  512
#define ROD  64
#define HIDD 256
#define RHD  128
#define OUTD 15

// ---------------- persistent device scratch ----------------
__device__ float g_readout[NP * ROD];
__device__ float g_degi[NP], g_dego[NP], g_nim[NP], g_nom[NP];
__device__ float g_h1m[NP * HIDD];
__device__ float g_r[RHD];
__device__ int   g_poff[NN + 1];
__device__ int   g_peid[NE];
__device__ int   g_mcnt[NP];
__device__ int   g_moff[NP + 1];
__device__ int   g_meid[NEM];
__device__ int   g_msrc[NEM];
__device__ float g_mcoef[NEM];

// ---------------- f32x2 helpers ----------------
typedef unsigned long long ull;
__device__ __forceinline__ void ffma2(ull& acc, ull a, ull b) {
    asm("fma.rn.f32x2 %0, %1, %2, %0;" : "+l"(acc) : "l"(a), "l"(b));
}
__device__ __forceinline__ ull bcast2(float x) {
    ull r; unsigned u = __float_as_uint(x);
    asm("mov.b64 %0, {%1, %1};" : "=l"(r) : "r"(u));
    return r;
}
__device__ __forceinline__ float2 unpack2(ull v) {
    unsigned lo, hi;
    asm("mov.b64 {%0, %1}, %2;" : "=r"(lo), "=r"(hi) : "l"(v));
    return make_float2(__uint_as_float(lo), __uint_as_float(hi));
}

// ---------------- patch kernel shared memory ----------------
// agg_t/h1t rows stride 66 floats (264B): 8B-aligned rows, low-conflict.
struct PS {
    int   src[NE];            // 1000
    int   dst[NE];            // 1000
    int   eoff[NN + 2];       // 208
    int   gsrc[NE];           // 1000  src[eid[q]] pre-gathered (CSR order)
    float gcoef[NE];          // 1000  coef[eid[q]] * no[src]
    int   eid[NE];            // 1000
    float coef[NE];           // 1000
    float ni[NN];             // 200
    float no_[NN];            // 200
    float x[NN * IND];        // 6400  [n][k]
    float agg_t[IND * 66];    // 8448  [k][node 0..63] pair-packed, pads zero
    float h1t[64 * 66];       // 16896 [tile-col][node] pair-packed
    float y_t[ROD * 67];      // 17152 [col][node] (67: conflict-free gather)
    float agg2v[NN * ROD];    // 12800
};
// sizeof(PS) = 68304 -> 3 CTAs/SM (204912 B)

// ---------------- small setup kernels ----------------
__global__ void k_zero0() {
    int i = blockIdx.x * 256 + threadIdx.x;   // grid 16 -> 4096
    g_mcnt[i] = 0; g_degi[i] = 0.f; g_dego[i] = 0.f;
    if (i < RHD) g_r[i] = 0.f;
}

__global__ void k_csr(const int* __restrict__ pedges) {
    if (threadIdx.x != 0 || blockIdx.x != 0) return;
    int cnt[NN];
    for (int n = 0; n < NN; n++) cnt[n] = 0;
    for (int e = 0; e < NE; e++) cnt[pedges[2 * e + 1]]++;
    int off = 0;
    for (int n = 0; n < NN; n++) { g_poff[n] = off; off += cnt[n]; cnt[n] = g_poff[n]; }
    g_poff[NN] = off;
    for (int e = 0; e < NE; e++) { int d = pedges[2 * e + 1]; g_peid[cnt[d]++] = e; }
}

__global__ void k_mcount(const float* __restrict__ mew, const int* __restrict__ med) {
    int e = blockIdx.x * 256 + threadIdx.x;
    if (e < NEM) {
        int s = med[2 * e], d = med[2 * e + 1];
        float w = mew[e];
        atomicAdd(&g_mcnt[d], 1);
        atomicAdd(&g_degi[d], w);
        atomicAdd(&g_dego[s], w);
    }
}

__global__ void k_mscan() {
    __shared__ int sp[256];
    int t = threadIdx.x, base = t * 16;
    int s = 0;
    #pragma unroll
    for (int i = 0; i < 16; i++) s += g_mcnt[base + i];
    sp[t] = s; __syncthreads();
    if (t == 0) { int run = 0; for (int i = 0; i < 256; i++) { int v = sp[i]; sp[i] = run; run += v; } }
    __syncthreads();
    int run = sp[t];
    #pragma unroll
    for (int i = 0; i < 16; i++) {
        int v = g_mcnt[base + i];
        g_moff[base + i] = run; g_mcnt[base + i] = run; run += v;
    }
    if (t == 255) g_moff[NP] = NEM;
}

__global__ void k_norm() {
    int i = blockIdx.x * 256 + threadIdx.x;
    if (i < NP) {
        float a = g_degi[i], b = g_dego[i];
        g_nim[i] = (a > 0.f) ? rsqrtf(a) : 1.f;
        g_nom[i] = (b > 0.f) ? rsqrtf(b) : 1.f;
    }
}

__global__ void k_mscatter(const int* __restrict__ med) {
    int e = blockIdx.x * 256 + threadIdx.x;
    if (e < NEM) {
        int d = med[2 * e + 1];
        int pos = atomicAdd(&g_mcnt[d], 1);
        g_meid[pos] = e;
    }
}

__global__ void k_mprep(const float* __restrict__ mew, const int* __restrict__ med) {
    int q = blockIdx.x * 256 + threadIdx.x;
    if (q < NEM) {
        int e = g_meid[q];
        int s = med[2 * e];
        g_msrc[q] = s;
        g_mcoef[q] = mew[e] * g_nom[s];
    }
}

// ---------------- fused per-patch GNN: j-tiled layer fusion ----------------
__global__ void __launch_bounds__(256, 3)
k_patch(const float* __restrict__ feats, const float* __restrict__ pew,
        const int* __restrict__ pedges,
        const float* __restrict__ W1p, const float* __restrict__ b1p,
        const float* __restrict__ W2p, const float* __restrict__ b2p)
{
    extern __shared__ char sraw[];
    PS* S = (PS*)sraw;
    const int tid = threadIdx.x;
    const int p   = blockIdx.x;

    for (int i = tid; i < NE; i += 256) {
        S->src[i]  = pedges[2 * i];
        S->dst[i]  = pedges[2 * i + 1];
        S->coef[i] = pew[p * NE + i];
        S->eid[i]  = g_peid[i];
    }
    for (int i = tid; i <= NN; i += 256) S->eoff[i] = g_poff[i];
    for (int i = tid; i < NN; i += 256) { S->ni[i] = 0.f; S->no_[i] = 0.f; }
    for (int i = tid; i < NN * IND; i += 256) S->x[i] = feats[p * NN * IND + i];
    for (int i = tid; i < IND * 66; i += 256) S->agg_t[i] = 0.f;   // pads stay 0
    __syncthreads();

    for (int i = tid; i < NE; i += 256) {
        float w = S->coef[i];
        atomicAdd(&S->ni[S->dst[i]], w);
        atomicAdd(&S->no_[S->src[i]], w);
    }
    __syncthreads();
    if (tid < NN) {
        float a = S->ni[tid], b = S->no_[tid];
        S->ni[tid]  = (a > 0.f) ? rsqrtf(a) : 1.f;
        S->no_[tid] = (b > 0.f) ? rsqrtf(b) : 1.f;
    }
    __syncthreads();
    // pre-gather edge src + normalized coef in CSR order (one indirection less)
    for (int q = tid; q < NE; q += 256) {
        int ed = S->eid[q];
        int s  = S->src[ed];
        S->gsrc[q]  = s;
        S->gcoef[q] = S->coef[ed] * S->no_[s];
    }
    __syncthreads();

    // layer-1 aggregation -> agg_t[k][node]
    for (int i = tid; i < NN * IND; i += 256) {
        int n = i >> 5, d = i & 31;
        int b = S->eoff[n], e = S->eoff[n + 1];
        float s = 0.f;
        for (int q = b; q < e; q++)
            s += S->x[S->gsrc[q] * IND + d] * S->gcoef[q];
        S->agg_t[d * 66 + n] = s * S->ni[n];
    }
    __syncthreads();

    // GEMM1 map: 2 cols x 8 nodes.  GEMM2 map: 4 cols x 4 nodes.
    const int jp  = tid & 31, ng1 = tid >> 5;       // GEMM1 (ng1 7 = all-pad, skip)
    const int c4  = tid & 15, ng2 = tid >> 4;       // GEMM2 (ng2 >= 14 skip)

    ull yacc[8];                                    // [cc 0..3][pair 0..1], persists
    #pragma unroll
    for (int i = 0; i < 8; i++) yacc[i] = 0ull;

    for (int t = 0; t < 8; t++) {
        const int jbase = t * 64;

        // ---- GEMM1: h1 tile = relu(agg @ W1p[:, jbase:jbase+64] + b1) ----
        if (ng1 < 7) {
            ull acc[8];                             // [col 0/1][pair 0..3]
            #pragma unroll
            for (int i = 0; i < 8; i++) acc[i] = 0ull;
            #pragma unroll 4
            for (int k = 0; k < IND; k++) {
                float2 wf = *(const float2*)&W1p[k * PHD + jbase + 2 * jp];
                ull wa = bcast2(wf.x), wb = bcast2(wf.y);
                #pragma unroll
                for (int i = 0; i < 4; i++) {
                    ull z = *(const ull*)&S->agg_t[k * 66 + ng1 * 8 + 2 * i];
                    ffma2(acc[i],     z, wa);
                    ffma2(acc[4 + i], z, wb);
                }
            }
            float2 bv = *(const float2*)&b1p[jbase + 2 * jp];
            #pragma unroll
            for (int i = 0; i < 4; i++) {
                float2 a = unpack2(acc[i]);
                *(float2*)&S->h1t[(2 * jp) * 66 + ng1 * 8 + 2 * i] =
                    make_float2(fmaxf(a.x + bv.x, 0.f), fmaxf(a.y + bv.x, 0.f));
                float2 b = unpack2(acc[4 + i]);
                *(float2*)&S->h1t[(2 * jp + 1) * 66 + ng1 * 8 + 2 * i] =
                    make_float2(fmaxf(b.x + bv.y, 0.f), fmaxf(b.y + bv.y, 0.f));
            }
        }
        __syncthreads();

        // ---- GEMM2: yacc += h1tile @ W2p[jbase:jbase+64, :] ----
        if (ng2 < 14) {
            #pragma unroll 4
            for (int j = 0; j < 64; j++) {
                float4 w = *(const float4*)&W2p[(jbase + j) * ROD + 4 * c4];
                ull w0 = bcast2(w.x), w1 = bcast2(w.y),
                    w2 = bcast2(w.z), w3 = bcast2(w.w);
                ull z0 = *(const ull*)&S->h1t[j * 66 + ng2 * 4];
                ull z1 = *(const ull*)&S->h1t[j * 66 + ng2 * 4 + 2];
                ffma2(yacc[0], z0, w0); ffma2(yacc[1], z1, w0);
                ffma2(yacc[2], z0, w1); ffma2(yacc[3], z1, w1);
                ffma2(yacc[4], z0, w2); ffma2(yacc[5], z1, w2);
                ffma2(yacc[6], z0, w3); ffma2(yacc[7], z1, w3);
            }
        }
        __syncthreads();
    }

    // write y (only real-node entries will ever be read)
    if (ng2 < 14) {
        #pragma unroll
        for (int cc = 0; cc < 4; cc++) {
            #pragma unroll
            for (int pi = 0; pi < 2; pi++) {
                float2 v = unpack2(yacc[cc * 2 + pi]);
                S->y_t[(4 * c4 + cc) * 67 + ng2 * 4 + 2 * pi]     = v.x;
                S->y_t[(4 * c4 + cc) * 67 + ng2 * 4 + 2 * pi + 1] = v.y;
            }
        }
    }
    __syncthreads();

    // layer-2 aggregation + bias + relu
    for (int i = tid; i < NN * ROD; i += 256) {
        int n = i >> 6, d = i & 63;
        int b = S->eoff[n], e = S->eoff[n + 1];
        float s = 0.f;
        for (int q = b; q < e; q++)
            s += S->y_t[d * 67 + S->gsrc[q]] * S->gcoef[q];
        S->agg2v[i] = fmaxf(S->ni[n] * s + b2p[d], 0.f);
    }
    __syncthreads();

    if (tid < ROD) {
        float s = 0.f;
        #pragma unroll 10
        for (int n = 0; n < NN; n++) s += S->agg2v[n * ROD + tid];
        g_readout[p * ROD + tid] = s * (1.f / NN);
    }
}

// ---------------- mesh stage (gather-fused) ----------------
__global__ void k_mgc1(const float* __restrict__ W1m, const float* __restrict__ b1m) {
    extern __shared__ float sm[];
    float* sW = sm;                  // 64*256
    float* sA = sm + ROD * HIDD;     // 16*64
    int tid = threadIdx.x, p0 = blockIdx.x * 16;
    for (int i = tid; i < ROD * HIDD; i += 256) sW[i] = W1m[i];
    for (int i = tid; i < 16 * ROD; i += 256) sA[i] = 0.f;
    __syncthreads();

    int d = tid & 63, qo = tid >> 6;
    for (int r = 0; r < 16; r++) {
        int t = p0 + r;
        int b = g_moff[t], en = g_moff[t + 1];
        float acc = 0.f;
        for (int q = b + qo; q < en; q += 4)
            acc += g_readout[g_msrc[q] * ROD + d] * g_mcoef[q];
        atomicAdd(&sA[r * ROD + d], acc);
    }
    __syncthreads();
    for (int i = tid; i < 16 * ROD; i += 256) sA[i] *= g_nim[p0 + (i >> 6)];
    __syncthreads();

    float acc[16];
    #pragma unroll
    for (int r = 0; r < 16; r++) acc[r] = 0.f;
    #pragma unroll 2
    for (int k = 0; k < ROD; k++) {
        float wv = sW[k * HIDD + tid];
        #pragma unroll
        for (int r = 0; r < 16; r++) acc[r] = fmaf(sA[r * ROD + k], wv, acc[r]);
    }
    float bb = b1m[tid];
    #pragma unroll
    for (int r = 0; r < 16; r++)
        g_h1m[(p0 + r) * HIDD + tid] = fmaxf(acc[r] + bb, 0.f);
}

__global__ void k_mgc2(const float* __restrict__ W2m, const float* __restrict__ b2m,
                       const float* __restrict__ Wu1, const float* __restrict__ bu1) {
    extern __shared__ float sm[];
    float* sA = sm;              // 16*256
    float* sH = sm + 16 * HIDD;  // 16*256
    int tid = threadIdx.x, p0 = blockIdx.x * 16;

    for (int r = 0; r < 16; r++) {
        int t = p0 + r;
        int b = g_moff[t], en = g_moff[t + 1];
        float acc = 0.f;
        for (int q = b; q < en; q++)
            acc += g_h1m[g_msrc[q] * HIDD + tid] * g_mcoef[q];
        sA[r * HIDD + tid] = acc * g_nim[t];
    }
    __syncthreads();
    {
        float acc[16];
        #pragma unroll
        for (int r = 0; r < 16; r++) acc[r] = 0.f;
        #pragma unroll 2
        for (int k = 0; k < HIDD; k++) {
            float wv = __ldg(&W2m[k * HIDD + tid]);
            #pragma unroll
            for (int r = 0; r < 16; r++) acc[r] = fmaf(sA[r * HIDD + k], wv, acc[r]);
        }
        float bb = b2m[tid];
        #pragma unroll
        for (int r = 0; r < 16; r++) sH[r * HIDD + tid] = fmaxf(acc[r] + bb, 0.f);
    }
    __syncthreads();
    {
        int m = tid & 127, grp = tid >> 7;
        float acc[8];
        #pragma unroll
        for (int r = 0; r < 8; r++) acc[r] = 0.f;
        #pragma unroll 2
        for (int k = 0; k < HIDD; k++) {
            float wv = __ldg(&Wu1[k * RHD + m]);
            #pragma unroll
            for (int r = 0; r < 8; r++)
                acc[r] = fmaf(sH[(grp * 8 + r) * HIDD + k], wv, acc[r]);
        }
        float bb = bu1[m];
        float s = 0.f;
        #pragma unroll
        for (int r = 0; r < 8; r++) s += fmaxf(acc[r] + bb, 0.f);
        atomicAdd(&g_r[m], s);
    }
}

__global__ void k_final(const float* __restrict__ Wout, const float* __restrict__ bout,
                        float* __restrict__ out) {
    int o = threadIdx.x;
    if (o < OUTD) {
        float s = bout[o];
        for (int j = 0; j < RHD; j++) s = fmaf(g_r[j], Wout[j * OUTD + o], s);
        out[o] = s;
    }
}

// ---------------- launch ----------------
extern "C" void kernel_launch(void* const* d_in, const int* in_sizes, int n_in,
                              void* d_out, int out_size) {
    const float* feats = (const float*)d_in[0];
    const float* pew   = (const float*)d_in[1];
    const float* mew   = (const float*)d_in[2];
    const float* W1p   = (const float*)d_in[3];
    const float* b1p   = (const float*)d_in[4];
    const float* W2p   = (const float*)d_in[5];
    const float* b2p   = (const float*)d_in[6];
    const float* W1m   = (const float*)d_in[7];
    const float* b1m   = (const float*)d_in[8];
    const float* W2m   = (const float*)d_in[9];
    const float* b2m   = (const float*)d_in[10];
    const float* Wu1   = (const float*)d_in[11];
    const float* bu1   = (const float*)d_in[12];
    const float* Wout  = (const float*)d_in[13];
    const float* bout  = (const float*)d_in[14];
    const int*   pedg  = (const int*)d_in[15];
    const int*   medg  = (const int*)d_in[16];

    cudaFuncSetAttribute(k_patch, cudaFuncAttributeMaxDynamicSharedMemorySize,
                         (int)sizeof(PS));
    cudaFuncSetAttribute(k_mgc1, cudaFuncAttributeMaxDynamicSharedMemorySize, 69632);

    k_zero0<<<16, 256>>>();
    k_csr<<<1, 1>>>(pedg);
    k_mcount<<<NEM / 256, 256>>>(mew, medg);
    k_patch<<<NP, 256, sizeof(PS)>>>(feats, pew, pedg, W1p, b1p, W2p, b2p);  // ncu slot
    k_mscan<<<1, 256>>>();
    k_norm<<<NP / 256, 256>>>();
    k_mscatter<<<NEM / 256, 256>>>(medg);
    k_mprep<<<NEM / 256, 256>>>(mew, medg);
    k_mgc1<<<NP / 16, 256, 69632>>>(W1m, b1m);
    k_mgc2<<<NP / 16, 256, 32768>>>(W2m, b2m, Wu1, bu1);
    k_final<<<1, 32>>>(Wout, bout, (float*)d_out);
}

// round 7
// speedup vs baseline: 1.2566x; 1.2246x over previous
#include <cuda_runtime.h>
#include <cuda_bf16.h>
#include <cstdint>

#define NP   4096
#define NN   50
#define NE   250
#define NEM  65536
#define IND  32
#define PHD  512
#define ROD  64
#define HIDD 256
#define RHD  128
#define OUTD 15

// ---------------- persistent device scratch ----------------
__device__ float g_readout[NP * ROD];
__device__ float g_degi[NP], g_dego[NP], g_nim[NP], g_nom[NP];
__device__ float g_h1m[NP * HIDD];
__device__ float g_r[RHD];
__device__ int   g_poff[NN + 1];
__device__ int   g_peid[NE];
__device__ int   g_gsrc[NE];
__device__ int   g_mcnt[NP];
__device__ int   g_moff[NP + 1];
__device__ int   g_meid[NEM];
__device__ int   g_msrc[NEM];
__device__ float g_mcoef[NEM];
// patch-MLP staging
__device__ float g_agg[NP * 64 * IND];     // [patch][64 rows pad][32]
__device__ float g_y[NP * 64 * ROD];       // [patch][64 rows pad][64]
__device__ float g_gcoefP[NP * 256];
__device__ float g_pni[NP * 64];
// fragment-packed weights: [nt][kt][lane][reg] as u32 (two bf16, low = smaller k)
__device__ uint32_t g_w1f_hi[64 * 2 * 32 * 2];    // W1: 512n x 32k
__device__ uint32_t g_w1f_lo[64 * 2 * 32 * 2];
__device__ uint32_t g_w2f_hi[8 * 32 * 32 * 2];    // W2: 64n x 512k
__device__ uint32_t g_w2f_lo[8 * 32 * 32 * 2];

// ---------------- helpers ----------------
__device__ __forceinline__ uint32_t pkbf(__nv_bfloat16 a, __nv_bfloat16 b) {
    unsigned short ua = *(unsigned short*)&a, ub = *(unsigned short*)&b;
    return ((uint32_t)ub << 16) | (uint32_t)ua;
}
__device__ __forceinline__ void split2(float x0, float x1, uint32_t& hi, uint32_t& lo) {
    __nv_bfloat16 h0 = __float2bfloat16(x0), h1 = __float2bfloat16(x1);
    __nv_bfloat16 l0 = __float2bfloat16(x0 - __bfloat162float(h0));
    __nv_bfloat16 l1 = __float2bfloat16(x1 - __bfloat162float(h1));
    hi = pkbf(h0, h1); lo = pkbf(l0, l1);
}
__device__ __forceinline__ void mma16816(float* c, const uint32_t* a, const uint32_t* b) {
    asm volatile("mma.sync.aligned.m16n8k16.row.col.f32.bf16.bf16.f32 "
        "{%0,%1,%2,%3}, {%4,%5,%6,%7}, {%8,%9}, {%0,%1,%2,%3};"
        : "+f"(c[0]), "+f"(c[1]), "+f"(c[2]), "+f"(c[3])
        : "r"(a[0]), "r"(a[1]), "r"(a[2]), "r"(a[3]), "r"(b[0]), "r"(b[1]));
}

// ---------------- setup kernels ----------------
__global__ void k_zero0() {
    int i = blockIdx.x * 256 + threadIdx.x;
    g_mcnt[i] = 0; g_degi[i] = 0.f; g_dego[i] = 0.f;
    if (i < RHD) g_r[i] = 0.f;
}

__global__ void k_csr(const int* __restrict__ pedges) {
    if (threadIdx.x != 0 || blockIdx.x != 0) return;
    int cnt[NN];
    for (int n = 0; n < NN; n++) cnt[n] = 0;
    for (int e = 0; e < NE; e++) cnt[pedges[2 * e + 1]]++;
    int off = 0;
    for (int n = 0; n < NN; n++) { g_poff[n] = off; off += cnt[n]; cnt[n] = g_poff[n]; }
    g_poff[NN] = off;
    for (int e = 0; e < NE; e++) { int d = pedges[2 * e + 1]; g_peid[cnt[d]++] = e; }
    for (int q = 0; q < NE; q++) g_gsrc[q] = pedges[2 * g_peid[q]];
}

// build per-lane mma fragments of W1 (hi/lo) and W2 (hi/lo)
__global__ void k_wprep(const float* __restrict__ W1p, const float* __restrict__ W2p) {
    int i = blockIdx.x * 256 + threadIdx.x;      // 96*256 = 24576
    if (i < 8192) {                              // W1 frags
        int reg = i & 1, lane = (i >> 1) & 31, kt = (i >> 6) & 1, nt = i >> 7;
        int n = nt * 8 + (lane >> 2);
        int k = kt * 16 + (lane & 3) * 2 + reg * 8;
        float v0 = W1p[k * PHD + n], v1 = W1p[(k + 1) * PHD + n];
        uint32_t hi, lo; split2(v0, v1, hi, lo);
        g_w1f_hi[i] = hi; g_w1f_lo[i] = lo;
    } else if (i < 8192 + 16384) {               // W2 frags
        int j = i - 8192;
        int reg = j & 1, lane = (j >> 1) & 31, kt = (j >> 6) & 31, nt = j >> 11;
        int n = nt * 8 + (lane >> 2);
        int k = kt * 16 + (lane & 3) * 2 + reg * 8;
        float v0 = W2p[k * ROD + n], v1 = W2p[(k + 1) * ROD + n];
        uint32_t hi, lo; split2(v0, v1, hi, lo);
        g_w2f_hi[j] = hi; g_w2f_lo[j] = lo;
    }
}

// ---------------- per-patch layer-1 aggregation ----------------
__global__ void __launch_bounds__(256) k_agg1(const float* __restrict__ feats,
                                              const float* __restrict__ pew,
                                              const int* __restrict__ pedges) {
    __shared__ int   ssrc[NE], sdst[NE], eoff[NN + 1], sgs[NE];
    __shared__ float coef[NE], gc[NE], ni[NN], no_[NN], x[NN * IND];
    int tid = threadIdx.x, p = blockIdx.x;
    for (int i = tid; i < NE; i += 256) {
        ssrc[i] = pedges[2 * i]; sdst[i] = pedges[2 * i + 1];
        coef[i] = pew[p * NE + i]; sgs[i] = g_gsrc[i];
    }
    for (int i = tid; i <= NN; i += 256) eoff[i] = g_poff[i];
    for (int i = tid; i < NN; i += 256) { ni[i] = 0.f; no_[i] = 0.f; }
    for (int i = tid; i < NN * IND; i += 256) x[i] = feats[p * NN * IND + i];
    __syncthreads();
    for (int i = tid; i < NE; i += 256) {
        float w = coef[i];
        atomicAdd(&ni[sdst[i]], w);
        atomicAdd(&no_[ssrc[i]], w);
    }
    __syncthreads();
    if (tid < NN) {
        float a = ni[tid], b = no_[tid];
        ni[tid]  = (a > 0.f) ? rsqrtf(a) : 1.f;
        no_[tid] = (b > 0.f) ? rsqrtf(b) : 1.f;
    }
    __syncthreads();
    for (int q = tid; q < NE; q += 256) {
        int e = g_peid[q];
        gc[q] = coef[e] * no_[ssrc[e]];
    }
    __syncthreads();
    for (int i = tid; i < 64 * IND; i += 256) {
        int n = i >> 5, d = i & 31;
        float s = 0.f;
        if (n < NN) {
            int b0 = eoff[n], e0 = eoff[n + 1];
            for (int q = b0; q < e0; q++) s += x[sgs[q] * IND + d] * gc[q];
            s *= ni[n];
        }
        g_agg[p * 2048 + i] = s;
    }
    for (int q = tid; q < NE; q += 256) g_gcoefP[p * 256 + q] = gc[q];
    if (tid < NN) g_pni[p * 64 + tid] = ni[tid];
}

// ---------------- fused MLP on tensor cores (mma.sync, 2 patches/CTA) ----------------
// GEMM1: [128,32]@[32,512] -> relu -> GEMM2: [128,512]@[512,64], fully register-fused.
__global__ void __launch_bounds__(256) k_mlp(const float* __restrict__ b1p) {
    __shared__ float sagg[128 * IND];     // 16 KB
    __shared__ float sb1[PHD];            // 2 KB
    const int tid = threadIdx.x, lane = tid & 31, wid = tid >> 5;
    const int b = blockIdx.x;
    const int m0 = wid * 16;
    const int r0 = m0 + (lane >> 2);
    const int kq = (lane & 3) * 2;

    for (int i = tid; i < 128 * IND; i += 256) sagg[i] = g_agg[b * 4096 + i];
    for (int i = tid; i < PHD; i += 256) sb1[i] = b1p[i];
    __syncthreads();

    // A1 fragments (K=32 -> 2 ktiles), hi/lo
    uint32_t a1hi[2][4], a1lo[2][4];
    #pragma unroll
    for (int kt = 0; kt < 2; kt++) {
        #pragma unroll
        for (int j = 0; j < 4; j++) {
            int dr = (j & 1) * 8, dk = (j >> 1) * 8;
            int rr = r0 + dr, kk = kt * 16 + kq + dk;
            split2(sagg[rr * IND + kk], sagg[rr * IND + kk + 1],
                   a1hi[kt][j], a1lo[kt][j]);
        }
    }

    float acc2[8][4];
    #pragma unroll
    for (int nt = 0; nt < 8; nt++)
        #pragma unroll
        for (int j = 0; j < 4; j++) acc2[nt][j] = 0.f;

    for (int c = 0; c < 8; c++) {
        // ---- GEMM1 chunk: cols c*64 .. c*64+63 -> A2 fragments in registers ----
        uint32_t a2hi[4][4], a2lo[4][4];
        #pragma unroll
        for (int ntl = 0; ntl < 8; ntl++) {
            int nt = c * 8 + ntl;
            float acc[4] = {0.f, 0.f, 0.f, 0.f};
            #pragma unroll
            for (int kt = 0; kt < 2; kt++) {
                int base = ((nt * 2 + kt) * 32 + lane) * 2;
                uint2 bh = *(const uint2*)&g_w1f_hi[base];
                uint2 bl = *(const uint2*)&g_w1f_lo[base];
                mma16816(acc, a1hi[kt], (const uint32_t*)&bh);
                mma16816(acc, a1hi[kt], (const uint32_t*)&bl);
                mma16816(acc, a1lo[kt], (const uint32_t*)&bh);
            }
            // bias + relu, convert to A2 fragment (GEMM1 n == GEMM2 k)
            int nbase = c * 64 + ntl * 8 + kq;
            float f0 = fmaxf(acc[0] + sb1[nbase],     0.f);
            float f1 = fmaxf(acc[1] + sb1[nbase + 1], 0.f);
            float f2 = fmaxf(acc[2] + sb1[nbase],     0.f);
            float f3 = fmaxf(acc[3] + sb1[nbase + 1], 0.f);
            int ktl = ntl >> 1, hi8 = (ntl & 1) * 2;   // regs {0,1} or {2,3}
            split2(f0, f1, a2hi[ktl][hi8],     a2lo[ktl][hi8]);
            split2(f2, f3, a2hi[ktl][hi8 + 1], a2lo[ktl][hi8 + 1]);
        }
        // ---- GEMM2 partial: k-range c*64 .. c*64+63 ----
        #pragma unroll
        for (int ktl = 0; ktl < 4; ktl++) {
            int kt = c * 4 + ktl;
            #pragma unroll
            for (int nt = 0; nt < 8; nt++) {
                int base = ((nt * 32 + kt) * 32 + lane) * 2;
                uint2 bh = *(const uint2*)&g_w2f_hi[base];
                uint2 bl = *(const uint2*)&g_w2f_lo[base];
                mma16816(acc2[nt], a2hi[ktl], (const uint32_t*)&bh);
                mma16816(acc2[nt], a2hi[ktl], (const uint32_t*)&bl);
                mma16816(acc2[nt], a2lo[ktl], (const uint32_t*)&bh);
            }
        }
    }

    // write y: rows r0/r0+8, cols nt*8+kq (+1)
    float* yb = g_y + b * 8192;
    #pragma unroll
    for (int nt = 0; nt < 8; nt++) {
        int n = nt * 8 + kq;
        *(float2*)&yb[r0 * ROD + n]       = make_float2(acc2[nt][0], acc2[nt][1]);
        *(float2*)&yb[(r0 + 8) * ROD + n] = make_float2(acc2[nt][2], acc2[nt][3]);
    }
}

// ---------------- per-patch layer-2 aggregation + readout ----------------
__global__ void __launch_bounds__(256) k_agg2(const float* __restrict__ b2p) {
    __shared__ float yt[ROD * 65];
    __shared__ float a2[NN * ROD];
    __shared__ float gc[NE], sni[NN];
    __shared__ int   gs[NE], eo[NN + 1];
    int tid = threadIdx.x, p = blockIdx.x;
    for (int i = tid; i < 64 * ROD; i += 256) {
        int r = i >> 6, d = i & 63;
        yt[d * 65 + r] = g_y[p * 4096 + i];
    }
    for (int q = tid; q < NE; q += 256) { gs[q] = g_gsrc[q]; gc[q] = g_gcoefP[p * 256 + q]; }
    for (int i = tid; i <= NN; i += 256) eo[i] = g_poff[i];
    if (tid < NN) sni[tid] = g_pni[p * 64 + tid];
    __syncthreads();
    for (int i = tid; i < NN * ROD; i += 256) {
        int n = i >> 6, d = i & 63;
        float s = 0.f;
        for (int q = eo[n]; q < eo[n + 1]; q++) s += yt[d * 65 + gs[q]] * gc[q];
        a2[i] = fmaxf(sni[n] * s + b2p[d], 0.f);
    }
    __syncthreads();
    if (tid < ROD) {
        float s = 0.f;
        #pragma unroll 10
        for (int n = 0; n < NN; n++) s += a2[n * ROD + tid];
        g_readout[p * ROD + tid] = s * (1.f / NN);
    }
}

// ---------------- mesh stage ----------------
__global__ void k_mcount(const float* __restrict__ mew, const int* __restrict__ med) {
    int e = blockIdx.x * 256 + threadIdx.x;
    if (e < NEM) {
        int s = med[2 * e], d = med[2 * e + 1];
        float w = mew[e];
        atomicAdd(&g_mcnt[d], 1);
        atomicAdd(&g_degi[d], w);
        atomicAdd(&g_dego[s], w);
    }
}

__global__ void k_mscan() {
    __shared__ int sp[256];
    int t = threadIdx.x, base = t * 16;
    int s = 0;
    #pragma unroll
    for (int i = 0; i < 16; i++) s += g_mcnt[base + i];
    sp[t] = s; __syncthreads();
    if (t == 0) { int run = 0; for (int i = 0; i < 256; i++) { int v = sp[i]; sp[i] = run; run += v; } }
    __syncthreads();
    int run = sp[t];
    #pragma unroll
    for (int i = 0; i < 16; i++) {
        int v = g_mcnt[base + i];
        g_moff[base + i] = run; g_mcnt[base + i] = run; run += v;
    }
    if (t == 255) g_moff[NP] = NEM;
}

__global__ void k_norm() {
    int i = blockIdx.x * 256 + threadIdx.x;
    if (i < NP) {
        float a = g_degi[i], b = g_dego[i];
        g_nim[i] = (a > 0.f) ? rsqrtf(a) : 1.f;
        g_nom[i] = (b > 0.f) ? rsqrtf(b) : 1.f;
    }
}

__global__ void k_mscatter(const int* __restrict__ med) {
    int e = blockIdx.x * 256 + threadIdx.x;
    if (e < NEM) {
        int d = med[2 * e + 1];
        int pos = atomicAdd(&g_mcnt[d], 1);
        g_meid[pos] = e;
    }
}

__global__ void k_mprep(const float* __restrict__ mew, const int* __restrict__ med) {
    int q = blockIdx.x * 256 + threadIdx.x;
    if (q < NEM) {
        int e = g_meid[q];
        int s = med[2 * e];
        g_msrc[q] = s;
        g_mcoef[q] = mew[e] * g_nom[s];
    }
}

__global__ void k_mgc1(const float* __restrict__ W1m, const float* __restrict__ b1m) {
    extern __shared__ float smf[];
    float* sW = smf;
    float* sA = smf + ROD * HIDD;
    int tid = threadIdx.x, p0 = blockIdx.x * 16;
    for (int i = tid; i < ROD * HIDD; i += 256) sW[i] = W1m[i];
    for (int i = tid; i < 16 * ROD; i += 256) sA[i] = 0.f;
    __syncthreads();
    int d = tid & 63, qo = tid >> 6;
    for (int r = 0; r < 16; r++) {
        int t = p0 + r;
        int b = g_moff[t], en = g_moff[t + 1];
        float acc = 0.f;
        for (int q = b + qo; q < en; q += 4)
            acc += g_readout[g_msrc[q] * ROD + d] * g_mcoef[q];
        atomicAdd(&sA[r * ROD + d], acc);
    }
    __syncthreads();
    for (int i = tid; i < 16 * ROD; i += 256) sA[i] *= g_nim[p0 + (i >> 6)];
    __syncthreads();
    float acc[16];
    #pragma unroll
    for (int r = 0; r < 16; r++) acc[r] = 0.f;
    #pragma unroll 2
    for (int k = 0; k < ROD; k++) {
        float wv = sW[k * HIDD + tid];
        #pragma unroll
        for (int r = 0; r < 16; r++) acc[r] = fmaf(sA[r * ROD + k], wv, acc[r]);
    }
    float bb = b1m[tid];
    #pragma unroll
    for (int r = 0; r < 16; r++)
        g_h1m[(p0 + r) * HIDD + tid] = fmaxf(acc[r] + bb, 0.f);
}

__global__ void k_mgc2(const float* __restrict__ W2m, const float* __restrict__ b2m,
                       const float* __restrict__ Wu1, const float* __restrict__ bu1) {
    extern __shared__ float smf[];
    float* sA = smf;
    float* sH = smf + 16 * HIDD;
    int tid = threadIdx.x, p0 = blockIdx.x * 16;
    for (int r = 0; r < 16; r++) {
        int t = p0 + r;
        int b = g_moff[t], en = g_moff[t + 1];
        float acc = 0.f;
        for (int q = b; q < en; q++)
            acc += g_h1m[g_msrc[q] * HIDD + tid] * g_mcoef[q];
        sA[r * HIDD + tid] = acc * g_nim[t];
    }
    __syncthreads();
    {
        float acc[16];
        #pragma unroll
        for (int r = 0; r < 16; r++) acc[r] = 0.f;
        #pragma unroll 2
        for (int k = 0; k < HIDD; k++) {
            float wv = __ldg(&W2m[k * HIDD + tid]);
            #pragma unroll
            for (int r = 0; r < 16; r++) acc[r] = fmaf(sA[r * HIDD + k], wv, acc[r]);
        }
        float bb = b2m[tid];
        #pragma unroll
        for (int r = 0; r < 16; r++) sH[r * HIDD + tid] = fmaxf(acc[r] + bb, 0.f);
    }
    __syncthreads();
    {
        int m = tid & 127, grp = tid >> 7;
        float acc[8];
        #pragma unroll
        for (int r = 0; r < 8; r++) acc[r] = 0.f;
        #pragma unroll 2
        for (int k = 0; k < HIDD; k++) {
            float wv = __ldg(&Wu1[k * RHD + m]);
            #pragma unroll
            for (int r = 0; r < 8; r++)
                acc[r] = fmaf(sH[(grp * 8 + r) * HIDD + k], wv, acc[r]);
        }
        float bb = bu1[m];
        float s = 0.f;
        #pragma unroll
        for (int r = 0; r < 8; r++) s += fmaxf(acc[r] + bb, 0.f);
        atomicAdd(&g_r[m], s);
    }
}

__global__ void k_final(const float* __restrict__ Wout, const float* __restrict__ bout,
                        float* __restrict__ out) {
    int o = threadIdx.x;
    if (o < OUTD) {
        float s = bout[o];
        for (int j = 0; j < RHD; j++) s = fmaf(g_r[j], Wout[j * OUTD + o], s);
        out[o] = s;
    }
}

// ---------------- launch ----------------
extern "C" void kernel_launch(void* const* d_in, const int* in_sizes, int n_in,
                              void* d_out, int out_size) {
    const float* feats = (const float*)d_in[0];
    const float* pew   = (const float*)d_in[1];
    const float* mew   = (const float*)d_in[2];
    const float* W1p   = (const float*)d_in[3];
    const float* b1p   = (const float*)d_in[4];
    const float* W2p   = (const float*)d_in[5];
    const float* b2p   = (const float*)d_in[6];
    const float* W1m   = (const float*)d_in[7];
    const float* b1m   = (const float*)d_in[8];
    const float* W2m   = (const float*)d_in[9];
    const float* b2m   = (const float*)d_in[10];
    const float* Wu1   = (const float*)d_in[11];
    const float* bu1   = (const float*)d_in[12];
    const float* Wout  = (const float*)d_in[13];
    const float* bout  = (const float*)d_in[14];
    const int*   pedg  = (const int*)d_in[15];
    const int*   medg  = (const int*)d_in[16];

    cudaFuncSetAttribute(k_mgc1, cudaFuncAttributeMaxDynamicSharedMemorySize, 69632);

    k_csr<<<1, 1>>>(pedg);
    k_wprep<<<96, 256>>>(W1p, W2p);
    k_agg1<<<NP, 256>>>(feats, pew, pedg);
    k_mlp<<<NP / 2, 256>>>(b1p);                 // ncu capture slot (#4)
    k_agg2<<<NP, 256>>>(b2p);
    k_zero0<<<16, 256>>>();
    k_mcount<<<NEM / 256, 256>>>(mew, medg);
    k_mscan<<<1, 256>>>();
    k_norm<<<NP / 256, 256>>>();
    k_mscatter<<<NEM / 256, 256>>>(medg);
    k_mprep<<<NEM / 256, 256>>>(mew, medg);
    k_mgc1<<<NP / 16, 256, 69632>>>(W1m, b1m);
    k_mgc2<<<NP / 16, 256, 32768>>>(W2m, b2m, Wu1, bu1);
    k_final<<<1, 32>>>(Wout, bout, (float*)d_out);
}

// round 8
// speedup vs baseline: 1.5225x; 1.2116x over previous
#include <cuda_runtime.h>
#include <cuda_bf16.h>
#include <cstdint>

#define NP   4096
#define NN   50
#define NE   250
#define NEM  65536
#define IND  32
#define PHD  512
#define ROD  64
#define HIDD 256
#define RHD  128
#define OUTD 15

// ---------------- persistent device scratch ----------------
__device__ float g_readout[NP * ROD];
__device__ float g_degi[NP], g_dego[NP], g_nim[NP], g_nom[NP];
__device__ float g_h1m[NP * HIDD];
__device__ float g_r[RHD];
__device__ int   g_poff[NN + 1];
__device__ int   g_peid[NE];
__device__ int   g_gsrc[NE];
__device__ int   g_mcnt[NP];
__device__ int   g_moff[NP + 1];
__device__ int   g_meid[NEM];
__device__ int   g_msrc[NEM];
__device__ float g_mcoef[NEM];
// patch-MLP staging
__device__ float g_agg[NP * 64 * IND];
__device__ float g_y[NP * 64 * ROD];
__device__ float g_gcoefP[NP * 256];
__device__ float g_pni[NP * 64];
// fragment-packed weights: [nt][kt][lane][reg] as u32 (two bf16, low = smaller k)
__device__ uint32_t g_w1f_hi[64 * 2 * 32 * 2];
__device__ uint32_t g_w1f_lo[64 * 2 * 32 * 2];
__device__ uint32_t g_w2f_hi[8 * 32 * 32 * 2];
__device__ uint32_t g_w2f_lo[8 * 32 * 32 * 2];

// ---------------- helpers ----------------
__device__ __forceinline__ uint32_t pkbf(__nv_bfloat16 a, __nv_bfloat16 b) {
    unsigned short ua = *(unsigned short*)&a, ub = *(unsigned short*)&b;
    return ((uint32_t)ub << 16) | (uint32_t)ua;
}
__device__ __forceinline__ void split2(float x0, float x1, uint32_t& hi, uint32_t& lo) {
    __nv_bfloat16 h0 = __float2bfloat16(x0), h1 = __float2bfloat16(x1);
    __nv_bfloat16 l0 = __float2bfloat16(x0 - __bfloat162float(h0));
    __nv_bfloat16 l1 = __float2bfloat16(x1 - __bfloat162float(h1));
    hi = pkbf(h0, h1); lo = pkbf(l0, l1);
}
__device__ __forceinline__ void mma16816(float* c, const uint32_t* a, const uint32_t* b) {
    asm volatile("mma.sync.aligned.m16n8k16.row.col.f32.bf16.bf16.f32 "
        "{%0,%1,%2,%3}, {%4,%5,%6,%7}, {%8,%9}, {%0,%1,%2,%3};"
        : "+f"(c[0]), "+f"(c[1]), "+f"(c[2]), "+f"(c[3])
        : "r"(a[0]), "r"(a[1]), "r"(a[2]), "r"(a[3]), "r"(b[0]), "r"(b[1]));
}

// ---------------- setup kernels ----------------
__global__ void k_zero0() {
    int i = blockIdx.x * 256 + threadIdx.x;
    g_mcnt[i] = 0; g_degi[i] = 0.f; g_dego[i] = 0.f;
    if (i < RHD) g_r[i] = 0.f;
}

__global__ void k_csr(const int* __restrict__ pedges) {
    if (threadIdx.x != 0 || blockIdx.x != 0) return;
    int cnt[NN];
    for (int n = 0; n < NN; n++) cnt[n] = 0;
    for (int e = 0; e < NE; e++) cnt[pedges[2 * e + 1]]++;
    int off = 0;
    for (int n = 0; n < NN; n++) { g_poff[n] = off; off += cnt[n]; cnt[n] = g_poff[n]; }
    g_poff[NN] = off;
    for (int e = 0; e < NE; e++) { int d = pedges[2 * e + 1]; g_peid[cnt[d]++] = e; }
    for (int q = 0; q < NE; q++) g_gsrc[q] = pedges[2 * g_peid[q]];
}

__global__ void k_wprep(const float* __restrict__ W1p, const float* __restrict__ W2p) {
    int i = blockIdx.x * 256 + threadIdx.x;
    if (i < 8192) {
        int reg = i & 1, lane = (i >> 1) & 31, kt = (i >> 6) & 1, nt = i >> 7;
        int n = nt * 8 + (lane >> 2);
        int k = kt * 16 + (lane & 3) * 2 + reg * 8;
        float v0 = W1p[k * PHD + n], v1 = W1p[(k + 1) * PHD + n];
        uint32_t hi, lo; split2(v0, v1, hi, lo);
        g_w1f_hi[i] = hi; g_w1f_lo[i] = lo;
    } else if (i < 8192 + 16384) {
        int j = i - 8192;
        int reg = j & 1, lane = (j >> 1) & 31, kt = (j >> 6) & 31, nt = j >> 11;
        int n = nt * 8 + (lane >> 2);
        int k = kt * 16 + (lane & 3) * 2 + reg * 8;
        float v0 = W2p[k * ROD + n], v1 = W2p[(k + 1) * ROD + n];
        uint32_t hi, lo; split2(v0, v1, hi, lo);
        g_w2f_hi[j] = hi; g_w2f_lo[j] = lo;
    }
}

// ---------------- per-patch layer-1 aggregation ----------------
__global__ void __launch_bounds__(256) k_agg1(const float* __restrict__ feats,
                                              const float* __restrict__ pew,
                                              const int* __restrict__ pedges) {
    __shared__ int   ssrc[NE], sdst[NE], eoff[NN + 1], sgs[NE];
    __shared__ float coef[NE], gc[NE], ni[NN], no_[NN], x[NN * IND];
    int tid = threadIdx.x, p = blockIdx.x;
    for (int i = tid; i < NE; i += 256) {
        ssrc[i] = pedges[2 * i]; sdst[i] = pedges[2 * i + 1];
        coef[i] = pew[p * NE + i]; sgs[i] = g_gsrc[i];
    }
    for (int i = tid; i <= NN; i += 256) eoff[i] = g_poff[i];
    for (int i = tid; i < NN; i += 256) { ni[i] = 0.f; no_[i] = 0.f; }
    for (int i = tid; i < NN * IND; i += 256) x[i] = feats[p * NN * IND + i];
    __syncthreads();
    for (int i = tid; i < NE; i += 256) {
        float w = coef[i];
        atomicAdd(&ni[sdst[i]], w);
        atomicAdd(&no_[ssrc[i]], w);
    }
    __syncthreads();
    if (tid < NN) {
        float a = ni[tid], b = no_[tid];
        ni[tid]  = (a > 0.f) ? rsqrtf(a) : 1.f;
        no_[tid] = (b > 0.f) ? rsqrtf(b) : 1.f;
    }
    __syncthreads();
    for (int q = tid; q < NE; q += 256) {
        int e = g_peid[q];
        gc[q] = coef[e] * no_[ssrc[e]];
    }
    __syncthreads();
    for (int i = tid; i < 64 * IND; i += 256) {
        int n = i >> 5, d = i & 31;
        float s = 0.f;
        if (n < NN) {
            int b0 = eoff[n], e0 = eoff[n + 1];
            for (int q = b0; q < e0; q++) s += x[sgs[q] * IND + d] * gc[q];
            s *= ni[n];
        }
        g_agg[p * 2048 + i] = s;
    }
    for (int q = tid; q < NE; q += 256) g_gcoefP[p * 256 + q] = gc[q];
    if (tid < NN) g_pni[p * 64 + tid] = ni[tid];
}

// ---------------- fused MLP on tensor cores (mma.sync, 2 patches/CTA) ----------------
// ktl-interleaved: a2 fragments live only across one 16-k tile -> ~110 regs -> 2 CTAs/SM
__global__ void __launch_bounds__(256, 2) k_mlp(const float* __restrict__ b1p) {
    __shared__ float sagg[128 * IND];
    __shared__ float sb1[PHD];
    const int tid = threadIdx.x, lane = tid & 31, wid = tid >> 5;
    const int b = blockIdx.x;
    const int m0 = wid * 16;
    const int r0 = m0 + (lane >> 2);
    const int kq = (lane & 3) * 2;

    for (int i = tid; i < 128 * IND; i += 256) sagg[i] = g_agg[b * 4096 + i];
    for (int i = tid; i < PHD; i += 256) sb1[i] = b1p[i];
    __syncthreads();

    // A1 fragments (K=32 -> 2 ktiles), hi/lo
    uint32_t a1hi[2][4], a1lo[2][4];
    #pragma unroll
    for (int kt = 0; kt < 2; kt++) {
        #pragma unroll
        for (int j = 0; j < 4; j++) {
            int dr = (j & 1) * 8, dk = (j >> 1) * 8;
            int rr = r0 + dr, kk = kt * 16 + kq + dk;
            split2(sagg[rr * IND + kk], sagg[rr * IND + kk + 1],
                   a1hi[kt][j], a1lo[kt][j]);
        }
    }

    float acc2[8][4];
    #pragma unroll
    for (int nt = 0; nt < 8; nt++)
        #pragma unroll
        for (int j = 0; j < 4; j++) acc2[nt][j] = 0.f;

    for (int c = 0; c < 8; c++) {
        #pragma unroll
        for (int ktl = 0; ktl < 4; ktl++) {
            // ---- GEMM1: two 8-col groups (ntl = 2*ktl, 2*ktl+1) -> one a2 frag ----
            uint32_t a2hi[4], a2lo[4];
            #pragma unroll
            for (int half = 0; half < 2; half++) {
                int ntl = 2 * ktl + half;
                int nt = c * 8 + ntl;
                float acc[4] = {0.f, 0.f, 0.f, 0.f};
                #pragma unroll
                for (int kt = 0; kt < 2; kt++) {
                    int base = ((nt * 2 + kt) * 32 + lane) * 2;
                    uint2 bh = *(const uint2*)&g_w1f_hi[base];
                    uint2 bl = *(const uint2*)&g_w1f_lo[base];
                    mma16816(acc, a1hi[kt], (const uint32_t*)&bh);
                    mma16816(acc, a1hi[kt], (const uint32_t*)&bl);
                    mma16816(acc, a1lo[kt], (const uint32_t*)&bh);
                }
                int nbase = c * 64 + ntl * 8 + kq;
                float f0 = fmaxf(acc[0] + sb1[nbase],     0.f);
                float f1 = fmaxf(acc[1] + sb1[nbase + 1], 0.f);
                float f2 = fmaxf(acc[2] + sb1[nbase],     0.f);
                float f3 = fmaxf(acc[3] + sb1[nbase + 1], 0.f);
                split2(f0, f1, a2hi[2 * half],     a2lo[2 * half]);
                split2(f2, f3, a2hi[2 * half + 1], a2lo[2 * half + 1]);
            }
            // ---- GEMM2 partial for this 16-k tile ----
            int kt = c * 4 + ktl;
            #pragma unroll
            for (int nt = 0; nt < 8; nt++) {
                int base = ((nt * 32 + kt) * 32 + lane) * 2;
                uint2 bh = *(const uint2*)&g_w2f_hi[base];
                uint2 bl = *(const uint2*)&g_w2f_lo[base];
                mma16816(acc2[nt], a2hi, (const uint32_t*)&bh);
                mma16816(acc2[nt], a2hi, (const uint32_t*)&bl);
                mma16816(acc2[nt], a2lo, (const uint32_t*)&bh);
            }
        }
    }

    float* yb = g_y + b * 8192;
    #pragma unroll
    for (int nt = 0; nt < 8; nt++) {
        int n = nt * 8 + kq;
        *(float2*)&yb[r0 * ROD + n]       = make_float2(acc2[nt][0], acc2[nt][1]);
        *(float2*)&yb[(r0 + 8) * ROD + n] = make_float2(acc2[nt][2], acc2[nt][3]);
    }
}

// ---------------- per-patch layer-2 aggregation + readout ----------------
__global__ void __launch_bounds__(256) k_agg2(const float* __restrict__ b2p) {
    __shared__ float yt[ROD * 65];
    __shared__ float a2[NN * ROD];
    __shared__ float gc[NE], sni[NN];
    __shared__ int   gs[NE], eo[NN + 1];
    int tid = threadIdx.x, p = blockIdx.x;
    for (int i = tid; i < 64 * ROD; i += 256) {
        int r = i >> 6, d = i & 63;
        yt[d * 65 + r] = g_y[p * 4096 + i];
    }
    for (int q = tid; q < NE; q += 256) { gs[q] = g_gsrc[q]; gc[q] = g_gcoefP[p * 256 + q]; }
    for (int i = tid; i <= NN; i += 256) eo[i] = g_poff[i];
    if (tid < NN) sni[tid] = g_pni[p * 64 + tid];
    __syncthreads();
    for (int i = tid; i < NN * ROD; i += 256) {
        int n = i >> 6, d = i & 63;
        float s = 0.f;
        for (int q = eo[n]; q < eo[n + 1]; q++) s += yt[d * 65 + gs[q]] * gc[q];
        a2[i] = fmaxf(sni[n] * s + b2p[d], 0.f);
    }
    __syncthreads();
    if (tid < ROD) {
        float s = 0.f;
        #pragma unroll 10
        for (int n = 0; n < NN; n++) s += a2[n * ROD + tid];
        g_readout[p * ROD + tid] = s * (1.f / NN);
    }
}

// ---------------- mesh stage ----------------
__global__ void k_mcount(const float* __restrict__ mew, const int* __restrict__ med) {
    int e = blockIdx.x * 256 + threadIdx.x;
    if (e < NEM) {
        int s = med[2 * e], d = med[2 * e + 1];
        float w = mew[e];
        atomicAdd(&g_mcnt[d], 1);
        atomicAdd(&g_degi[d], w);
        atomicAdd(&g_dego[s], w);
    }
}

__global__ void k_mscan() {
    __shared__ int sp[256];
    int t = threadIdx.x, base = t * 16;
    int s = 0;
    #pragma unroll
    for (int i = 0; i < 16; i++) s += g_mcnt[base + i];
    sp[t] = s; __syncthreads();
    if (t == 0) { int run = 0; for (int i = 0; i < 256; i++) { int v = sp[i]; sp[i] = run; run += v; } }
    __syncthreads();
    int run = sp[t];
    #pragma unroll
    for (int i = 0; i < 16; i++) {
        int v = g_mcnt[base + i];
        g_moff[base + i] = run; g_mcnt[base + i] = run; run += v;
    }
    if (t == 255) g_moff[NP] = NEM;
}

__global__ void k_norm() {
    int i = blockIdx.x * 256 + threadIdx.x;
    if (i < NP) {
        float a = g_degi[i], b = g_dego[i];
        g_nim[i] = (a > 0.f) ? rsqrtf(a) : 1.f;
        g_nom[i] = (b > 0.f) ? rsqrtf(b) : 1.f;
    }
}

__global__ void k_mscatter(const int* __restrict__ med) {
    int e = blockIdx.x * 256 + threadIdx.x;
    if (e < NEM) {
        int d = med[2 * e + 1];
        int pos = atomicAdd(&g_mcnt[d], 1);
        g_meid[pos] = e;
    }
}

__global__ void k_mprep(const float* __restrict__ mew, const int* __restrict__ med) {
    int q = blockIdx.x * 256 + threadIdx.x;
    if (q < NEM) {
        int e = g_meid[q];
        int s = med[2 * e];
        g_msrc[q] = s;
        g_mcoef[q] = mew[e] * g_nom[s];
    }
}

__global__ void k_mgc1(const float* __restrict__ W1m, const float* __restrict__ b1m) {
    extern __shared__ float smf[];
    float* sW = smf;
    float* sA = smf + ROD * HIDD;
    int tid = threadIdx.x, p0 = blockIdx.x * 16;
    for (int i = tid; i < ROD * HIDD; i += 256) sW[i] = W1m[i];
    for (int i = tid; i < 16 * ROD; i += 256) sA[i] = 0.f;
    __syncthreads();
    int d = tid & 63, qo = tid >> 6;
    for (int r = 0; r < 16; r++) {
        int t = p0 + r;
        int b = g_moff[t], en = g_moff[t + 1];
        float acc = 0.f;
        for (int q = b + qo; q < en; q += 4)
            acc += g_readout[g_msrc[q] * ROD + d] * g_mcoef[q];
        atomicAdd(&sA[r * ROD + d], acc);
    }
    __syncthreads();
    for (int i = tid; i < 16 * ROD; i += 256) sA[i] *= g_nim[p0 + (i >> 6)];
    __syncthreads();
    float acc[16];
    #pragma unroll
    for (int r = 0; r < 16; r++) acc[r] = 0.f;
    #pragma unroll 2
    for (int k = 0; k < ROD; k++) {
        float wv = sW[k * HIDD + tid];
        #pragma unroll
        for (int r = 0; r < 16; r++) acc[r] = fmaf(sA[r * ROD + k], wv, acc[r]);
    }
    float bb = b1m[tid];
    #pragma unroll
    for (int r = 0; r < 16; r++)
        g_h1m[(p0 + r) * HIDD + tid] = fmaxf(acc[r] + bb, 0.f);
}

__global__ void k_mgc2(const float* __restrict__ W2m, const float* __restrict__ b2m,
                       const float* __restrict__ Wu1, const float* __restrict__ bu1) {
    extern __shared__ float smf[];
    float* sA = smf;
    float* sH = smf + 16 * HIDD;
    int tid = threadIdx.x, p0 = blockIdx.x * 16;
    for (int r = 0; r < 16; r++) {
        int t = p0 + r;
        int b = g_moff[t], en = g_moff[t + 1];
        float acc = 0.f;
        for (int q = b; q < en; q++)
            acc += g_h1m[g_msrc[q] * HIDD + tid] * g_mcoef[q];
        sA[r * HIDD + tid] = acc * g_nim[t];
    }
    __syncthreads();
    {
        float acc[16];
        #pragma unroll
        for (int r = 0; r < 16; r++) acc[r] = 0.f;
        #pragma unroll 2
        for (int k = 0; k < HIDD; k++) {
            float wv = __ldg(&W2m[k * HIDD + tid]);
            #pragma unroll
            for (int r = 0; r < 16; r++) acc[r] = fmaf(sA[r * HIDD + k], wv, acc[r]);
        }
        float bb = b2m[tid];
        #pragma unroll
        for (int r = 0; r < 16; r++) sH[r * HIDD + tid] = fmaxf(acc[r] + bb, 0.f);
    }
    __syncthreads();
    {
        int m = tid & 127, grp = tid >> 7;
        float acc[8];
        #pragma unroll
        for (int r = 0; r < 8; r++) acc[r] = 0.f;
        #pragma unroll 2
        for (int k = 0; k < HIDD; k++) {
            float wv = __ldg(&Wu1[k * RHD + m]);
            #pragma unroll
            for (int r = 0; r < 8; r++)
                acc[r] = fmaf(sH[(grp * 8 + r) * HIDD + k], wv, acc[r]);
        }
        float bb = bu1[m];
        float s = 0.f;
        #pragma unroll
        for (int r = 0; r < 8; r++) s += fmaxf(acc[r] + bb, 0.f);
        atomicAdd(&g_r[m], s);
    }
}

__global__ void k_final(const float* __restrict__ Wout, const float* __restrict__ bout,
                        float* __restrict__ out) {
    int o = threadIdx.x;
    if (o < OUTD) {
        float s = bout[o];
        for (int j = 0; j < RHD; j++) s = fmaf(g_r[j], Wout[j * OUTD + o], s);
        out[o] = s;
    }
}

// ---------------- launch ----------------
extern "C" void kernel_launch(void* const* d_in, const int* in_sizes, int n_in,
                              void* d_out, int out_size) {
    const float* feats = (const float*)d_in[0];
    const float* pew   = (const float*)d_in[1];
    const float* mew   = (const float*)d_in[2];
    const float* W1p   = (const float*)d_in[3];
    const float* b1p   = (const float*)d_in[4];
    const float* W2p   = (const float*)d_in[5];
    const float* b2p   = (const float*)d_in[6];
    const float* W1m   = (const float*)d_in[7];
    const float* b1m   = (const float*)d_in[8];
    const float* W2m   = (const float*)d_in[9];
    const float* b2m   = (const float*)d_in[10];
    const float* Wu1   = (const float*)d_in[11];
    const float* bu1   = (const float*)d_in[12];
    const float* Wout  = (const float*)d_in[13];
    const float* bout  = (const float*)d_in[14];
    const int*   pedg  = (const int*)d_in[15];
    const int*   medg  = (const int*)d_in[16];

    cudaFuncSetAttribute(k_mgc1, cudaFuncAttributeMaxDynamicSharedMemorySize, 69632);

    k_csr<<<1, 1>>>(pedg);
    k_wprep<<<96, 256>>>(W1p, W2p);
    k_agg1<<<NP, 256>>>(feats, pew, pedg);
    k_mlp<<<NP / 2, 256>>>(b1p);                 // ncu capture slot (#4)
    k_agg2<<<NP, 256>>>(b2p);
    k_zero0<<<16, 256>>>();
    k_mcount<<<NEM / 256, 256>>>(mew, medg);
    k_mscan<<<1, 256>>>();
    k_norm<<<NP / 256, 256>>>();
    k_mscatter<<<NEM / 256, 256>>>(medg);
    k_mprep<<<NEM / 256, 256>>>(mew, medg);
    k_mgc1<<<NP / 16, 256, 69632>>>(W1m, b1m);
    k_mgc2<<<NP / 16, 256, 32768>>>(W2m, b2m, Wu1, bu1);
    k_final<<<1, 32>>>(Wout, bout, (float*)d_out);
}

// round 9
// speedup vs baseline: 1.6318x; 1.0718x over previous
#include <cuda_runtime.h>
#include <cuda_bf16.h>
#include <cstdint>

#define NP   4096
#define NN   50
#define NE   250
#define NEM  65536
#define IND  32
#define PHD  512
#define ROD  64
#define HIDD 256
#define RHD  128
#define OUTD 15

// ---------------- persistent device scratch ----------------
__device__ float g_readout[NP * ROD];
__device__ float g_degi[NP], g_dego[NP], g_nim[NP], g_nom[NP];
__device__ float g_h1m[NP * HIDD];
__device__ float g_r[RHD];
__device__ int   g_poff[NN + 1];
__device__ int   g_peid[NE];
__device__ int   g_gsrc[NE];
__device__ int   g_mcnt[NP];
__device__ int   g_moff[NP + 1];
__device__ int   g_meid[NEM];
__device__ int   g_msrc[NEM];
__device__ float g_mcoef[NEM];
// patch-MLP staging
__device__ float g_agg[NP * 64 * IND];
__device__ float g_y[NP * 64 * ROD];
__device__ float g_gcoefP[NP * 256];
__device__ float g_pni[NP * 64];
// fragment-packed weights, uint4 = {hi_reg0, hi_reg1, lo_reg0, lo_reg1}
__device__ uint4 g_w1f4[64 * 2 * 32];     // W1: [nt][kt][lane]
__device__ uint4 g_w2f4[8 * 32 * 32];     // W2: [nt][kt][lane]

// ---------------- helpers ----------------
__device__ __forceinline__ uint32_t pkbf(__nv_bfloat16 a, __nv_bfloat16 b) {
    unsigned short ua = *(unsigned short*)&a, ub = *(unsigned short*)&b;
    return ((uint32_t)ub << 16) | (uint32_t)ua;
}
__device__ __forceinline__ void split2(float x0, float x1, uint32_t& hi, uint32_t& lo) {
    __nv_bfloat16 h0 = __float2bfloat16(x0), h1 = __float2bfloat16(x1);
    __nv_bfloat16 l0 = __float2bfloat16(x0 - __bfloat162float(h0));
    __nv_bfloat16 l1 = __float2bfloat16(x1 - __bfloat162float(h1));
    hi = pkbf(h0, h1); lo = pkbf(l0, l1);
}
__device__ __forceinline__ void mma16816(float* c, const uint32_t* a, const uint32_t* b) {
    asm volatile("mma.sync.aligned.m16n8k16.row.col.f32.bf16.bf16.f32 "
        "{%0,%1,%2,%3}, {%4,%5,%6,%7}, {%8,%9}, {%0,%1,%2,%3};"
        : "+f"(c[0]), "+f"(c[1]), "+f"(c[2]), "+f"(c[3])
        : "r"(a[0]), "r"(a[1]), "r"(a[2]), "r"(a[3]), "r"(b[0]), "r"(b[1]));
}

// ---------------- setup kernels ----------------
__global__ void k_zero0() {
    int i = blockIdx.x * 256 + threadIdx.x;
    g_mcnt[i] = 0; g_degi[i] = 0.f; g_dego[i] = 0.f;
    if (i < RHD) g_r[i] = 0.f;
}

// parallel deterministic CSR (order within dst preserved -> bit-identical sums)
__global__ void k_csr(const int* __restrict__ pedges) {
    __shared__ int sdst[NE], ssrc[NE], cnt[NN], off[NN + 1];
    int tid = threadIdx.x;
    for (int e = tid; e < NE; e += 256) {
        ssrc[e] = pedges[2 * e];
        sdst[e] = pedges[2 * e + 1];
    }
    if (tid < NN) cnt[tid] = 0;
    __syncthreads();
    for (int e = tid; e < NE; e += 256) atomicAdd(&cnt[sdst[e]], 1);
    __syncthreads();
    if (tid == 0) {
        int run = 0;
        for (int n = 0; n < NN; n++) { off[n] = run; run += cnt[n]; }
        off[NN] = run;
    }
    __syncthreads();
    if (tid <= NN) g_poff[tid] = off[tid];
    if (tid < NE) {
        int d = sdst[tid], rank = 0;
        for (int e2 = 0; e2 < tid; e2++) rank += (sdst[e2] == d);
        int pos = off[d] + rank;
        g_peid[pos] = tid;
        g_gsrc[pos] = ssrc[tid];
    }
}

__global__ void k_wprep(const float* __restrict__ W1p, const float* __restrict__ W2p) {
    int i = blockIdx.x * 256 + threadIdx.x;    // 48*256 = 12288
    if (i < 4096) {                            // W1 frags
        int lane = i & 31, kt = (i >> 5) & 1, nt = i >> 6;
        int n = nt * 8 + (lane >> 2);
        int k0 = kt * 16 + (lane & 3) * 2;
        uint32_t h0, l0, h1, l1;
        split2(W1p[k0 * PHD + n],       W1p[(k0 + 1) * PHD + n], h0, l0);
        split2(W1p[(k0 + 8) * PHD + n], W1p[(k0 + 9) * PHD + n], h1, l1);
        g_w1f4[i] = make_uint4(h0, h1, l0, l1);
    } else if (i < 4096 + 8192) {              // W2 frags
        int j = i - 4096;
        int lane = j & 31, kt = (j >> 5) & 31, nt = j >> 10;
        int n = nt * 8 + (lane >> 2);
        int k0 = kt * 16 + (lane & 3) * 2;
        uint32_t h0, l0, h1, l1;
        split2(W2p[k0 * ROD + n],       W2p[(k0 + 1) * ROD + n], h0, l0);
        split2(W2p[(k0 + 8) * ROD + n], W2p[(k0 + 9) * ROD + n], h1, l1);
        g_w2f4[j] = make_uint4(h0, h1, l0, l1);
    }
}

// ---------------- per-patch layer-1 aggregation ----------------
__global__ void __launch_bounds__(256) k_agg1(const float* __restrict__ feats,
                                              const float* __restrict__ pew,
                                              const int* __restrict__ pedges) {
    __shared__ int   ssrc[NE], sdst[NE], eoff[NN + 1], sgs[NE];
    __shared__ float coef[NE], gc[NE], ni[NN], no_[NN], x[NN * IND];
    int tid = threadIdx.x, p = blockIdx.x;
    for (int i = tid; i < NE; i += 256) {
        ssrc[i] = pedges[2 * i]; sdst[i] = pedges[2 * i + 1];
        coef[i] = pew[p * NE + i]; sgs[i] = g_gsrc[i];
    }
    for (int i = tid; i <= NN; i += 256) eoff[i] = g_poff[i];
    for (int i = tid; i < NN; i += 256) { ni[i] = 0.f; no_[i] = 0.f; }
    for (int i = tid; i < NN * IND; i += 256) x[i] = feats[p * NN * IND + i];
    __syncthreads();
    for (int i = tid; i < NE; i += 256) {
        float w = coef[i];
        atomicAdd(&ni[sdst[i]], w);
        atomicAdd(&no_[ssrc[i]], w);
    }
    __syncthreads();
    if (tid < NN) {
        float a = ni[tid], b = no_[tid];
        ni[tid]  = (a > 0.f) ? rsqrtf(a) : 1.f;
        no_[tid] = (b > 0.f) ? rsqrtf(b) : 1.f;
    }
    __syncthreads();
    for (int q = tid; q < NE; q += 256) {
        int e = g_peid[q];
        gc[q] = coef[e] * no_[ssrc[e]];
    }
    __syncthreads();
    for (int i = tid; i < 64 * IND; i += 256) {
        int n = i >> 5, d = i & 31;
        float s = 0.f;
        if (n < NN) {
            int b0 = eoff[n], e0 = eoff[n + 1];
            for (int q = b0; q < e0; q++) s += x[sgs[q] * IND + d] * gc[q];
            s *= ni[n];
        }
        g_agg[p * 2048 + i] = s;
    }
    for (int q = tid; q < NE; q += 256) g_gcoefP[p * 256 + q] = gc[q];
    if (tid < NN) g_pni[p * 64 + tid] = ni[tid];
}

// ---------------- fused MLP on tensor cores (mma.sync, 2 patches/CTA) ----------------
__global__ void __launch_bounds__(256, 2) k_mlp(const float* __restrict__ b1p) {
    __shared__ float sagg[128 * IND];
    __shared__ float sb1[PHD];
    const int tid = threadIdx.x, lane = tid & 31, wid = tid >> 5;
    const int b = blockIdx.x;
    const int m0 = wid * 16;
    const int r0 = m0 + (lane >> 2);
    const int kq = (lane & 3) * 2;

    for (int i = tid; i < 128 * IND; i += 256) sagg[i] = g_agg[b * 4096 + i];
    for (int i = tid; i < PHD; i += 256) sb1[i] = b1p[i];
    __syncthreads();

    // A1 fragments (K=32 -> 2 ktiles), hi/lo
    uint32_t a1hi[2][4], a1lo[2][4];
    #pragma unroll
    for (int kt = 0; kt < 2; kt++) {
        #pragma unroll
        for (int j = 0; j < 4; j++) {
            int dr = (j & 1) * 8, dk = (j >> 1) * 8;
            int rr = r0 + dr, kk = kt * 16 + kq + dk;
            split2(sagg[rr * IND + kk], sagg[rr * IND + kk + 1],
                   a1hi[kt][j], a1lo[kt][j]);
        }
    }

    float acc2[8][4];
    #pragma unroll
    for (int nt = 0; nt < 8; nt++)
        #pragma unroll
        for (int j = 0; j < 4; j++) acc2[nt][j] = 0.f;

    for (int c = 0; c < 8; c++) {
        #pragma unroll
        for (int ktl = 0; ktl < 4; ktl++) {
            // ---- GEMM1: two 8-col groups -> one a2 fragment ----
            uint32_t a2hi[4], a2lo[4];
            #pragma unroll
            for (int half = 0; half < 2; half++) {
                int ntl = 2 * ktl + half;
                int nt = c * 8 + ntl;
                float acc[4] = {0.f, 0.f, 0.f, 0.f};
                #pragma unroll
                for (int kt = 0; kt < 2; kt++) {
                    uint4 w = g_w1f4[(nt * 2 + kt) * 32 + lane];
                    uint32_t bh[2] = {w.x, w.y}, bl[2] = {w.z, w.w};
                    mma16816(acc, a1hi[kt], bh);
                    mma16816(acc, a1hi[kt], bl);
                    mma16816(acc, a1lo[kt], bh);
                }
                int nbase = c * 64 + ntl * 8 + kq;
                float f0 = fmaxf(acc[0] + sb1[nbase],     0.f);
                float f1 = fmaxf(acc[1] + sb1[nbase + 1], 0.f);
                float f2 = fmaxf(acc[2] + sb1[nbase],     0.f);
                float f3 = fmaxf(acc[3] + sb1[nbase + 1], 0.f);
                split2(f0, f1, a2hi[2 * half],     a2lo[2 * half]);
                split2(f2, f3, a2hi[2 * half + 1], a2lo[2 * half + 1]);
            }
            // ---- GEMM2 partial for this 16-k tile ----
            int kt = c * 4 + ktl;
            #pragma unroll
            for (int nt = 0; nt < 8; nt++) {
                uint4 w = g_w2f4[(nt * 32 + kt) * 32 + lane];
                uint32_t bh[2] = {w.x, w.y}, bl[2] = {w.z, w.w};
                mma16816(acc2[nt], a2hi, bh);
                mma16816(acc2[nt], a2hi, bl);
                mma16816(acc2[nt], a2lo, bh);
            }
        }
    }

    float* yb = g_y + b * 8192;
    #pragma unroll
    for (int nt = 0; nt < 8; nt++) {
        int n = nt * 8 + kq;
        *(float2*)&yb[r0 * ROD + n]       = make_float2(acc2[nt][0], acc2[nt][1]);
        *(float2*)&yb[(r0 + 8) * ROD + n] = make_float2(acc2[nt][2], acc2[nt][3]);
    }
}

// ---------------- per-patch layer-2 aggregation + readout ----------------
__global__ void __launch_bounds__(256) k_agg2(const float* __restrict__ b2p) {
    __shared__ float yt[ROD * 65];
    __shared__ float a2[NN * ROD];
    __shared__ float gc[NE], sni[NN];
    __shared__ int   gs[NE], eo[NN + 1];
    int tid = threadIdx.x, p = blockIdx.x;
    for (int i = tid; i < 64 * ROD; i += 256) {
        int r = i >> 6, d = i & 63;
        yt[d * 65 + r] = g_y[p * 4096 + i];
    }
    for (int q = tid; q < NE; q += 256) { gs[q] = g_gsrc[q]; gc[q] = g_gcoefP[p * 256 + q]; }
    for (int i = tid; i <= NN; i += 256) eo[i] = g_poff[i];
    if (tid < NN) sni[tid] = g_pni[p * 64 + tid];
    __syncthreads();
    for (int i = tid; i < NN * ROD; i += 256) {
        int n = i >> 6, d = i & 63;
        float s = 0.f;
        for (int q = eo[n]; q < eo[n + 1]; q++) s += yt[d * 65 + gs[q]] * gc[q];
        a2[i] = fmaxf(sni[n] * s + b2p[d], 0.f);
    }
    __syncthreads();
    if (tid < ROD) {
        float s = 0.f;
        #pragma unroll 10
        for (int n = 0; n < NN; n++) s += a2[n * ROD + tid];
        g_readout[p * ROD + tid] = s * (1.f / NN);
    }
}

// ---------------- mesh stage ----------------
__global__ void k_mcount(const float* __restrict__ mew, const int* __restrict__ med) {
    int e = blockIdx.x * 256 + threadIdx.x;
    if (e < NEM) {
        int s = med[2 * e], d = med[2 * e + 1];
        float w = mew[e];
        atomicAdd(&g_mcnt[d], 1);
        atomicAdd(&g_degi[d], w);
        atomicAdd(&g_dego[s], w);
    }
}

__global__ void k_mscan() {
    __shared__ int sp[256];
    int t = threadIdx.x, base = t * 16;
    int s = 0;
    #pragma unroll
    for (int i = 0; i < 16; i++) s += g_mcnt[base + i];
    sp[t] = s; __syncthreads();
    if (t == 0) { int run = 0; for (int i = 0; i < 256; i++) { int v = sp[i]; sp[i] = run; run += v; } }
    __syncthreads();
    int run = sp[t];
    #pragma unroll
    for (int i = 0; i < 16; i++) {
        int v = g_mcnt[base + i];
        g_moff[base + i] = run; g_mcnt[base + i] = run; run += v;
    }
    if (t == 255) g_moff[NP] = NEM;
}

__global__ void k_norm() {
    int i = blockIdx.x * 256 + threadIdx.x;
    if (i < NP) {
        float a = g_degi[i], b = g_dego[i];
        g_nim[i] = (a > 0.f) ? rsqrtf(a) : 1.f;
        g_nom[i] = (b > 0.f) ? rsqrtf(b) : 1.f;
    }
}

__global__ void k_mscatter(const int* __restrict__ med) {
    int e = blockIdx.x * 256 + threadIdx.x;
    if (e < NEM) {
        int d = med[2 * e + 1];
        int pos = atomicAdd(&g_mcnt[d], 1);
        g_meid[pos] = e;
    }
}

__global__ void k_mprep(const float* __restrict__ mew, const int* __restrict__ med) {
    int q = blockIdx.x * 256 + threadIdx.x;
    if (q < NEM) {
        int e = g_meid[q];
        int s = med[2 * e];
        g_msrc[q] = s;
        g_mcoef[q] = mew[e] * g_nom[s];
    }
}

__global__ void k_mgc1(const float* __restrict__ W1m, const float* __restrict__ b1m) {
    extern __shared__ float smf[];
    float* sW = smf;
    float* sA = smf + ROD * HIDD;
    int tid = threadIdx.x, p0 = blockIdx.x * 16;
    for (int i = tid; i < ROD * HIDD; i += 256) sW[i] = W1m[i];
    for (int i = tid; i < 16 * ROD; i += 256) sA[i] = 0.f;
    __syncthreads();
    int d = tid & 63, qo = tid >> 6;
    for (int r = 0; r < 16; r++) {
        int t = p0 + r;
        int b = g_moff[t], en = g_moff[t + 1];
        float acc = 0.f;
        for (int q = b + qo; q < en; q += 4)
            acc += g_readout[g_msrc[q] * ROD + d] * g_mcoef[q];
        atomicAdd(&sA[r * ROD + d], acc);
    }
    __syncthreads();
    for (int i = tid; i < 16 * ROD; i += 256) sA[i] *= g_nim[p0 + (i >> 6)];
    __syncthreads();
    float acc[16];
    #pragma unroll
    for (int r = 0; r < 16; r++) acc[r] = 0.f;
    #pragma unroll 2
    for (int k = 0; k < ROD; k++) {
        float wv = sW[k * HIDD + tid];
        #pragma unroll
        for (int r = 0; r < 16; r++) acc[r] = fmaf(sA[r * ROD + k], wv, acc[r]);
    }
    float bb = b1m[tid];
    #pragma unroll
    for (int r = 0; r < 16; r++)
        g_h1m[(p0 + r) * HIDD + tid] = fmaxf(acc[r] + bb, 0.f);
}

__global__ void k_mgc2(const float* __restrict__ W2m, const float* __restrict__ b2m,
                       const float* __restrict__ Wu1, const float* __restrict__ bu1) {
    extern __shared__ float smf[];
    float* sA = smf;
    float* sH = smf + 16 * HIDD;
    int tid = threadIdx.x, p0 = blockIdx.x * 16;
    for (int r = 0; r < 16; r++) {
        int t = p0 + r;
        int b = g_moff[t], en = g_moff[t + 1];
        float acc = 0.f;
        for (int q = b; q < en; q++)
            acc += g_h1m[g_msrc[q] * HIDD + tid] * g_mcoef[q];
        sA[r * HIDD + tid] = acc * g_nim[t];
    }
    __syncthreads();
    {
        float acc[16];
        #pragma unroll
        for (int r = 0; r < 16; r++) acc[r] = 0.f;
        #pragma unroll 2
        for (int k = 0; k < HIDD; k++) {
            float wv = __ldg(&W2m[k * HIDD + tid]);
            #pragma unroll
            for (int r = 0; r < 16; r++) acc[r] = fmaf(sA[r * HIDD + k], wv, acc[r]);
        }
        float bb = b2m[tid];
        #pragma unroll
        for (int r = 0; r < 16; r++) sH[r * HIDD + tid] = fmaxf(acc[r] + bb, 0.f);
    }
    __syncthreads();
    {
        int m = tid & 127, grp = tid >> 7;
        float acc[8];
        #pragma unroll
        for (int r = 0; r < 8; r++) acc[r] = 0.f;
        #pragma unroll 2
        for (int k = 0; k < HIDD; k++) {
            float wv = __ldg(&Wu1[k * RHD + m]);
            #pragma unroll
            for (int r = 0; r < 8; r++)
                acc[r] = fmaf(sH[(grp * 8 + r) * HIDD + k], wv, acc[r]);
        }
        float bb = bu1[m];
        float s = 0.f;
        #pragma unroll
        for (int r = 0; r < 8; r++) s += fmaxf(acc[r] + bb, 0.f);
        atomicAdd(&g_r[m], s);
    }
}

__global__ void k_final(const float* __restrict__ Wout, const float* __restrict__ bout,
                        float* __restrict__ out) {
    int o = threadIdx.x;
    if (o < OUTD) {
        float s = bout[o];
        for (int j = 0; j < RHD; j++) s = fmaf(g_r[j], Wout[j * OUTD + o], s);
        out[o] = s;
    }
}

// ---------------- launch ----------------
extern "C" void kernel_launch(void* const* d_in, const int* in_sizes, int n_in,
                              void* d_out, int out_size) {
    const float* feats = (const float*)d_in[0];
    const float* pew   = (const float*)d_in[1];
    const float* mew   = (const float*)d_in[2];
    const float* W1p   = (const float*)d_in[3];
    const float* b1p   = (const float*)d_in[4];
    const float* W2p   = (const float*)d_in[5];
    const float* b2p   = (const float*)d_in[6];
    const float* W1m   = (const float*)d_in[7];
    const float* b1m   = (const float*)d_in[8];
    const float* W2m   = (const float*)d_in[9];
    const float* b2m   = (const float*)d_in[10];
    const float* Wu1   = (const float*)d_in[11];
    const float* bu1   = (const float*)d_in[12];
    const float* Wout  = (const float*)d_in[13];
    const float* bout  = (const float*)d_in[14];
    const int*   pedg  = (const int*)d_in[15];
    const int*   medg  = (const int*)d_in[16];

    cudaFuncSetAttribute(k_mgc1, cudaFuncAttributeMaxDynamicSharedMemorySize, 69632);

    k_csr<<<1, 256>>>(pedg);
    k_wprep<<<48, 256>>>(W1p, W2p);
    k_agg1<<<NP, 256>>>(feats, pew, pedg);
    k_mlp<<<NP / 2, 256>>>(b1p);                 // ncu capture slot (#4)
    k_agg2<<<NP, 256>>>(b2p);
    k_zero0<<<16, 256>>>();
    k_mcount<<<NEM / 256, 256>>>(mew, medg);
    k_mscan<<<1, 256>>>();
    k_norm<<<NP / 256, 256>>>();
    k_mscatter<<<NEM / 256, 256>>>(medg);
    k_mprep<<<NEM / 256, 256>>>(mew, medg);
    k_mgc1<<<NP / 16, 256, 69632>>>(W1m, b1m);
    k_mgc2<<<NP / 16, 256, 32768>>>(W2m, b2m, Wu1, bu1);
    k_final<<<1, 32>>>(Wout, bout, (float*)d_out);
}

// round 10
// speedup vs baseline: 1.8400x; 1.1276x over previous
#include <cuda_runtime.h>
#include <cuda_bf16.h>
#include <cstdint>

#define NP   4096
#define NN   50
#define NE   250
#define NEM  65536
#define IND  32
#define PHD  512
#define ROD  64
#define HIDD 256
#define RHD  128
#define OUTD 15

// ---------------- persistent device scratch ----------------
__device__ float g_readout[NP * ROD];
__device__ float g_degi[NP], g_dego[NP], g_nim[NP], g_nom[NP];
__device__ float g_h1m[NP * HIDD];
__device__ float g_r[RHD];
__device__ int   g_poff[NN + 1];
__device__ int   g_peid[NE];
__device__ int   g_gsrc[NE];
__device__ int   g_mcnt[NP];
__device__ int   g_moff[NP + 1];
__device__ int   g_msrc[NEM];
__device__ float g_mcoef[NEM];
// patch-MLP staging
__device__ float g_agg[NP * 64 * IND];
__device__ float g_y[NP * 64 * ROD];
__device__ float g_gcoefP[NP * 256];
__device__ float g_pni[NP * 64];
// fragment-packed weights, uint4 = {hi_reg0, hi_reg1, lo_reg0, lo_reg1}
__device__ uint4 g_w1f4[64 * 2 * 32];     // W1: [nt][kt][lane]
__device__ uint4 g_w2f4[8 * 32 * 32];     // W2: [nt][kt][lane]

// ---------------- helpers ----------------
__device__ __forceinline__ uint32_t pkbf(__nv_bfloat16 a, __nv_bfloat16 b) {
    unsigned short ua = *(unsigned short*)&a, ub = *(unsigned short*)&b;
    return ((uint32_t)ub << 16) | (uint32_t)ua;
}
__device__ __forceinline__ void split2(float x0, float x1, uint32_t& hi, uint32_t& lo) {
    __nv_bfloat16 h0 = __float2bfloat16(x0), h1 = __float2bfloat16(x1);
    __nv_bfloat16 l0 = __float2bfloat16(x0 - __bfloat162float(h0));
    __nv_bfloat16 l1 = __float2bfloat16(x1 - __bfloat162float(h1));
    hi = pkbf(h0, h1); lo = pkbf(l0, l1);
}
// one-instruction pack: {hi16=bf16(xhi), lo16=bf16(xlo)}
__device__ __forceinline__ uint32_t cvt2(float xlo, float xhi) {
    uint32_t r;
    asm("cvt.rn.bf16x2.f32 %0, %1, %2;" : "=r"(r) : "f"(xhi), "f"(xlo));
    return r;
}
__device__ __forceinline__ void mma16816(float* c, const uint32_t* a, const uint32_t* b) {
    asm volatile("mma.sync.aligned.m16n8k16.row.col.f32.bf16.bf16.f32 "
        "{%0,%1,%2,%3}, {%4,%5,%6,%7}, {%8,%9}, {%0,%1,%2,%3};"
        : "+f"(c[0]), "+f"(c[1]), "+f"(c[2]), "+f"(c[3])
        : "r"(a[0]), "r"(a[1]), "r"(a[2]), "r"(a[3]), "r"(b[0]), "r"(b[1]));
}

// ---------------- setup kernels ----------------
// parallel deterministic CSR (order within dst preserved -> bit-identical sums)
__global__ void k_csr(const int* __restrict__ pedges) {
    __shared__ int sdst[NE], ssrc[NE], cnt[NN], off[NN + 1];
    int tid = threadIdx.x;
    for (int e = tid; e < NE; e += 256) {
        ssrc[e] = pedges[2 * e];
        sdst[e] = pedges[2 * e + 1];
    }
    if (tid < NN) cnt[tid] = 0;
    __syncthreads();
    for (int e = tid; e < NE; e += 256) atomicAdd(&cnt[sdst[e]], 1);
    __syncthreads();
    if (tid == 0) {
        int run = 0;
        for (int n = 0; n < NN; n++) { off[n] = run; run += cnt[n]; }
        off[NN] = run;
    }
    __syncthreads();
    if (tid <= NN) g_poff[tid] = off[tid];
    if (tid < NE) {
        int d = sdst[tid], rank = 0;
        for (int e2 = 0; e2 < tid; e2++) rank += (sdst[e2] == d);
        int pos = off[d] + rank;
        g_peid[pos] = tid;
        g_gsrc[pos] = ssrc[tid];
    }
}

// weight fragment packing + zeroing of mesh scratch (merged)
__global__ void k_wprep(const float* __restrict__ W1p, const float* __restrict__ W2p) {
    int i = blockIdx.x * 256 + threadIdx.x;    // grid 64 -> 16384
    if (i < 4096) {                            // W1 frags
        int lane = i & 31, kt = (i >> 5) & 1, nt = i >> 6;
        int n = nt * 8 + (lane >> 2);
        int k0 = kt * 16 + (lane & 3) * 2;
        uint32_t h0, l0, h1, l1;
        split2(W1p[k0 * PHD + n],       W1p[(k0 + 1) * PHD + n], h0, l0);
        split2(W1p[(k0 + 8) * PHD + n], W1p[(k0 + 9) * PHD + n], h1, l1);
        g_w1f4[i] = make_uint4(h0, h1, l0, l1);
    } else if (i < 4096 + 8192) {              // W2 frags
        int j = i - 4096;
        int lane = j & 31, kt = (j >> 5) & 31, nt = j >> 10;
        int n = nt * 8 + (lane >> 2);
        int k0 = kt * 16 + (lane & 3) * 2;
        uint32_t h0, l0, h1, l1;
        split2(W2p[k0 * ROD + n],       W2p[(k0 + 1) * ROD + n], h0, l0);
        split2(W2p[(k0 + 8) * ROD + n], W2p[(k0 + 9) * ROD + n], h1, l1);
        g_w2f4[j] = make_uint4(h0, h1, l0, l1);
    }
    if (i < NP) { g_mcnt[i] = 0; g_degi[i] = 0.f; g_dego[i] = 0.f; }
    if (i < RHD) g_r[i] = 0.f;
}

// ---------------- per-patch layer-1 aggregation ----------------
__global__ void __launch_bounds__(256) k_agg1(const float* __restrict__ feats,
                                              const float* __restrict__ pew,
                                              const int* __restrict__ pedges) {
    __shared__ int   ssrc[NE], sdst[NE], eoff[NN + 1], sgs[NE];
    __shared__ float coef[NE], gc[NE], ni[NN], no_[NN], x[NN * IND];
    int tid = threadIdx.x, p = blockIdx.x;
    for (int i = tid; i < NE; i += 256) {
        ssrc[i] = pedges[2 * i]; sdst[i] = pedges[2 * i + 1];
        coef[i] = pew[p * NE + i]; sgs[i] = g_gsrc[i];
    }
    for (int i = tid; i <= NN; i += 256) eoff[i] = g_poff[i];
    for (int i = tid; i < NN; i += 256) { ni[i] = 0.f; no_[i] = 0.f; }
    for (int i = tid; i < NN * IND; i += 256) x[i] = feats[p * NN * IND + i];
    __syncthreads();
    for (int i = tid; i < NE; i += 256) {
        float w = coef[i];
        atomicAdd(&ni[sdst[i]], w);
        atomicAdd(&no_[ssrc[i]], w);
    }
    __syncthreads();
    if (tid < NN) {
        float a = ni[tid], b = no_[tid];
        ni[tid]  = (a > 0.f) ? rsqrtf(a) : 1.f;
        no_[tid] = (b > 0.f) ? rsqrtf(b) : 1.f;
    }
    __syncthreads();
    for (int q = tid; q < NE; q += 256) {
        int e = g_peid[q];
        gc[q] = coef[e] * no_[ssrc[e]];
    }
    __syncthreads();
    for (int i = tid; i < 64 * IND; i += 256) {
        int n = i >> 5, d = i & 31;
        float s = 0.f;
        if (n < NN) {
            int b0 = eoff[n], e0 = eoff[n + 1];
            for (int q = b0; q < e0; q++) s += x[sgs[q] * IND + d] * gc[q];
            s *= ni[n];
        }
        g_agg[p * 2048 + i] = s;
    }
    for (int q = tid; q < NE; q += 256) g_gcoefP[p * 256 + q] = gc[q];
    if (tid < NN) g_pni[p * 64 + tid] = ni[tid];
}

// ---------------- fused MLP on tensor cores (mma.sync, 2 patches/CTA) ----------------
// A-operands hi-only (bf16 activations), B split hi+lo (fp32-equivalent weights).
__global__ void __launch_bounds__(256, 3) k_mlp(const float* __restrict__ b1p) {
    __shared__ float sagg[128 * IND];
    __shared__ float sb1[PHD];
    const int tid = threadIdx.x, lane = tid & 31, wid = tid >> 5;
    const int b = blockIdx.x;
    const int m0 = wid * 16;
    const int r0 = m0 + (lane >> 2);
    const int kq = (lane & 3) * 2;

    for (int i = tid; i < 128 * IND; i += 256) sagg[i] = g_agg[b * 4096 + i];
    for (int i = tid; i < PHD; i += 256) sb1[i] = b1p[i];
    __syncthreads();

    // A1 fragments, hi only
    uint32_t a1[2][4];
    #pragma unroll
    for (int kt = 0; kt < 2; kt++) {
        #pragma unroll
        for (int j = 0; j < 4; j++) {
            int dr = (j & 1) * 8, dk = (j >> 1) * 8;
            int rr = r0 + dr, kk = kt * 16 + kq + dk;
            a1[kt][j] = cvt2(sagg[rr * IND + kk], sagg[rr * IND + kk + 1]);
        }
    }

    float acc2[8][4];
    #pragma unroll
    for (int nt = 0; nt < 8; nt++)
        #pragma unroll
        for (int j = 0; j < 4; j++) acc2[nt][j] = 0.f;

    for (int c = 0; c < 8; c++) {
        #pragma unroll
        for (int ktl = 0; ktl < 4; ktl++) {
            // ---- GEMM1: two 8-col groups -> one a2 fragment (hi only) ----
            uint32_t a2[4];
            #pragma unroll
            for (int half = 0; half < 2; half++) {
                int ntl = 2 * ktl + half;
                int nt = c * 8 + ntl;
                float acc[4] = {0.f, 0.f, 0.f, 0.f};
                #pragma unroll
                for (int kt = 0; kt < 2; kt++) {
                    uint4 w = g_w1f4[(nt * 2 + kt) * 32 + lane];
                    uint32_t bh[2] = {w.x, w.y}, bl[2] = {w.z, w.w};
                    mma16816(acc, a1[kt], bh);   // Ahi * Bhi
                    mma16816(acc, a1[kt], bl);   // Ahi * Blo
                }
                int nbase = c * 64 + ntl * 8 + kq;
                float f0 = fmaxf(acc[0] + sb1[nbase],     0.f);
                float f1 = fmaxf(acc[1] + sb1[nbase + 1], 0.f);
                float f2 = fmaxf(acc[2] + sb1[nbase],     0.f);
                float f3 = fmaxf(acc[3] + sb1[nbase + 1], 0.f);
                a2[2 * half]     = cvt2(f0, f1);
                a2[2 * half + 1] = cvt2(f2, f3);
            }
            // ---- GEMM2 partial for this 16-k tile ----
            int kt = c * 4 + ktl;
            #pragma unroll
            for (int nt = 0; nt < 8; nt++) {
                uint4 w = g_w2f4[(nt * 32 + kt) * 32 + lane];
                uint32_t bh[2] = {w.x, w.y}, bl[2] = {w.z, w.w};
                mma16816(acc2[nt], a2, bh);
                mma16816(acc2[nt], a2, bl);
            }
        }
    }

    float* yb = g_y + b * 8192;
    #pragma unroll
    for (int nt = 0; nt < 8; nt++) {
        int n = nt * 8 + kq;
        *(float2*)&yb[r0 * ROD + n]       = make_float2(acc2[nt][0], acc2[nt][1]);
        *(float2*)&yb[(r0 + 8) * ROD + n] = make_float2(acc2[nt][2], acc2[nt][3]);
    }
}

// ---------------- per-patch layer-2 aggregation + readout ----------------
__global__ void __launch_bounds__(256) k_agg2(const float* __restrict__ b2p) {
    __shared__ float yt[ROD * 65];
    __shared__ float a2[NN * ROD];
    __shared__ float gc[NE], sni[NN];
    __shared__ int   gs[NE], eo[NN + 1];
    int tid = threadIdx.x, p = blockIdx.x;
    for (int i = tid; i < 64 * ROD; i += 256) {
        int r = i >> 6, d = i & 63;
        yt[d * 65 + r] = g_y[p * 4096 + i];
    }
    for (int q = tid; q < NE; q += 256) { gs[q] = g_gsrc[q]; gc[q] = g_gcoefP[p * 256 + q]; }
    for (int i = tid; i <= NN; i += 256) eo[i] = g_poff[i];
    if (tid < NN) sni[tid] = g_pni[p * 64 + tid];
    __syncthreads();
    for (int i = tid; i < NN * ROD; i += 256) {
        int n = i >> 6, d = i & 63;
        float s = 0.f;
        for (int q = eo[n]; q < eo[n + 1]; q++) s += yt[d * 65 + gs[q]] * gc[q];
        a2[i] = fmaxf(sni[n] * s + b2p[d], 0.f);
    }
    __syncthreads();
    if (tid < ROD) {
        float s = 0.f;
        #pragma unroll 10
        for (int n = 0; n < NN; n++) s += a2[n * ROD + tid];
        g_readout[p * ROD + tid] = s * (1.f / NN);
    }
}

// ---------------- mesh stage ----------------
__global__ void k_mcount(const float* __restrict__ mew, const int* __restrict__ med) {
    int e = blockIdx.x * 256 + threadIdx.x;
    if (e < NEM) {
        int s = med[2 * e], d = med[2 * e + 1];
        float w = mew[e];
        atomicAdd(&g_mcnt[d], 1);
        atomicAdd(&g_degi[d], w);
        atomicAdd(&g_dego[s], w);
    }
}

// scan of g_mcnt + degree normalization (merged), 1 block x 256
__global__ void k_scan_norm() {
    __shared__ int sp[256];
    int t = threadIdx.x, base = t * 16;
    int s = 0;
    #pragma unroll
    for (int i = 0; i < 16; i++) s += g_mcnt[base + i];
    sp[t] = s; __syncthreads();
    if (t == 0) { int run = 0; for (int i = 0; i < 256; i++) { int v = sp[i]; sp[i] = run; run += v; } }
    __syncthreads();
    int run = sp[t];
    #pragma unroll
    for (int i = 0; i < 16; i++) {
        int v = g_mcnt[base + i];
        g_moff[base + i] = run; g_mcnt[base + i] = run; run += v;
    }
    if (t == 255) g_moff[NP] = NEM;
    #pragma unroll
    for (int i = 0; i < 16; i++) {
        int idx = base + i;
        float a = g_degi[idx], b = g_dego[idx];
        g_nim[idx] = (a > 0.f) ? rsqrtf(a) : 1.f;
        g_nom[idx] = (b > 0.f) ? rsqrtf(b) : 1.f;
    }
}

// scatter + coef prep (merged)
__global__ void k_mscatter_prep(const float* __restrict__ mew, const int* __restrict__ med) {
    int e = blockIdx.x * 256 + threadIdx.x;
    if (e < NEM) {
        int s = med[2 * e], d = med[2 * e + 1];
        int pos = atomicAdd(&g_mcnt[d], 1);
        g_msrc[pos]  = s;
        g_mcoef[pos] = mew[e] * g_nom[s];
    }
}

__global__ void k_mgc1(const float* __restrict__ W1m, const float* __restrict__ b1m) {
    extern __shared__ float smf[];
    float* sW = smf;
    float* sA = smf + ROD * HIDD;
    int tid = threadIdx.x, p0 = blockIdx.x * 16;
    for (int i = tid; i < ROD * HIDD; i += 256) sW[i] = W1m[i];
    for (int i = tid; i < 16 * ROD; i += 256) sA[i] = 0.f;
    __syncthreads();
    int d = tid & 63, qo = tid >> 6;
    for (int r = 0; r < 16; r++) {
        int t = p0 + r;
        int b = g_moff[t], en = g_moff[t + 1];
        float acc = 0.f;
        for (int q = b + qo; q < en; q += 4)
            acc += g_readout[g_msrc[q] * ROD + d] * g_mcoef[q];
        atomicAdd(&sA[r * ROD + d], acc);
    }
    __syncthreads();
    for (int i = tid; i < 16 * ROD; i += 256) sA[i] *= g_nim[p0 + (i >> 6)];
    __syncthreads();
    float acc[16];
    #pragma unroll
    for (int r = 0; r < 16; r++) acc[r] = 0.f;
    #pragma unroll 2
    for (int k = 0; k < ROD; k++) {
        float wv = sW[k * HIDD + tid];
        #pragma unroll
        for (int r = 0; r < 16; r++) acc[r] = fmaf(sA[r * ROD + k], wv, acc[r]);
    }
    float bb = b1m[tid];
    #pragma unroll
    for (int r = 0; r < 16; r++)
        g_h1m[(p0 + r) * HIDD + tid] = fmaxf(acc[r] + bb, 0.f);
}

__global__ void k_mgc2(const float* __restrict__ W2m, const float* __restrict__ b2m,
                       const float* __restrict__ Wu1, const float* __restrict__ bu1) {
    extern __shared__ float smf[];
    float* sA = smf;
    float* sH = smf + 16 * HIDD;
    int tid = threadIdx.x, p0 = blockIdx.x * 16;
    for (int r = 0; r < 16; r++) {
        int t = p0 + r;
        int b = g_moff[t], en = g_moff[t + 1];
        float acc = 0.f;
        for (int q = b; q < en; q++)
            acc += g_h1m[g_msrc[q] * HIDD + tid] * g_mcoef[q];
        sA[r * HIDD + tid] = acc * g_nim[t];
    }
    __syncthreads();
    {
        float acc[16];
        #pragma unroll
        for (int r = 0; r < 16; r++) acc[r] = 0.f;
        #pragma unroll 2
        for (int k = 0; k < HIDD; k++) {
            float wv = __ldg(&W2m[k * HIDD + tid]);
            #pragma unroll
            for (int r = 0; r < 16; r++) acc[r] = fmaf(sA[r * HIDD + k], wv, acc[r]);
        }
        float bb = b2m[tid];
        #pragma unroll
        for (int r = 0; r < 16; r++) sH[r * HIDD + tid] = fmaxf(acc[r] + bb, 0.f);
    }
    __syncthreads();
    {
        int m = tid & 127, grp = tid >> 7;
        float acc[8];
        #pragma unroll
        for (int r = 0; r < 8; r++) acc[r] = 0.f;
        #pragma unroll 2
        for (int k = 0; k < HIDD; k++) {
            float wv = __ldg(&Wu1[k * RHD + m]);
            #pragma unroll
            for (int r = 0; r < 8; r++)
                acc[r] = fmaf(sH[(grp * 8 + r) * HIDD + k], wv, acc[r]);
        }
        float bb = bu1[m];
        float s = 0.f;
        #pragma unroll
        for (int r = 0; r < 8; r++) s += fmaxf(acc[r] + bb, 0.f);
        atomicAdd(&g_r[m], s);
    }
}

__global__ void k_final(const float* __restrict__ Wout, const float* __restrict__ bout,
                        float* __restrict__ out) {
    int o = threadIdx.x;
    if (o < OUTD) {
        float s = bout[o];
        for (int j = 0; j < RHD; j++) s = fmaf(g_r[j], Wout[j * OUTD + o], s);
        out[o] = s;
    }
}

// ---------------- launch ----------------
extern "C" void kernel_launch(void* const* d_in, const int* in_sizes, int n_in,
                              void* d_out, int out_size) {
    const float* feats = (const float*)d_in[0];
    const float* pew   = (const float*)d_in[1];
    const float* mew   = (const float*)d_in[2];
    const float* W1p   = (const float*)d_in[3];
    const float* b1p   = (const float*)d_in[4];
    const float* W2p   = (const float*)d_in[5];
    const float* b2p   = (const float*)d_in[6];
    const float* W1m   = (const float*)d_in[7];
    const float* b1m   = (const float*)d_in[8];
    const float* W2m   = (const float*)d_in[9];
    const float* b2m   = (const float*)d_in[10];
    const float* Wu1   = (const float*)d_in[11];
    const float* bu1   = (const float*)d_in[12];
    const float* Wout  = (const float*)d_in[13];
    const float* bout  = (const float*)d_in[14];
    const int*   pedg  = (const int*)d_in[15];
    const int*   medg  = (const int*)d_in[16];

    cudaFuncSetAttribute(k_mgc1, cudaFuncAttributeMaxDynamicSharedMemorySize, 69632);

    k_csr<<<1, 256>>>(pedg);
    k_wprep<<<64, 256>>>(W1p, W2p);
    k_agg1<<<NP, 256>>>(feats, pew, pedg);
    k_mlp<<<NP / 2, 256>>>(b1p);                 // ncu capture slot (#4)
    k_agg2<<<NP, 256>>>(b2p);
    k_mcount<<<NEM / 256, 256>>>(mew, medg);
    k_scan_norm<<<1, 256>>>();
    k_mscatter_prep<<<NEM / 256, 256>>>(mew, medg);
    k_mgc1<<<NP / 16, 256, 69632>>>(W1m, b1m);
    k_mgc2<<<NP / 16, 256, 32768>>>(W2m, b2m, Wu1, bu1);
    k_final<<<1, 32>>>(Wout, bout, (float*)d_out);
}

// round 11
// speedup vs baseline: 1.9906x; 1.0819x over previous
#include <cuda_runtime.h>
#include <cuda_bf16.h>
#include <cstdint>

#define NP   4096
#define NN   50
#define NE   250
#define NEM  65536
#define IND  32
#define PHD  512
#define ROD  64
#define HIDD 256
#define RHD  128
#define OUTD 15

// ---------------- persistent device scratch ----------------
__device__ float g_readout[NP * ROD];
__device__ float g_degi[NP], g_dego[NP], g_nim[NP], g_nom[NP];
__device__ float g_h1m[NP * HIDD];
__device__ float g_r[RHD];
__device__ int   g_poff[NN + 1];
__device__ int   g_peid[NE];
__device__ int   g_gsrc[NE];
__device__ int   g_mcnt[NP];
__device__ int   g_moff[NP + 1];
__device__ int   g_msrc[NEM];
__device__ float g_mcoef[NEM];
// patch-MLP staging
__device__ float g_agg[NP * 64 * IND];
__device__ float g_gcoefP[NP * 256];
__device__ float g_pni[NP * 64];
// fragment-packed weights, uint4 = {hi_reg0, hi_reg1, lo_reg0, lo_reg1}
__device__ uint4 g_w1f4[64 * 2 * 32];     // W1: [nt][kt][lane]
__device__ uint4 g_w2f4[8 * 32 * 32];     // W2: [nt][kt][lane]

// ---------------- helpers ----------------
__device__ __forceinline__ uint32_t pkbf(__nv_bfloat16 a, __nv_bfloat16 b) {
    unsigned short ua = *(unsigned short*)&a, ub = *(unsigned short*)&b;
    return ((uint32_t)ub << 16) | (uint32_t)ua;
}
__device__ __forceinline__ void split2(float x0, float x1, uint32_t& hi, uint32_t& lo) {
    __nv_bfloat16 h0 = __float2bfloat16(x0), h1 = __float2bfloat16(x1);
    __nv_bfloat16 l0 = __float2bfloat16(x0 - __bfloat162float(h0));
    __nv_bfloat16 l1 = __float2bfloat16(x1 - __bfloat162float(h1));
    hi = pkbf(h0, h1); lo = pkbf(l0, l1);
}
__device__ __forceinline__ uint32_t cvt2(float xlo, float xhi) {
    uint32_t r;
    asm("cvt.rn.bf16x2.f32 %0, %1, %2;" : "=r"(r) : "f"(xhi), "f"(xlo));
    return r;
}
__device__ __forceinline__ void mma16816(float* c, const uint32_t* a, const uint32_t* b) {
    asm volatile("mma.sync.aligned.m16n8k16.row.col.f32.bf16.bf16.f32 "
        "{%0,%1,%2,%3}, {%4,%5,%6,%7}, {%8,%9}, {%0,%1,%2,%3};"
        : "+f"(c[0]), "+f"(c[1]), "+f"(c[2]), "+f"(c[3])
        : "r"(a[0]), "r"(a[1]), "r"(a[2]), "r"(a[3]), "r"(b[0]), "r"(b[1]));
}

// ---------------- setup kernels ----------------
__global__ void k_csr(const int* __restrict__ pedges) {
    __shared__ int sdst[NE], ssrc[NE], cnt[NN], off[NN + 1];
    int tid = threadIdx.x;
    for (int e = tid; e < NE; e += 256) {
        ssrc[e] = pedges[2 * e];
        sdst[e] = pedges[2 * e + 1];
    }
    if (tid < NN) cnt[tid] = 0;
    __syncthreads();
    for (int e = tid; e < NE; e += 256) atomicAdd(&cnt[sdst[e]], 1);
    __syncthreads();
    if (tid == 0) {
        int run = 0;
        for (int n = 0; n < NN; n++) { off[n] = run; run += cnt[n]; }
        off[NN] = run;
    }
    __syncthreads();
    if (tid <= NN) g_poff[tid] = off[tid];
    if (tid < NE) {
        int d = sdst[tid], rank = 0;
        for (int e2 = 0; e2 < tid; e2++) rank += (sdst[e2] == d);
        int pos = off[d] + rank;
        g_peid[pos] = tid;
        g_gsrc[pos] = ssrc[tid];
    }
}

__global__ void k_wprep(const float* __restrict__ W1p, const float* __restrict__ W2p) {
    int i = blockIdx.x * 256 + threadIdx.x;    // grid 64 -> 16384
    if (i < 4096) {
        int lane = i & 31, kt = (i >> 5) & 1, nt = i >> 6;
        int n = nt * 8 + (lane >> 2);
        int k0 = kt * 16 + (lane & 3) * 2;
        uint32_t h0, l0, h1, l1;
        split2(W1p[k0 * PHD + n],       W1p[(k0 + 1) * PHD + n], h0, l0);
        split2(W1p[(k0 + 8) * PHD + n], W1p[(k0 + 9) * PHD + n], h1, l1);
        g_w1f4[i] = make_uint4(h0, h1, l0, l1);
    } else if (i < 4096 + 8192) {
        int j = i - 4096;
        int lane = j & 31, kt = (j >> 5) & 31, nt = j >> 10;
        int n = nt * 8 + (lane >> 2);
        int k0 = kt * 16 + (lane & 3) * 2;
        uint32_t h0, l0, h1, l1;
        split2(W2p[k0 * ROD + n],       W2p[(k0 + 1) * ROD + n], h0, l0);
        split2(W2p[(k0 + 8) * ROD + n], W2p[(k0 + 9) * ROD + n], h1, l1);
        g_w2f4[j] = make_uint4(h0, h1, l0, l1);
    }
    if (i < NP) { g_mcnt[i] = 0; g_degi[i] = 0.f; g_dego[i] = 0.f; }
    if (i < RHD) g_r[i] = 0.f;
}

// ---------------- per-patch layer-1 aggregation ----------------
__global__ void __launch_bounds__(256) k_agg1(const float* __restrict__ feats,
                                              const float* __restrict__ pew,
                                              const int* __restrict__ pedges) {
    __shared__ int   ssrc[NE], sdst[NE], eoff[NN + 1], sgs[NE];
    __shared__ float coef[NE], gc[NE], ni[NN], no_[NN], x[NN * IND];
    int tid = threadIdx.x, p = blockIdx.x;
    for (int i = tid; i < NE; i += 256) {
        ssrc[i] = pedges[2 * i]; sdst[i] = pedges[2 * i + 1];
        coef[i] = pew[p * NE + i]; sgs[i] = g_gsrc[i];
    }
    for (int i = tid; i <= NN; i += 256) eoff[i] = g_poff[i];
    for (int i = tid; i < NN; i += 256) { ni[i] = 0.f; no_[i] = 0.f; }
    for (int i = tid; i < NN * IND; i += 256) x[i] = feats[p * NN * IND + i];
    __syncthreads();
    for (int i = tid; i < NE; i += 256) {
        float w = coef[i];
        atomicAdd(&ni[sdst[i]], w);
        atomicAdd(&no_[ssrc[i]], w);
    }
    __syncthreads();
    if (tid < NN) {
        float a = ni[tid], b = no_[tid];
        ni[tid]  = (a > 0.f) ? rsqrtf(a) : 1.f;
        no_[tid] = (b > 0.f) ? rsqrtf(b) : 1.f;
    }
    __syncthreads();
    for (int q = tid; q < NE; q += 256) {
        int e = g_peid[q];
        gc[q] = coef[e] * no_[ssrc[e]];
    }
    __syncthreads();
    for (int i = tid; i < 64 * IND; i += 256) {
        int n = i >> 5, d = i & 31;
        float s = 0.f;
        if (n < NN) {
            int b0 = eoff[n], e0 = eoff[n + 1];
            for (int q = b0; q < e0; q++) s += x[sgs[q] * IND + d] * gc[q];
            s *= ni[n];
        }
        g_agg[p * 2048 + i] = s;
    }
    for (int q = tid; q < NE; q += 256) g_gcoefP[p * 256 + q] = gc[q];
    if (tid < NN) g_pni[p * 64 + tid] = ni[tid];
}

// ---------------- fused MLP + layer-2 aggregation + readout (2 patches/CTA) ----------------
struct MLPShared {
    float sb1[PHD];                 // 2048 B; reused as partial buffer at the end
    int   gs[NE];                   // 1000
    int   eo[NN + 2];               // 208
    float gc[2][256];               // 2048
    float sni[2][ROD];              // 512
    union {
        float sagg[128 * IND];      // 16384
        float yt[2][ROD][66];       // 33792  [patch][col][node]
    } u;
};

__global__ void __launch_bounds__(256, 3) k_mlp(const float* __restrict__ b1p,
                                                const float* __restrict__ b2p) {
    __shared__ MLPShared S;
    const int tid = threadIdx.x, lane = tid & 31, wid = tid >> 5;
    const int b = blockIdx.x;
    const int m0 = wid * 16;
    const int r0 = m0 + (lane >> 2);
    const int kq = (lane & 3) * 2;

    for (int i = tid; i < 128 * IND; i += 256) S.u.sagg[i] = g_agg[b * 4096 + i];
    for (int i = tid; i < PHD; i += 256) S.sb1[i] = b1p[i];
    for (int q = tid; q < NE; q += 256) {
        S.gs[q] = g_gsrc[q];
        S.gc[0][q] = g_gcoefP[(2 * b) * 256 + q];
        S.gc[1][q] = g_gcoefP[(2 * b + 1) * 256 + q];
    }
    for (int i = tid; i <= NN; i += 256) S.eo[i] = g_poff[i];
    if (tid < NN) {
        S.sni[0][tid] = g_pni[(2 * b) * 64 + tid];
        S.sni[1][tid] = g_pni[(2 * b + 1) * 64 + tid];
    }
    __syncthreads();

    // A1 fragments, hi only
    uint32_t a1[2][4];
    #pragma unroll
    for (int kt = 0; kt < 2; kt++) {
        #pragma unroll
        for (int j = 0; j < 4; j++) {
            int dr = (j & 1) * 8, dk = (j >> 1) * 8;
            int rr = r0 + dr, kk = kt * 16 + kq + dk;
            a1[kt][j] = cvt2(S.u.sagg[rr * IND + kk], S.u.sagg[rr * IND + kk + 1]);
        }
    }
    __syncthreads();   // all sagg reads complete before yt overwrites the union

    float acc2[8][4];
    #pragma unroll
    for (int nt = 0; nt < 8; nt++)
        #pragma unroll
        for (int j = 0; j < 4; j++) acc2[nt][j] = 0.f;

    for (int c = 0; c < 8; c++) {
        #pragma unroll
        for (int ktl = 0; ktl < 4; ktl++) {
            uint32_t a2[4];
            #pragma unroll
            for (int half = 0; half < 2; half++) {
                int ntl = 2 * ktl + half;
                int nt = c * 8 + ntl;
                float acc[4] = {0.f, 0.f, 0.f, 0.f};
                #pragma unroll
                for (int kt = 0; kt < 2; kt++) {
                    uint4 w = g_w1f4[(nt * 2 + kt) * 32 + lane];
                    uint32_t bh[2] = {w.x, w.y}, bl[2] = {w.z, w.w};
                    mma16816(acc, a1[kt], bh);
                    mma16816(acc, a1[kt], bl);
                }
                int nbase = c * 64 + ntl * 8 + kq;
                float f0 = fmaxf(acc[0] + S.sb1[nbase],     0.f);
                float f1 = fmaxf(acc[1] + S.sb1[nbase + 1], 0.f);
                float f2 = fmaxf(acc[2] + S.sb1[nbase],     0.f);
                float f3 = fmaxf(acc[3] + S.sb1[nbase + 1], 0.f);
                a2[2 * half]     = cvt2(f0, f1);
                a2[2 * half + 1] = cvt2(f2, f3);
            }
            int kt = c * 4 + ktl;
            #pragma unroll
            for (int nt = 0; nt < 8; nt++) {
                uint4 w = g_w2f4[(nt * 32 + kt) * 32 + lane];
                uint32_t bh[2] = {w.x, w.y}, bl[2] = {w.z, w.w};
                mma16816(acc2[nt], a2, bh);
                mma16816(acc2[nt], a2, bl);
            }
        }
    }

    // write y into transposed smem [patch][col][node]
    {
        int p1 = r0 >> 6, i1 = r0 & 63;
        int r2 = r0 + 8;
        int p2 = r2 >> 6, i2 = r2 & 63;
        #pragma unroll
        for (int nt = 0; nt < 8; nt++) {
            int n = nt * 8 + kq;
            S.u.yt[p1][n][i1]     = acc2[nt][0];
            S.u.yt[p1][n + 1][i1] = acc2[nt][1];
            S.u.yt[p2][n][i2]     = acc2[nt][2];
            S.u.yt[p2][n + 1][i2] = acc2[nt][3];
        }
    }
    __syncthreads();

    // layer-2 aggregation + bias + relu + partial node-sum
    // thread map: pl = tid>>7, d = tid&63, g = (tid>>6)&1 (node groups of 25)
    {
        int pl = tid >> 7, rest = tid & 127;
        int d = rest & 63, g = rest >> 6;
        float bb = b2p[d];
        float part = 0.f;
        for (int n = g * 25; n < g * 25 + 25; n++) {
            int b0 = S.eo[n], e0 = S.eo[n + 1];
            float s = 0.f;
            for (int q = b0; q < e0; q++)
                s += S.u.yt[pl][d][S.gs[q]] * S.gc[pl][q];
            part += fmaxf(S.sni[pl][n] * s + bb, 0.f);
        }
        S.sb1[tid] = part;    // sb1 reused as partial buffer
    }
    __syncthreads();
    if (tid < 128) {
        int pl = tid >> 6, d = tid & 63;
        float s = S.sb1[pl * 128 + d] + S.sb1[pl * 128 + 64 + d];
        g_readout[(2 * b + pl) * ROD + d] = s * (1.f / NN);
    }
}

// ---------------- mesh stage ----------------
__global__ void k_mcount(const float* __restrict__ mew, const int* __restrict__ med) {
    int e = blockIdx.x * 256 + threadIdx.x;
    if (e < NEM) {
        int s = med[2 * e], d = med[2 * e + 1];
        float w = mew[e];
        atomicAdd(&g_mcnt[d], 1);
        atomicAdd(&g_degi[d], w);
        atomicAdd(&g_dego[s], w);
    }
}

__global__ void k_scan_norm() {
    __shared__ int sp[256];
    int t = threadIdx.x, base = t * 16;
    int s = 0;
    #pragma unroll
    for (int i = 0; i < 16; i++) s += g_mcnt[base + i];
    sp[t] = s; __syncthreads();
    if (t == 0) { int run = 0; for (int i = 0; i < 256; i++) { int v = sp[i]; sp[i] = run; run += v; } }
    __syncthreads();
    int run = sp[t];
    #pragma unroll
    for (int i = 0; i < 16; i++) {
        int v = g_mcnt[base + i];
        g_moff[base + i] = run; g_mcnt[base + i] = run; run += v;
    }
    if (t == 255) g_moff[NP] = NEM;
    #pragma unroll
    for (int i = 0; i < 16; i++) {
        int idx = base + i;
        float a = g_degi[idx], b = g_dego[idx];
        g_nim[idx] = (a > 0.f) ? rsqrtf(a) : 1.f;
        g_nom[idx] = (b > 0.f) ? rsqrtf(b) : 1.f;
    }
}

__global__ void k_mscatter_prep(const float* __restrict__ mew, const int* __restrict__ med) {
    int e = blockIdx.x * 256 + threadIdx.x;
    if (e < NEM) {
        int s = med[2 * e], d = med[2 * e + 1];
        int pos = atomicAdd(&g_mcnt[d], 1);
        g_msrc[pos]  = s;
        g_mcoef[pos] = mew[e] * g_nom[s];
    }
}

__global__ void k_mgc1(const float* __restrict__ W1m, const float* __restrict__ b1m) {
    extern __shared__ float smf[];
    float* sW = smf;
    float* sA = smf + ROD * HIDD;
    int tid = threadIdx.x, p0 = blockIdx.x * 16;
    for (int i = tid; i < ROD * HIDD; i += 256) sW[i] = W1m[i];
    for (int i = tid; i < 16 * ROD; i += 256) sA[i] = 0.f;
    __syncthreads();
    int d = tid & 63, qo = tid >> 6;
    for (int r = 0; r < 16; r++) {
        int t = p0 + r;
        int b = g_moff[t], en = g_moff[t + 1];
        float acc = 0.f;
        for (int q = b + qo; q < en; q += 4)
            acc += g_readout[g_msrc[q] * ROD + d] * g_mcoef[q];
        atomicAdd(&sA[r * ROD + d], acc);
    }
    __syncthreads();
    for (int i = tid; i < 16 * ROD; i += 256) sA[i] *= g_nim[p0 + (i >> 6)];
    __syncthreads();
    float acc[16];
    #pragma unroll
    for (int r = 0; r < 16; r++) acc[r] = 0.f;
    #pragma unroll 2
    for (int k = 0; k < ROD; k++) {
        float wv = sW[k * HIDD + tid];
        #pragma unroll
        for (int r = 0; r < 16; r++) acc[r] = fmaf(sA[r * ROD + k], wv, acc[r]);
    }
    float bb = b1m[tid];
    #pragma unroll
    for (int r = 0; r < 16; r++)
        g_h1m[(p0 + r) * HIDD + tid] = fmaxf(acc[r] + bb, 0.f);
}

// 512 threads: 2 row-groups for gather/GEMM1, 4 row-groups for GEMM2
__global__ void k_mgc2(const float* __restrict__ W2m, const float* __restrict__ b2m,
                       const float* __restrict__ Wu1, const float* __restrict__ bu1) {
    extern __shared__ float smf[];
    float* sA = smf;              // 16*256
    float* sH = smf + 16 * HIDD;  // 16*256
    int tid = threadIdx.x, p0 = blockIdx.x * 16;
    int f = tid & 255, rg = tid >> 8;       // rg in {0,1}

    #pragma unroll
    for (int r8 = 0; r8 < 8; r8++) {
        int r = rg * 8 + r8, t = p0 + r;
        int b = g_moff[t], en = g_moff[t + 1];
        float acc = 0.f;
        #pragma unroll 2
        for (int q = b; q < en; q++)
            acc += g_h1m[g_msrc[q] * HIDD + f] * g_mcoef[q];
        sA[r * HIDD + f] = acc * g_nim[t];
    }
    __syncthreads();
    {
        float acc[8];
        #pragma unroll
        for (int r = 0; r < 8; r++) acc[r] = 0.f;
        #pragma unroll 2
        for (int k = 0; k < HIDD; k++) {
            float wv = __ldg(&W2m[k * HIDD + f]);
            #pragma unroll
            for (int r = 0; r < 8; r++)
                acc[r] = fmaf(sA[(rg * 8 + r) * HIDD + k], wv, acc[r]);
        }
        float bb = b2m[f];
        #pragma unroll
        for (int r = 0; r < 8; r++)
            sH[(rg * 8 + r) * HIDD + f] = fmaxf(acc[r] + bb, 0.f);
    }
    __syncthreads();
    {
        int m = tid & 127, grp = tid >> 7;   // 4 groups x 4 rows
        float acc[4];
        #pragma unroll
        for (int r = 0; r < 4; r++) acc[r] = 0.f;
        #pragma unroll 2
        for (int k = 0; k < HIDD; k++) {
            float wv = __ldg(&Wu1[k * RHD + m]);
            #pragma unroll
            for (int r = 0; r < 4; r++)
                acc[r] = fmaf(sH[(grp * 4 + r) * HIDD + k], wv, acc[r]);
        }
        float bb = bu1[m];
        float s = 0.f;
        #pragma unroll
        for (int r = 0; r < 4; r++) s += fmaxf(acc[r] + bb, 0.f);
        atomicAdd(&g_r[m], s);
    }
}

__global__ void k_final(const float* __restrict__ Wout, const float* __restrict__ bout,
                        float* __restrict__ out) {
    int o = threadIdx.x;
    if (o < OUTD) {
        float s = bout[o];
        for (int j = 0; j < RHD; j++) s = fmaf(g_r[j], Wout[j * OUTD + o], s);
        out[o] = s;
    }
}

// ---------------- launch ----------------
extern "C" void kernel_launch(void* const* d_in, const int* in_sizes, int n_in,
                              void* d_out, int out_size) {
    const float* feats = (const float*)d_in[0];
    const float* pew   = (const float*)d_in[1];
    const float* mew   = (const float*)d_in[2];
    const float* W1p   = (const float*)d_in[3];
    const float* b1p   = (const float*)d_in[4];
    const float* W2p   = (const float*)d_in[5];
    const float* b2p   = (const float*)d_in[6];
    const float* W1m   = (const float*)d_in[7];
    const float* b1m   = (const float*)d_in[8];
    const float* W2m   = (const float*)d_in[9];
    const float* b2m   = (const float*)d_in[10];
    const float* Wu1   = (const float*)d_in[11];
    const float* bu1   = (const float*)d_in[12];
    const float* Wout  = (const float*)d_in[13];
    const float* bout  = (const float*)d_in[14];
    const int*   pedg  = (const int*)d_in[15];
    const int*   medg  = (const int*)d_in[16];

    cudaFuncSetAttribute(k_mgc1, cudaFuncAttributeMaxDynamicSharedMemorySize, 69632);

    k_csr<<<1, 256>>>(pedg);
    k_wprep<<<64, 256>>>(W1p, W2p);
    k_agg1<<<NP, 256>>>(feats, pew, pedg);
    k_mlp<<<NP / 2, 256>>>(b1p, b2p);            // ncu capture slot (#4)
    k_mcount<<<NEM / 256, 256>>>(mew, medg);
    k_scan_norm<<<1, 256>>>();
    k_mscatter_prep<<<NEM / 256, 256>>>(mew, medg);
    k_mgc1<<<NP / 16, 256, 69632>>>(W1m, b1m);
    k_mgc2<<<NP / 16, 512, 32768>>>(W2m, b2m, Wu1, bu1);
    k_final<<<1, 32>>>(Wout, bout, (float*)d_out);
}

// round 13
// speedup vs baseline: 2.0684x; 1.0390x over previous
#include <cuda_runtime.h>
#include <cuda_bf16.h>
#include <cstdint>

#define NP   4096
#define NN   50
#define NE   250
#define NEM  65536
#define IND  32
#define PHD  512
#define ROD  64
#define HIDD 256
#define RHD  128
#define OUTD 15

// ---------------- persistent device scratch ----------------
__device__ float g_readout[NP * ROD];
__device__ float g_degi[NP], g_dego[NP], g_nim[NP], g_nom[NP];
__device__ float g_h1m[NP * HIDD];
__device__ float g_r[RHD];
__device__ int   g_poff[NN + 1];
__device__ int   g_peid[NE];
__device__ int   g_gsrc[NE];
__device__ int   g_mcnt[NP];
__device__ int   g_moff[NP + 1];
__device__ int   g_msrc[NEM];
__device__ float g_mcoef[NEM];
// patch-MLP staging
__device__ float g_agg[NP * 64 * IND];
__device__ float g_gcoefP[NP * 256];
__device__ float g_pni[NP * 64];
// fragment-packed weights, uint4 = {hi_reg0, hi_reg1, lo_reg0, lo_reg1}
__device__ uint4 g_w1f4[64 * 2 * 32];     // W1: [nt][kt][lane]
__device__ uint4 g_w2f4[8 * 32 * 32];     // W2: [nt][kt][lane]

// ---------------- helpers ----------------
__device__ __forceinline__ uint32_t pkbf(__nv_bfloat16 a, __nv_bfloat16 b) {
    unsigned short ua = *(unsigned short*)&a, ub = *(unsigned short*)&b;
    return ((uint32_t)ub << 16) | (uint32_t)ua;
}
__device__ __forceinline__ void split2(float x0, float x1, uint32_t& hi, uint32_t& lo) {
    __nv_bfloat16 h0 = __float2bfloat16(x0), h1 = __float2bfloat16(x1);
    __nv_bfloat16 l0 = __float2bfloat16(x0 - __bfloat162float(h0));
    __nv_bfloat16 l1 = __float2bfloat16(x1 - __bfloat162float(h1));
    hi = pkbf(h0, h1); lo = pkbf(l0, l1);
}
__device__ __forceinline__ uint32_t cvt2(float xlo, float xhi) {
    uint32_t r;
    asm("cvt.rn.bf16x2.f32 %0, %1, %2;" : "=r"(r) : "f"(xhi), "f"(xlo));
    return r;
}
__device__ __forceinline__ void mma16816(float* c, const uint32_t* a, const uint32_t* b) {
    asm volatile("mma.sync.aligned.m16n8k16.row.col.f32.bf16.bf16.f32 "
        "{%0,%1,%2,%3}, {%4,%5,%6,%7}, {%8,%9}, {%0,%1,%2,%3};"
        : "+f"(c[0]), "+f"(c[1]), "+f"(c[2]), "+f"(c[3])
        : "r"(a[0]), "r"(a[1]), "r"(a[2]), "r"(a[3]), "r"(b[0]), "r"(b[1]));
}

// ---------------- setup kernels ----------------
__global__ void k_csr(const int* __restrict__ pedges) {
    __shared__ int sdst[NE], ssrc[NE], cnt[NN], off[NN + 1];
    int tid = threadIdx.x;
    for (int e = tid; e < NE; e += 256) {
        ssrc[e] = pedges[2 * e];
        sdst[e] = pedges[2 * e + 1];
    }
    if (tid < NN) cnt[tid] = 0;
    __syncthreads();
    for (int e = tid; e < NE; e += 256) atomicAdd(&cnt[sdst[e]], 1);
    __syncthreads();
    if (tid == 0) {
        int run = 0;
        for (int n = 0; n < NN; n++) { off[n] = run; run += cnt[n]; }
        off[NN] = run;
    }
    __syncthreads();
    if (tid <= NN) g_poff[tid] = off[tid];
    if (tid < NE) {
        int d = sdst[tid], rank = 0;
        for (int e2 = 0; e2 < tid; e2++) rank += (sdst[e2] == d);
        int pos = off[d] + rank;
        g_peid[pos] = tid;
        g_gsrc[pos] = ssrc[tid];
    }
}

__global__ void k_wprep(const float* __restrict__ W1p, const float* __restrict__ W2p) {
    int i = blockIdx.x * 256 + threadIdx.x;    // grid 64 -> 16384
    if (i < 4096) {
        int lane = i & 31, kt = (i >> 5) & 1, nt = i >> 6;
        int n = nt * 8 + (lane >> 2);
        int k0 = kt * 16 + (lane & 3) * 2;
        uint32_t h0, l0, h1, l1;
        split2(W1p[k0 * PHD + n],       W1p[(k0 + 1) * PHD + n], h0, l0);
        split2(W1p[(k0 + 8) * PHD + n], W1p[(k0 + 9) * PHD + n], h1, l1);
        g_w1f4[i] = make_uint4(h0, h1, l0, l1);
    } else if (i < 4096 + 8192) {
        int j = i - 4096;
        int lane = j & 31, kt = (j >> 5) & 31, nt = j >> 10;
        int n = nt * 8 + (lane >> 2);
        int k0 = kt * 16 + (lane & 3) * 2;
        uint32_t h0, l0, h1, l1;
        split2(W2p[k0 * ROD + n],       W2p[(k0 + 1) * ROD + n], h0, l0);
        split2(W2p[(k0 + 8) * ROD + n], W2p[(k0 + 9) * ROD + n], h1, l1);
        g_w2f4[j] = make_uint4(h0, h1, l0, l1);
    }
    if (i < NP) { g_mcnt[i] = 0; g_degi[i] = 0.f; g_dego[i] = 0.f; }
    if (i < RHD) g_r[i] = 0.f;
}

// ---------------- per-patch layer-1 aggregation ----------------
__global__ void __launch_bounds__(256) k_agg1(const float* __restrict__ feats,
                                              const float* __restrict__ pew,
                                              const int* __restrict__ pedges) {
    __shared__ int   ssrc[NE], sdst[NE], eoff[NN + 1], sgs[NE];
    __shared__ float coef[NE], gc[NE], ni[NN], no_[NN], x[NN * IND];
    int tid = threadIdx.x, p = blockIdx.x;
    for (int i = tid; i < NE; i += 256) {
        ssrc[i] = pedges[2 * i]; sdst[i] = pedges[2 * i + 1];
        coef[i] = pew[p * NE + i]; sgs[i] = g_gsrc[i];
    }
    for (int i = tid; i <= NN; i += 256) eoff[i] = g_poff[i];
    for (int i = tid; i < NN; i += 256) { ni[i] = 0.f; no_[i] = 0.f; }
    for (int i = tid; i < NN * IND; i += 256) x[i] = feats[p * NN * IND + i];
    __syncthreads();
    for (int i = tid; i < NE; i += 256) {
        float w = coef[i];
        atomicAdd(&ni[sdst[i]], w);
        atomicAdd(&no_[ssrc[i]], w);
    }
    __syncthreads();
    if (tid < NN) {
        float a = ni[tid], b = no_[tid];
        ni[tid]  = (a > 0.f) ? rsqrtf(a) : 1.f;
        no_[tid] = (b > 0.f) ? rsqrtf(b) : 1.f;
    }
    __syncthreads();
    for (int q = tid; q < NE; q += 256) {
        int e = g_peid[q];
        gc[q] = coef[e] * no_[ssrc[e]];
    }
    __syncthreads();
    for (int i = tid; i < 64 * IND; i += 256) {
        int n = i >> 5, d = i & 31;
        float s = 0.f;
        if (n < NN) {
            int b0 = eoff[n], e0 = eoff[n + 1];
            for (int q = b0; q < e0; q++) s += x[sgs[q] * IND + d] * gc[q];
            s *= ni[n];
        }
        g_agg[p * 2048 + i] = s;
    }
    for (int q = tid; q < NE; q += 256) g_gcoefP[p * 256 + q] = gc[q];
    if (tid < NN) g_pni[p * 64 + tid] = ni[tid];
}

// ---------------- fused MLP + layer-2 aggregation + readout (2 patches/CTA) ----------------
// warp = 32 rows (2 row-tiles) x half the k-range (KS=2): weight L1 traffic halved.
struct MLPShared {
    float sb1[PHD];                 // 2048 B; reused as partial buffer at the end
    int   gs[NE];                   // 1000
    int   eo[NN + 2];               // 208
    float gc[2][256];               // 2048
    float sni[2][ROD];              // 512
    union {
        float sagg[128 * IND];      // 16384
        float yt[2][ROD][66];       // 33792  [patch][col][node]
    } u;
};

__global__ void __launch_bounds__(256, 2) k_mlp(const float* __restrict__ b1p,
                                                const float* __restrict__ b2p) {
    __shared__ MLPShared S;
    const int tid = threadIdx.x, lane = tid & 31, wid = tid >> 5;
    const int b = blockIdx.x;
    const int rg = wid & 3, ks = wid >> 2;
    const int m0 = rg * 32;
    const int rl = lane >> 2;
    const int kq = (lane & 3) * 2;

    for (int i = tid; i < 128 * IND; i += 256) S.u.sagg[i] = g_agg[b * 4096 + i];
    for (int i = tid; i < PHD; i += 256) S.sb1[i] = b1p[i];
    for (int q = tid; q < NE; q += 256) {
        S.gs[q] = g_gsrc[q];
        S.gc[0][q] = g_gcoefP[(2 * b) * 256 + q];
        S.gc[1][q] = g_gcoefP[(2 * b + 1) * 256 + q];
    }
    for (int i = tid; i <= NN; i += 256) S.eo[i] = g_poff[i];
    if (tid < NN) {
        S.sni[0][tid] = g_pni[(2 * b) * 64 + tid];
        S.sni[1][tid] = g_pni[(2 * b + 1) * 64 + tid];
    }
    __syncthreads();

    // A1 fragments, hi only, 2 row-tiles
    uint32_t a1[2][2][4];   // [rt][kt][reg]
    #pragma unroll
    for (int rt = 0; rt < 2; rt++)
        #pragma unroll
        for (int kt = 0; kt < 2; kt++)
            #pragma unroll
            for (int j = 0; j < 4; j++) {
                int rr = m0 + rt * 16 + rl + (j & 1) * 8;
                int kk = kt * 16 + kq + (j >> 1) * 8;
                a1[rt][kt][j] = cvt2(S.u.sagg[rr * IND + kk], S.u.sagg[rr * IND + kk + 1]);
            }
    __syncthreads();   // all sagg reads complete before yt overwrites the union

    float acc2[2][8][4];
    #pragma unroll
    for (int rt = 0; rt < 2; rt++)
        #pragma unroll
        for (int nt = 0; nt < 8; nt++)
            #pragma unroll
            for (int j = 0; j < 4; j++) acc2[rt][nt][j] = 0.f;

    for (int c = ks * 4; c < ks * 4 + 4; c++) {
        #pragma unroll
        for (int ktl = 0; ktl < 4; ktl++) {
            uint32_t a2[2][4];
            #pragma unroll
            for (int half = 0; half < 2; half++) {
                int ntl = 2 * ktl + half;
                int nt = c * 8 + ntl;
                float acc[2][4] = {{0.f, 0.f, 0.f, 0.f}, {0.f, 0.f, 0.f, 0.f}};
                #pragma unroll
                for (int kt = 0; kt < 2; kt++) {
                    uint4 w = g_w1f4[(nt * 2 + kt) * 32 + lane];
                    uint32_t bh[2] = {w.x, w.y}, bl[2] = {w.z, w.w};
                    mma16816(acc[0], a1[0][kt], bh);
                    mma16816(acc[0], a1[0][kt], bl);
                    mma16816(acc[1], a1[1][kt], bh);
                    mma16816(acc[1], a1[1][kt], bl);
                }
                int nbase = c * 64 + ntl * 8 + kq;
                float b0 = S.sb1[nbase], b1 = S.sb1[nbase + 1];
                #pragma unroll
                for (int rt = 0; rt < 2; rt++) {
                    float f0 = fmaxf(acc[rt][0] + b0, 0.f);
                    float f1 = fmaxf(acc[rt][1] + b1, 0.f);
                    float f2 = fmaxf(acc[rt][2] + b0, 0.f);
                    float f3 = fmaxf(acc[rt][3] + b1, 0.f);
                    a2[rt][2 * half]     = cvt2(f0, f1);
                    a2[rt][2 * half + 1] = cvt2(f2, f3);
                }
            }
            int kt = c * 4 + ktl;
            #pragma unroll
            for (int nt = 0; nt < 8; nt++) {
                uint4 w = g_w2f4[(nt * 32 + kt) * 32 + lane];
                uint32_t bh[2] = {w.x, w.y}, bl[2] = {w.z, w.w};
                mma16816(acc2[0][nt], a2[0], bh);
                mma16816(acc2[0][nt], a2[0], bl);
                mma16816(acc2[1][nt], a2[1], bh);
                mma16816(acc2[1][nt], a2[1], bl);
            }
        }
    }
    __syncthreads();

    // deterministic k-half combine into yt: ks0 stores, ks1 adds
    if (ks == 0) {
        #pragma unroll
        for (int rt = 0; rt < 2; rt++) {
            int r1 = m0 + rt * 16 + rl, r2 = r1 + 8;
            int p1 = r1 >> 6, i1 = r1 & 63, p2 = r2 >> 6, i2 = r2 & 63;
            #pragma unroll
            for (int nt = 0; nt < 8; nt++) {
                int n = nt * 8 + kq;
                S.u.yt[p1][n][i1]     = acc2[rt][nt][0];
                S.u.yt[p1][n + 1][i1] = acc2[rt][nt][1];
                S.u.yt[p2][n][i2]     = acc2[rt][nt][2];
                S.u.yt[p2][n + 1][i2] = acc2[rt][nt][3];
            }
        }
    }
    __syncthreads();
    if (ks == 1) {
        #pragma unroll
        for (int rt = 0; rt < 2; rt++) {
            int r1 = m0 + rt * 16 + rl, r2 = r1 + 8;
            int p1 = r1 >> 6, i1 = r1 & 63, p2 = r2 >> 6, i2 = r2 & 63;
            #pragma unroll
            for (int nt = 0; nt < 8; nt++) {
                int n = nt * 8 + kq;
                S.u.yt[p1][n][i1]     += acc2[rt][nt][0];
                S.u.yt[p1][n + 1][i1] += acc2[rt][nt][1];
                S.u.yt[p2][n][i2]     += acc2[rt][nt][2];
                S.u.yt[p2][n + 1][i2] += acc2[rt][nt][3];
            }
        }
    }
    __syncthreads();

    // layer-2 aggregation + bias + relu + partial node-sum
    {
        int pl = tid >> 7, rest = tid & 127;
        int d = rest & 63, g = rest >> 6;
        float bb = b2p[d];
        float part = 0.f;
        for (int n = g * 25; n < g * 25 + 25; n++) {
            int b0 = S.eo[n], e0 = S.eo[n + 1];
            float s = 0.f;
            for (int q = b0; q < e0; q++)
                s += S.u.yt[pl][d][S.gs[q]] * S.gc[pl][q];
            part += fmaxf(S.sni[pl][n] * s + bb, 0.f);
        }
        S.sb1[tid] = part;
    }
    __syncthreads();
    if (tid < 128) {
        int pl = tid >> 6, d = tid & 63;
        float s = S.sb1[pl * 128 + d] + S.sb1[pl * 128 + 64 + d];
        g_readout[(2 * b + pl) * ROD + d] = s * (1.f / NN);
    }
}

// ---------------- mesh stage ----------------
__global__ void k_mcount(const float* __restrict__ mew, const int* __restrict__ med) {
    int e = blockIdx.x * 256 + threadIdx.x;
    if (e < NEM) {
        int s = med[2 * e], d = med[2 * e + 1];
        float w = mew[e];
        atomicAdd(&g_mcnt[d], 1);
        atomicAdd(&g_degi[d], w);
        atomicAdd(&g_dego[s], w);
    }
}

__global__ void k_scan_norm() {
    __shared__ int sp[256];
    int t = threadIdx.x, base = t * 16;
    int s = 0;
    #pragma unroll
    for (int i = 0; i < 16; i++) s += g_mcnt[base + i];
    sp[t] = s; __syncthreads();
    if (t == 0) { int run = 0; for (int i = 0; i < 256; i++) { int v = sp[i]; sp[i] = run; run += v; } }
    __syncthreads();
    int run = sp[t];
    #pragma unroll
    for (int i = 0; i < 16; i++) {
        int v = g_mcnt[base + i];
        g_moff[base + i] = run; g_mcnt[base + i] = run; run += v;
    }
    if (t == 255) g_moff[NP] = NEM;
    #pragma unroll
    for (int i = 0; i < 16; i++) {
        int idx = base + i;
        float a = g_degi[idx], b = g_dego[idx];
        g_nim[idx] = (a > 0.f) ? rsqrtf(a) : 1.f;
        g_nom[idx] = (b > 0.f) ? rsqrtf(b) : 1.f;
    }
}

__global__ void k_mscatter_prep(const float* __restrict__ mew, const int* __restrict__ med) {
    int e = blockIdx.x * 256 + threadIdx.x;
    if (e < NEM) {
        int s = med[2 * e], d = med[2 * e + 1];
        int pos = atomicAdd(&g_mcnt[d], 1);
        g_msrc[pos]  = s;
        g_mcoef[pos] = mew[e] * g_nom[s];
    }
}

__global__ void k_mgc1(const float* __restrict__ W1m, const float* __restrict__ b1m) {
    extern __shared__ float smf[];
    float* sW = smf;
    float* sA = smf + ROD * HIDD;
    int tid = threadIdx.x, p0 = blockIdx.x * 16;
    for (int i = tid; i < ROD * HIDD; i += 256) sW[i] = W1m[i];
    for (int i = tid; i < 16 * ROD; i += 256) sA[i] = 0.f;
    __syncthreads();
    int d = tid & 63, qo = tid >> 6;
    for (int r = 0; r < 16; r++) {
        int t = p0 + r;
        int b = g_moff[t], en = g_moff[t + 1];
        float acc = 0.f;
        for (int q = b + qo; q < en; q += 4)
            acc += g_readout[g_msrc[q] * ROD + d] * g_mcoef[q];
        atomicAdd(&sA[r * ROD + d], acc);
    }
    __syncthreads();
    for (int i = tid; i < 16 * ROD; i += 256) sA[i] *= g_nim[p0 + (i >> 6)];
    __syncthreads();
    float acc[16];
    #pragma unroll
    for (int r = 0; r < 16; r++) acc[r] = 0.f;
    #pragma unroll 2
    for (int k = 0; k < ROD; k++) {
        float wv = sW[k * HIDD + tid];
        #pragma unroll
        for (int r = 0; r < 16; r++) acc[r] = fmaf(sA[r * ROD + k], wv, acc[r]);
    }
    float bb = b1m[tid];
    #pragma unroll
    for (int r = 0; r < 16; r++)
        g_h1m[(p0 + r) * HIDD + tid] = fmaxf(acc[r] + bb, 0.f);
}

// 512 threads
__global__ void k_mgc2(const float* __restrict__ W2m, const float* __restrict__ b2m,
                       const float* __restrict__ Wu1, const float* __restrict__ bu1) {
    extern __shared__ float smf[];
    float* sA = smf;              // 16*256
    float* sH = smf + 16 * HIDD;  // 16*256
    int tid = threadIdx.x, p0 = blockIdx.x * 16;
    int f = tid & 255, rg = tid >> 8;

    #pragma unroll
    for (int r8 = 0; r8 < 8; r8++) {
        int r = rg * 8 + r8, t = p0 + r;
        int b = g_moff[t], en = g_moff[t + 1];
        float acc = 0.f;
        #pragma unroll 2
        for (int q = b; q < en; q++)
            acc += g_h1m[g_msrc[q] * HIDD + f] * g_mcoef[q];
        sA[r * HIDD + f] = acc * g_nim[t];
    }
    __syncthreads();
    {
        float acc[8];
        #pragma unroll
        for (int r = 0; r < 8; r++) acc[r] = 0.f;
        #pragma unroll 2
        for (int k = 0; k < HIDD; k++) {
            float wv = __ldg(&W2m[k * HIDD + f]);
            #pragma unroll
            for (int r = 0; r < 8; r++)
                acc[r] = fmaf(sA[(rg * 8 + r) * HIDD + k], wv, acc[r]);
        }
        float bb = b2m[f];
        #pragma unroll
        for (int r = 0; r < 8; r++)
            sH[(rg * 8 + r) * HIDD + f] = fmaxf(acc[r] + bb, 0.f);
    }
    __syncthreads();
    {
        int m = tid & 127, grp = tid >> 7;
        float acc[4];
        #pragma unroll
        for (int r = 0; r < 4; r++) acc[r] = 0.f;
        #pragma unroll 2
        for (int k = 0; k < HIDD; k++) {
            float wv = __ldg(&Wu1[k * RHD + m]);
            #pragma unroll
            for (int r = 0; r < 4; r++)
                acc[r] = fmaf(sH[(grp * 4 + r) * HIDD + k], wv, acc[r]);
        }
        float bb = bu1[m];
        float s = 0.f;
        #pragma unroll
        for (int r = 0; r < 4; r++) s += fmaxf(acc[r] + bb, 0.f);
        atomicAdd(&g_r[m], s);
    }
}

__global__ void k_final(const float* __restrict__ Wout, const float* __restrict__ bout,
                        float* __restrict__ out) {
    int o = threadIdx.x;
    if (o < OUTD) {
        float s = bout[o];
        for (int j = 0; j < RHD; j++) s = fmaf(g_r[j], Wout[j * OUTD + o], s);
        out[o] = s;
    }
}

// ---------------- launch ----------------
extern "C" void kernel_launch(void* const* d_in, const int* in_sizes, int n_in,
                              void* d_out, int out_size) {
    const float* feats = (const float*)d_in[0];
    const float* pew   = (const float*)d_in[1];
    const float* mew   = (const float*)d_in[2];
    const float* W1p   = (const float*)d_in[3];
    const float* b1p   = (const float*)d_in[4];
    const float* W2p   = (const float*)d_in[5];
    const float* b2p   = (const float*)d_in[6];
    const float* W1m   = (const float*)d_in[7];
    const float* b1m   = (const float*)d_in[8];
    const float* W2m   = (const float*)d_in[9];
    const float* b2m   = (const float*)d_in[10];
    const float* Wu1   = (const float*)d_in[11];
    const float* bu1   = (const float*)d_in[12];
    const float* Wout  = (const float*)d_in[13];
    const float* bout  = (const float*)d_in[14];
    const int*   pedg  = (const int*)d_in[15];
    const int*   medg  = (const int*)d_in[16];

    cudaFuncSetAttribute(k_mgc1, cudaFuncAttributeMaxDynamicSharedMemorySize, 69632);

    k_csr<<<1, 256>>>(pedg);
    k_wprep<<<64, 256>>>(W1p, W2p);
    k_agg1<<<NP, 256>>>(feats, pew, pedg);
    k_mlp<<<NP / 2, 256>>>(b1p, b2p);            // ncu capture slot (#4)
    k_mcount<<<NEM / 256, 256>>>(mew, medg);
    k_scan_norm<<<1, 256>>>();
    k_mscatter_prep<<<NEM / 256, 256>>>(mew, medg);
    k_mgc1<<<NP / 16, 256, 69632>>>(W1m, b1m);
    k_mgc2<<<NP / 16, 512, 32768>>>(W2m, b2m, Wu1, bu1);
    k_final<<<1, 32>>>(Wout, bout, (float*)d_out);
}

// round 14
// speedup vs baseline: 2.2042x; 1.0657x over previous
#include <cuda_runtime.h>
#include <cuda_bf16.h>
#include <cstdint>

#define NP   4096
#define NN   50
#define NE   250
#define NEM  65536
#define IND  32
#define PHD  512
#define ROD  64
#define HIDD 256
#define RHD  128
#define OUTD 15

// ---------------- persistent device scratch ----------------
__device__ float g_readout[NP * ROD];
__device__ float g_degi[NP], g_dego[NP], g_nim[NP], g_nom[NP];
__device__ float g_h1m[NP * HIDD];
__device__ float g_r[RHD];
__device__ int   g_poff[NN + 1];
__device__ int   g_peid[NE];
__device__ int   g_gsrc[NE];
__device__ int   g_mcnt[NP];
__device__ int   g_moff[NP + 1];
__device__ int   g_msrc[NEM];
__device__ float g_mcoef[NEM];
// fragment-packed weights, uint4 = {hi_reg0, hi_reg1, lo_reg0, lo_reg1}
__device__ uint4 g_w1f4[64 * 2 * 32];     // W1: [nt][kt][lane]
__device__ uint4 g_w2f4[8 * 32 * 32];     // W2: [nt][kt][lane]

// ---------------- helpers ----------------
__device__ __forceinline__ uint32_t pkbf(__nv_bfloat16 a, __nv_bfloat16 b) {
    unsigned short ua = *(unsigned short*)&a, ub = *(unsigned short*)&b;
    return ((uint32_t)ub << 16) | (uint32_t)ua;
}
__device__ __forceinline__ void split2(float x0, float x1, uint32_t& hi, uint32_t& lo) {
    __nv_bfloat16 h0 = __float2bfloat16(x0), h1 = __float2bfloat16(x1);
    __nv_bfloat16 l0 = __float2bfloat16(x0 - __bfloat162float(h0));
    __nv_bfloat16 l1 = __float2bfloat16(x1 - __bfloat162float(h1));
    hi = pkbf(h0, h1); lo = pkbf(l0, l1);
}
__device__ __forceinline__ uint32_t cvt2(float xlo, float xhi) {
    uint32_t r;
    asm("cvt.rn.bf16x2.f32 %0, %1, %2;" : "=r"(r) : "f"(xhi), "f"(xlo));
    return r;
}
__device__ __forceinline__ void mma16816(float* c, const uint32_t* a, const uint32_t* b) {
    asm volatile("mma.sync.aligned.m16n8k16.row.col.f32.bf16.bf16.f32 "
        "{%0,%1,%2,%3}, {%4,%5,%6,%7}, {%8,%9}, {%0,%1,%2,%3};"
        : "+f"(c[0]), "+f"(c[1]), "+f"(c[2]), "+f"(c[3])
        : "r"(a[0]), "r"(a[1]), "r"(a[2]), "r"(a[3]), "r"(b[0]), "r"(b[1]));
}

// ---------------- setup kernels ----------------
__global__ void k_csr(const int* __restrict__ pedges) {
    __shared__ int sdst[NE], ssrc[NE], cnt[NN], off[NN + 1];
    int tid = threadIdx.x;
    for (int e = tid; e < NE; e += 256) {
        ssrc[e] = pedges[2 * e];
        sdst[e] = pedges[2 * e + 1];
    }
    if (tid < NN) cnt[tid] = 0;
    __syncthreads();
    for (int e = tid; e < NE; e += 256) atomicAdd(&cnt[sdst[e]], 1);
    __syncthreads();
    if (tid == 0) {
        int run = 0;
        for (int n = 0; n < NN; n++) { off[n] = run; run += cnt[n]; }
        off[NN] = run;
    }
    __syncthreads();
    if (tid <= NN) g_poff[tid] = off[tid];
    if (tid < NE) {
        int d = sdst[tid], rank = 0;
        for (int e2 = 0; e2 < tid; e2++) rank += (sdst[e2] == d);
        int pos = off[d] + rank;
        g_peid[pos] = tid;
        g_gsrc[pos] = ssrc[tid];
    }
}

__global__ void k_wprep(const float* __restrict__ W1p, const float* __restrict__ W2p) {
    int i = blockIdx.x * 256 + threadIdx.x;    // grid 64 -> 16384
    if (i < 4096) {
        int lane = i & 31, kt = (i >> 5) & 1, nt = i >> 6;
        int n = nt * 8 + (lane >> 2);
        int k0 = kt * 16 + (lane & 3) * 2;
        uint32_t h0, l0, h1, l1;
        split2(W1p[k0 * PHD + n],       W1p[(k0 + 1) * PHD + n], h0, l0);
        split2(W1p[(k0 + 8) * PHD + n], W1p[(k0 + 9) * PHD + n], h1, l1);
        g_w1f4[i] = make_uint4(h0, h1, l0, l1);
    } else if (i < 4096 + 8192) {
        int j = i - 4096;
        int lane = j & 31, kt = (j >> 5) & 31, nt = j >> 10;
        int n = nt * 8 + (lane >> 2);
        int k0 = kt * 16 + (lane & 3) * 2;
        uint32_t h0, l0, h1, l1;
        split2(W2p[k0 * ROD + n],       W2p[(k0 + 1) * ROD + n], h0, l0);
        split2(W2p[(k0 + 8) * ROD + n], W2p[(k0 + 9) * ROD + n], h1, l1);
        g_w2f4[j] = make_uint4(h0, h1, l0, l1);
    }
    if (i < NP) { g_mcnt[i] = 0; g_degi[i] = 0.f; g_dego[i] = 0.f; }
    if (i < RHD) g_r[i] = 0.f;
}

// ---------------- fused agg1 + MLP + layer-2 aggregation + readout (2 patches/CTA) ----------------
struct MLPShared {
    float sb1[PHD];                 // 2048 B; reused as partial buffer at the end
    int   gs[NE];                   // 1000
    int   eo[NN + 2];               // 208
    float gc[2][256];               // 2048
    float sni[2][ROD];              // 512  (degree accum, then rsqrt)
    int   eid[NE];                  // 1000  phase-A
    float coef[2][NE];              // 2000  phase-A
    float no_[2][NN];               // 400   phase-A
    union {
        struct {
            float sagg[128 * IND];  // 16384
            float x[2][NN * IND];   // 12800
        } pa;
        float yt[2][ROD][66];       // 33792  [patch][col][node]
    } u;
};
// sizeof ~ 43 KB (static smem, < 48 KB)

__global__ void __launch_bounds__(256, 2) k_mlp(const float* __restrict__ feats,
                                                const float* __restrict__ pew,
                                                const int* __restrict__ pedges,
                                                const float* __restrict__ b1p,
                                                const float* __restrict__ b2p) {
    __shared__ MLPShared S;
    const int tid = threadIdx.x, lane = tid & 31, wid = tid >> 5;
    const int b = blockIdx.x;
    const int rg = wid & 3, ks = wid >> 2;
    const int m0 = rg * 32;
    const int rl = lane >> 2;
    const int kq = (lane & 3) * 2;

    // ---- phase A: graph setup + layer-1 aggregation (both patches) ----
    for (int q = tid; q < NE; q += 256) {
        S.gs[q]  = g_gsrc[q];
        S.eid[q] = g_peid[q];
    }
    for (int i = tid; i <= NN; i += 256) S.eo[i] = g_poff[i];
    for (int i = tid; i < PHD; i += 256) S.sb1[i] = b1p[i];
    for (int i = tid; i < 2 * NE; i += 256) {
        int pl = (i >= NE), e = pl ? i - NE : i;
        S.coef[pl][e] = pew[(2 * b + pl) * NE + e];
    }
    for (int i = tid; i < 2 * NN * IND; i += 256) {
        int pl = (i >= NN * IND), j = pl ? i - NN * IND : i;
        S.u.pa.x[pl][j] = feats[(2 * b + pl) * NN * IND + j];
    }
    if (tid < 128) {
        int pl = tid >> 6, n = tid & 63;
        S.sni[pl][n] = 0.f;
        if (n < NN) S.no_[pl][n] = 0.f;
    }
    __syncthreads();
    for (int i = tid; i < 2 * NE; i += 256) {
        int pl = (i >= NE), e = pl ? i - NE : i;
        float w = S.coef[pl][e];
        atomicAdd(&S.sni[pl][pedges[2 * e + 1]], w);
        atomicAdd(&S.no_[pl][pedges[2 * e]], w);
    }
    __syncthreads();
    if (tid < 128) {
        int pl = tid >> 6, n = tid & 63;
        if (n < NN) {
            float a = S.sni[pl][n], c = S.no_[pl][n];
            S.sni[pl][n] = (a > 0.f) ? rsqrtf(a) : 1.f;
            S.no_[pl][n] = (c > 0.f) ? rsqrtf(c) : 1.f;
        }
    }
    __syncthreads();
    for (int i = tid; i < 2 * NE; i += 256) {
        int pl = (i >= NE), q = pl ? i - NE : i;
        S.gc[pl][q] = S.coef[pl][S.eid[q]] * S.no_[pl][S.gs[q]];
    }
    __syncthreads();
    for (int i = tid; i < 128 * IND; i += 256) {
        int row = i >> 5, d = i & 31;
        int pl = row >> 6, n = row & 63;
        float s = 0.f;
        if (n < NN) {
            int b0 = S.eo[n], e0 = S.eo[n + 1];
            for (int q = b0; q < e0; q++)
                s += S.u.pa.x[pl][S.gs[q] * IND + d] * S.gc[pl][q];
            s *= S.sni[pl][n];
        }
        S.u.pa.sagg[i] = s;
    }
    __syncthreads();

    // ---- A1 fragments, hi only, 2 row-tiles ----
    uint32_t a1[2][2][4];   // [rt][kt][reg]
    #pragma unroll
    for (int rt = 0; rt < 2; rt++)
        #pragma unroll
        for (int kt = 0; kt < 2; kt++)
            #pragma unroll
            for (int j = 0; j < 4; j++) {
                int rr = m0 + rt * 16 + rl + (j & 1) * 8;
                int kk = kt * 16 + kq + (j >> 1) * 8;
                a1[rt][kt][j] = cvt2(S.u.pa.sagg[rr * IND + kk],
                                     S.u.pa.sagg[rr * IND + kk + 1]);
            }
    __syncthreads();   // all sagg/x reads complete before yt overwrites the union

    float acc2[2][8][4];
    #pragma unroll
    for (int rt = 0; rt < 2; rt++)
        #pragma unroll
        for (int nt = 0; nt < 8; nt++)
            #pragma unroll
            for (int j = 0; j < 4; j++) acc2[rt][nt][j] = 0.f;

    for (int c = ks * 4; c < ks * 4 + 4; c++) {
        #pragma unroll
        for (int ktl = 0; ktl < 4; ktl++) {
            uint32_t a2[2][4];
            #pragma unroll
            for (int half = 0; half < 2; half++) {
                int ntl = 2 * ktl + half;
                int nt = c * 8 + ntl;
                float acc[2][4] = {{0.f, 0.f, 0.f, 0.f}, {0.f, 0.f, 0.f, 0.f}};
                #pragma unroll
                for (int kt = 0; kt < 2; kt++) {
                    uint4 w = g_w1f4[(nt * 2 + kt) * 32 + lane];
                    uint32_t bh[2] = {w.x, w.y}, bl[2] = {w.z, w.w};
                    mma16816(acc[0], a1[0][kt], bh);
                    mma16816(acc[0], a1[0][kt], bl);
                    mma16816(acc[1], a1[1][kt], bh);
                    mma16816(acc[1], a1[1][kt], bl);
                }
                int nbase = c * 64 + ntl * 8 + kq;
                float b0 = S.sb1[nbase], b1 = S.sb1[nbase + 1];
                #pragma unroll
                for (int rt = 0; rt < 2; rt++) {
                    float f0 = fmaxf(acc[rt][0] + b0, 0.f);
                    float f1 = fmaxf(acc[rt][1] + b1, 0.f);
                    float f2 = fmaxf(acc[rt][2] + b0, 0.f);
                    float f3 = fmaxf(acc[rt][3] + b1, 0.f);
                    a2[rt][2 * half]     = cvt2(f0, f1);
                    a2[rt][2 * half + 1] = cvt2(f2, f3);
                }
            }
            int kt = c * 4 + ktl;
            #pragma unroll
            for (int nt = 0; nt < 8; nt++) {
                uint4 w = g_w2f4[(nt * 32 + kt) * 32 + lane];
                uint32_t bh[2] = {w.x, w.y}, bl[2] = {w.z, w.w};
                mma16816(acc2[0][nt], a2[0], bh);
                mma16816(acc2[0][nt], a2[0], bl);
                mma16816(acc2[1][nt], a2[1], bh);
                mma16816(acc2[1][nt], a2[1], bl);
            }
        }
    }
    __syncthreads();

    // deterministic k-half combine into yt: ks0 stores, ks1 adds
    if (ks == 0) {
        #pragma unroll
        for (int rt = 0; rt < 2; rt++) {
            int r1 = m0 + rt * 16 + rl, r2 = r1 + 8;
            int p1 = r1 >> 6, i1 = r1 & 63, p2 = r2 >> 6, i2 = r2 & 63;
            #pragma unroll
            for (int nt = 0; nt < 8; nt++) {
                int n = nt * 8 + kq;
                S.u.yt[p1][n][i1]     = acc2[rt][nt][0];
                S.u.yt[p1][n + 1][i1] = acc2[rt][nt][1];
                S.u.yt[p2][n][i2]     = acc2[rt][nt][2];
                S.u.yt[p2][n + 1][i2] = acc2[rt][nt][3];
            }
        }
    }
    __syncthreads();
    if (ks == 1) {
        #pragma unroll
        for (int rt = 0; rt < 2; rt++) {
            int r1 = m0 + rt * 16 + rl, r2 = r1 + 8;
            int p1 = r1 >> 6, i1 = r1 & 63, p2 = r2 >> 6, i2 = r2 & 63;
            #pragma unroll
            for (int nt = 0; nt < 8; nt++) {
                int n = nt * 8 + kq;
                S.u.yt[p1][n][i1]     += acc2[rt][nt][0];
                S.u.yt[p1][n + 1][i1] += acc2[rt][nt][1];
                S.u.yt[p2][n][i2]     += acc2[rt][nt][2];
                S.u.yt[p2][n + 1][i2] += acc2[rt][nt][3];
            }
        }
    }
    __syncthreads();

    // layer-2 aggregation + bias + relu + partial node-sum
    {
        int pl = tid >> 7, rest = tid & 127;
        int d = rest & 63, g = rest >> 6;
        float bb = b2p[d];
        float part = 0.f;
        for (int n = g * 25; n < g * 25 + 25; n++) {
            int b0 = S.eo[n], e0 = S.eo[n + 1];
            float s = 0.f;
            for (int q = b0; q < e0; q++)
                s += S.u.yt[pl][d][S.gs[q]] * S.gc[pl][q];
            part += fmaxf(S.sni[pl][n] * s + bb, 0.f);
        }
        S.sb1[tid] = part;
    }
    __syncthreads();
    if (tid < 128) {
        int pl = tid >> 6, d = tid & 63;
        float s = S.sb1[pl * 128 + d] + S.sb1[pl * 128 + 64 + d];
        g_readout[(2 * b + pl) * ROD + d] = s * (1.f / NN);
    }
}

// ---------------- mesh stage ----------------
__global__ void k_mcount(const float* __restrict__ mew, const int* __restrict__ med) {
    int e = blockIdx.x * 256 + threadIdx.x;
    if (e < NEM) {
        int s = med[2 * e], d = med[2 * e + 1];
        float w = mew[e];
        atomicAdd(&g_mcnt[d], 1);
        atomicAdd(&g_degi[d], w);
        atomicAdd(&g_dego[s], w);
    }
}

__global__ void k_scan_norm() {
    __shared__ int sp[256];
    int t = threadIdx.x, base = t * 16;
    int s = 0;
    #pragma unroll
    for (int i = 0; i < 16; i++) s += g_mcnt[base + i];
    sp[t] = s; __syncthreads();
    if (t == 0) { int run = 0; for (int i = 0; i < 256; i++) { int v = sp[i]; sp[i] = run; run += v; } }
    __syncthreads();
    int run = sp[t];
    #pragma unroll
    for (int i = 0; i < 16; i++) {
        int v = g_mcnt[base + i];
        g_moff[base + i] = run; g_mcnt[base + i] = run; run += v;
    }
    if (t == 255) g_moff[NP] = NEM;
    #pragma unroll
    for (int i = 0; i < 16; i++) {
        int idx = base + i;
        float a = g_degi[idx], b = g_dego[idx];
        g_nim[idx] = (a > 0.f) ? rsqrtf(a) : 1.f;
        g_nom[idx] = (b > 0.f) ? rsqrtf(b) : 1.f;
    }
}

__global__ void k_mscatter_prep(const float* __restrict__ mew, const int* __restrict__ med) {
    int e = blockIdx.x * 256 + threadIdx.x;
    if (e < NEM) {
        int s = med[2 * e], d = med[2 * e + 1];
        int pos = atomicAdd(&g_mcnt[d], 1);
        g_msrc[pos]  = s;
        g_mcoef[pos] = mew[e] * g_nom[s];
    }
}

// 512 CTAs x 8 rows
__global__ void k_mgc1(const float* __restrict__ W1m, const float* __restrict__ b1m) {
    extern __shared__ float smf[];
    float* sW = smf;                 // 64*256
    float* sA = smf + ROD * HIDD;    // 8*64
    int tid = threadIdx.x, p0 = blockIdx.x * 8;
    for (int i = tid; i < ROD * HIDD; i += 256) sW[i] = W1m[i];
    for (int i = tid; i < 8 * ROD; i += 256) sA[i] = 0.f;
    __syncthreads();
    int d = tid & 63, qo = tid >> 6;
    for (int r = 0; r < 8; r++) {
        int t = p0 + r;
        int b = g_moff[t], en = g_moff[t + 1];
        float acc = 0.f;
        for (int q = b + qo; q < en; q += 4)
            acc += g_readout[g_msrc[q] * ROD + d] * g_mcoef[q];
        atomicAdd(&sA[r * ROD + d], acc);
    }
    __syncthreads();
    for (int i = tid; i < 8 * ROD; i += 256) sA[i] *= g_nim[p0 + (i >> 6)];
    __syncthreads();
    float acc[8];
    #pragma unroll
    for (int r = 0; r < 8; r++) acc[r] = 0.f;
    #pragma unroll 2
    for (int k = 0; k < ROD; k++) {
        float wv = sW[k * HIDD + tid];
        #pragma unroll
        for (int r = 0; r < 8; r++) acc[r] = fmaf(sA[r * ROD + k], wv, acc[r]);
    }
    float bb = b1m[tid];
    #pragma unroll
    for (int r = 0; r < 8; r++)
        g_h1m[(p0 + r) * HIDD + tid] = fmaxf(acc[r] + bb, 0.f);
}

// 512 threads
__global__ void k_mgc2(const float* __restrict__ W2m, const float* __restrict__ b2m,
                       const float* __restrict__ Wu1, const float* __restrict__ bu1) {
    extern __shared__ float smf[];
    float* sA = smf;              // 16*256
    float* sH = smf + 16 * HIDD;  // 16*256
    int tid = threadIdx.x, p0 = blockIdx.x * 16;
    int f = tid & 255, rg = tid >> 8;

    #pragma unroll
    for (int r8 = 0; r8 < 8; r8++) {
        int r = rg * 8 + r8, t = p0 + r;
        int b = g_moff[t], en = g_moff[t + 1];
        float acc = 0.f;
        #pragma unroll 2
        for (int q = b; q < en; q++)
            acc += g_h1m[g_msrc[q] * HIDD + f] * g_mcoef[q];
        sA[r * HIDD + f] = acc * g_nim[t];
    }
    __syncthreads();
    {
        float acc[8];
        #pragma unroll
        for (int r = 0; r < 8; r++) acc[r] = 0.f;
        #pragma unroll 2
        for (int k = 0; k < HIDD; k++) {
            float wv = __ldg(&W2m[k * HIDD + f]);
            #pragma unroll
            for (int r = 0; r < 8; r++)
                acc[r] = fmaf(sA[(rg * 8 + r) * HIDD + k], wv, acc[r]);
        }
        float bb = b2m[f];
        #pragma unroll
        for (int r = 0; r < 8; r++)
            sH[(rg * 8 + r) * HIDD + f] = fmaxf(acc[r] + bb, 0.f);
    }
    __syncthreads();
    {
        int m = tid & 127, grp = tid >> 7;
        float acc[4];
        #pragma unroll
        for (int r = 0; r < 4; r++) acc[r] = 0.f;
        #pragma unroll 2
        for (int k = 0; k < HIDD; k++) {
            float wv = __ldg(&Wu1[k * RHD + m]);
            #pragma unroll
            for (int r = 0; r < 4; r++)
                acc[r] = fmaf(sH[(grp * 4 + r) * HIDD + k], wv, acc[r]);
        }
        float bb = bu1[m];
        float s = 0.f;
        #pragma unroll
        for (int r = 0; r < 4; r++) s += fmaxf(acc[r] + bb, 0.f);
        atomicAdd(&g_r[m], s);
    }
}

__global__ void k_final(const float* __restrict__ Wout, const float* __restrict__ bout,
                        float* __restrict__ out) {
    int o = threadIdx.x;
    if (o < OUTD) {
        float s = bout[o];
        for (int j = 0; j < RHD; j++) s = fmaf(g_r[j], Wout[j * OUTD + o], s);
        out[o] = s;
    }
}

// ---------------- launch ----------------
extern "C" void kernel_launch(void* const* d_in, const int* in_sizes, int n_in,
                              void* d_out, int out_size) {
    const float* feats = (const float*)d_in[0];
    const float* pew   = (const float*)d_in[1];
    const float* mew   = (const float*)d_in[2];
    const float* W1p   = (const float*)d_in[3];
    const float* b1p   = (const float*)d_in[4];
    const float* W2p   = (const float*)d_in[5];
    const float* b2p   = (const float*)d_in[6];
    const float* W1m   = (const float*)d_in[7];
    const float* b1m   = (const float*)d_in[8];
    const float* W2m   = (const float*)d_in[9];
    const float* b2m   = (const float*)d_in[10];
    const float* Wu1   = (const float*)d_in[11];
    const float* bu1   = (const float*)d_in[12];
    const float* Wout  = (const float*)d_in[13];
    const float* bout  = (const float*)d_in[14];
    const int*   pedg  = (const int*)d_in[15];
    const int*   medg  = (const int*)d_in[16];

    cudaFuncSetAttribute(k_mgc1, cudaFuncAttributeMaxDynamicSharedMemorySize, 67584);

    k_csr<<<1, 256>>>(pedg);
    k_wprep<<<64, 256>>>(W1p, W2p);
    k_mcount<<<NEM / 256, 256>>>(mew, medg);
    k_mlp<<<NP / 2, 256>>>(feats, pew, pedg, b1p, b2p);   // ncu capture slot (#4)
    k_scan_norm<<<1, 256>>>();
    k_mscatter_prep<<<NEM / 256, 256>>>(mew, medg);
    k_mgc1<<<NP / 8, 256, 67584>>>(W1m, b1m);
    k_mgc2<<<NP / 16, 512, 32768>>>(W2m, b2m, Wu1, bu1);
    k_final<<<1, 32>>>(Wout, bout, (float*)d_out);
}

// round 17
// speedup vs baseline: 2.3485x; 1.0654x over previous
#include <cuda_runtime.h>
#include <cuda_bf16.h>
#include <cstdint>

#define NP   4096
#define NN   50
#define NE   250
#define NEM  65536
#define IND  32
#define PHD  512
#define ROD  64
#define HIDD 256
#define RHD  128
#define OUTD 15

// ---------------- persistent device scratch ----------------
__device__ float g_readout[NP * ROD];
__device__ float g_degi[NP], g_dego[NP], g_nim[NP], g_nom[NP];
__device__ float g_h1m[NP * HIDD];
__device__ float g_r[RHD];
__device__ int   g_poff[NN + 1];
__device__ int   g_peid[NE];
__device__ int   g_gsrc[NE];
__device__ int   g_mcnt[NP];
__device__ int   g_moff[NP + 1];
__device__ int   g_msrc[NEM];
__device__ float g_mcoef[NEM];
// fragment-packed weights, uint4 = {hi_reg0, hi_reg1, lo_reg0, lo_reg1}
__device__ uint4 g_w1f4[64 * 2 * 32];     // W1: [nt][kt][lane]
__device__ uint4 g_w2f4[8 * 32 * 32];     // W2: [nt][kt][lane]

// ---------------- helpers ----------------
__device__ __forceinline__ uint32_t pkbf(__nv_bfloat16 a, __nv_bfloat16 b) {
    unsigned short ua = *(unsigned short*)&a, ub = *(unsigned short*)&b;
    return ((uint32_t)ub << 16) | (uint32_t)ua;
}
__device__ __forceinline__ void split2(float x0, float x1, uint32_t& hi, uint32_t& lo) {
    __nv_bfloat16 h0 = __float2bfloat16(x0), h1 = __float2bfloat16(x1);
    __nv_bfloat16 l0 = __float2bfloat16(x0 - __bfloat162float(h0));
    __nv_bfloat16 l1 = __float2bfloat16(x1 - __bfloat162float(h1));
    hi = pkbf(h0, h1); lo = pkbf(l0, l1);
}
__device__ __forceinline__ uint32_t cvt2(float xlo, float xhi) {
    uint32_t r;
    asm("cvt.rn.bf16x2.f32 %0, %1, %2;" : "=r"(r) : "f"(xhi), "f"(xlo));
    return r;
}
__device__ __forceinline__ void mma16816(float* c, const uint32_t* a, const uint32_t* b) {
    asm volatile("mma.sync.aligned.m16n8k16.row.col.f32.bf16.bf16.f32 "
        "{%0,%1,%2,%3}, {%4,%5,%6,%7}, {%8,%9}, {%0,%1,%2,%3};"
        : "+f"(c[0]), "+f"(c[1]), "+f"(c[2]), "+f"(c[3])
        : "r"(a[0]), "r"(a[1]), "r"(a[2]), "r"(a[3]), "r"(b[0]), "r"(b[1]));
}

// ---------------- setup kernels ----------------
__global__ void k_csr(const int* __restrict__ pedges) {
    __shared__ int sdst[NE], ssrc[NE], cnt[NN], off[NN + 1];
    int tid = threadIdx.x;
    for (int e = tid; e < NE; e += 256) {
        ssrc[e] = pedges[2 * e];
        sdst[e] = pedges[2 * e + 1];
    }
    if (tid < NN) cnt[tid] = 0;
    __syncthreads();
    for (int e = tid; e < NE; e += 256) atomicAdd(&cnt[sdst[e]], 1);
    __syncthreads();
    if (tid == 0) {
        int run = 0;
        for (int n = 0; n < NN; n++) { off[n] = run; run += cnt[n]; }
        off[NN] = run;
    }
    __syncthreads();
    if (tid <= NN) g_poff[tid] = off[tid];
    if (tid < NE) {
        int d = sdst[tid], rank = 0;
        for (int e2 = 0; e2 < tid; e2++) rank += (sdst[e2] == d);
        int pos = off[d] + rank;
        g_peid[pos] = tid;
        g_gsrc[pos] = ssrc[tid];
    }
}

__global__ void k_wprep(const float* __restrict__ W1p, const float* __restrict__ W2p) {
    int i = blockIdx.x * 256 + threadIdx.x;    // grid 64 -> 16384
    if (i < 4096) {
        int lane = i & 31, kt = (i >> 5) & 1, nt = i >> 6;
        int n = nt * 8 + (lane >> 2);
        int k0 = kt * 16 + (lane & 3) * 2;
        uint32_t h0, l0, h1, l1;
        split2(W1p[k0 * PHD + n],       W1p[(k0 + 1) * PHD + n], h0, l0);
        split2(W1p[(k0 + 8) * PHD + n], W1p[(k0 + 9) * PHD + n], h1, l1);
        g_w1f4[i] = make_uint4(h0, h1, l0, l1);
    } else if (i < 4096 + 8192) {
        int j = i - 4096;
        int lane = j & 31, kt = (j >> 5) & 31, nt = j >> 10;
        int n = nt * 8 + (lane >> 2);
        int k0 = kt * 16 + (lane & 3) * 2;
        uint32_t h0, l0, h1, l1;
        split2(W2p[k0 * ROD + n],       W2p[(k0 + 1) * ROD + n], h0, l0);
        split2(W2p[(k0 + 8) * ROD + n], W2p[(k0 + 9) * ROD + n], h1, l1);
        g_w2f4[j] = make_uint4(h0, h1, l0, l1);
    }
    if (i < NP) { g_mcnt[i] = 0; g_degi[i] = 0.f; g_dego[i] = 0.f; }
    if (i < RHD) g_r[i] = 0.f;
}

// ---------------- fused agg1 + MLP + layer-2 aggregation + readout (2 patches/CTA) ----------------
// n-split: warp = (rg: 32 rows) x (nh: half of GEMM1 cols / GEMM2 n); h1 frags via smem.
// Scratch region UBUF (33792 B) is time-multiplexed (barriers separate uses):
//   phase A : sagg[128*32] floats @0  |  x[2][NN*32] floats @16384
//   mainloop: a2buf[4][2][4][32] uint4 @0
//   epilogue: yt[2][64][66] floats @0
#define UBUF_BYTES 33792

__global__ void __launch_bounds__(256, 3) k_mlp(const float* __restrict__ feats,
                                                const float* __restrict__ pew,
                                                const int* __restrict__ pedges,
                                                const float* __restrict__ b1p,
                                                const float* __restrict__ b2p) {
    __shared__ float sb1[PHD];               // reused as partial buffer at the end
    __shared__ int   gs[NE];
    __shared__ int   eo[NN + 2];
    __shared__ float gc[2][256];
    __shared__ float sni[2][ROD];            // degree accum, then rsqrt
    __shared__ int   eid[NE];                // phase-A
    __shared__ float coef[2][NE];            // phase-A
    __shared__ float no_[2][NN];             // phase-A
    __shared__ __align__(16) char ubuf[UBUF_BYTES];

    float* sagg = (float*)ubuf;                      // [128][IND]
    float* xx   = (float*)(ubuf + 16384);            // [2][NN*IND]
    uint4* a2b  = (uint4*)ubuf;                      // [rg][rt][ktl][lane]
    float* yt   = (float*)ubuf;                      // [pl][64][66]

    const int tid = threadIdx.x, lane = tid & 31, wid = tid >> 5;
    const int b = blockIdx.x;
    const int rg = wid & 3, nh = wid >> 2;
    const int m0 = rg * 32;
    const int rl = lane >> 2;
    const int kq = (lane & 3) * 2;

    // ---- phase A: graph setup + layer-1 aggregation (both patches) ----
    for (int q = tid; q < NE; q += 256) {
        gs[q]  = g_gsrc[q];
        eid[q] = g_peid[q];
    }
    for (int i = tid; i <= NN; i += 256) eo[i] = g_poff[i];
    for (int i = tid; i < PHD; i += 256) sb1[i] = b1p[i];
    for (int i = tid; i < 2 * NE; i += 256) {
        int pl = (i >= NE), e = pl ? i - NE : i;
        coef[pl][e] = pew[(2 * b + pl) * NE + e];
    }
    for (int i = tid; i < 2 * NN * IND; i += 256) {
        int pl = (i >= NN * IND), j = pl ? i - NN * IND : i;
        xx[pl * NN * IND + j] = feats[(2 * b + pl) * NN * IND + j];
    }
    if (tid < 128) {
        int pl = tid >> 6, n = tid & 63;
        sni[pl][n] = 0.f;
        if (n < NN) no_[pl][n] = 0.f;
    }
    __syncthreads();
    for (int i = tid; i < 2 * NE; i += 256) {
        int pl = (i >= NE), e = pl ? i - NE : i;
        float w = coef[pl][e];
        atomicAdd(&sni[pl][pedges[2 * e + 1]], w);
        atomicAdd(&no_[pl][pedges[2 * e]], w);
    }
    __syncthreads();
    if (tid < 128) {
        int pl = tid >> 6, n = tid & 63;
        if (n < NN) {
            float a = sni[pl][n], c = no_[pl][n];
            sni[pl][n] = (a > 0.f) ? rsqrtf(a) : 1.f;
            no_[pl][n] = (c > 0.f) ? rsqrtf(c) : 1.f;
        }
    }
    __syncthreads();
    for (int i = tid; i < 2 * NE; i += 256) {
        int pl = (i >= NE), q = pl ? i - NE : i;
        gc[pl][q] = coef[pl][eid[q]] * no_[pl][gs[q]];
    }
    __syncthreads();
    for (int i = tid; i < 128 * IND; i += 256) {
        int row = i >> 5, d = i & 31;
        int pl = row >> 6, n = row & 63;
        float s = 0.f;
        if (n < NN) {
            int b0 = eo[n], e0 = eo[n + 1];
            for (int q = b0; q < e0; q++)
                s += xx[pl * NN * IND + gs[q] * IND + d] * gc[pl][q];
            s *= sni[pl][n];
        }
        sagg[i] = s;
    }
    __syncthreads();

    // ---- A1 fragments, hi only, 2 row-tiles ----
    uint32_t a1[2][2][4];   // [rt][kt][reg]
    #pragma unroll
    for (int rt = 0; rt < 2; rt++)
        #pragma unroll
        for (int kt = 0; kt < 2; kt++)
            #pragma unroll
            for (int j = 0; j < 4; j++) {
                int rr = m0 + rt * 16 + rl + (j & 1) * 8;
                int kk = kt * 16 + kq + (j >> 1) * 8;
                a1[rt][kt][j] = cvt2(sagg[rr * IND + kk], sagg[rr * IND + kk + 1]);
            }
    __syncthreads();   // all sagg/x reads complete before a2b overwrites the buffer

    float acc2[2][4][4];   // [rt][nt'][reg] -- 32 regs
    #pragma unroll
    for (int rt = 0; rt < 2; rt++)
        #pragma unroll
        for (int nt = 0; nt < 4; nt++)
            #pragma unroll
            for (int j = 0; j < 4; j++) acc2[rt][nt][j] = 0.f;

    for (int c = 0; c < 8; c++) {
        // ---- GEMM1: this warp's 4 col-groups (nh half) -> smem a2 fragments ----
        #pragma unroll
        for (int ktl2 = 0; ktl2 < 2; ktl2++) {
            uint32_t afr[2][4];
            #pragma unroll
            for (int half = 0; half < 2; half++) {
                int ntl = nh * 4 + ktl2 * 2 + half;
                int nt = c * 8 + ntl;
                float acc[2][4] = {{0.f, 0.f, 0.f, 0.f}, {0.f, 0.f, 0.f, 0.f}};
                #pragma unroll
                for (int kt = 0; kt < 2; kt++) {
                    uint4 w = g_w1f4[(nt * 2 + kt) * 32 + lane];
                    uint32_t bh[2] = {w.x, w.y}, bl[2] = {w.z, w.w};
                    mma16816(acc[0], a1[0][kt], bh);
                    mma16816(acc[0], a1[0][kt], bl);
                    mma16816(acc[1], a1[1][kt], bh);
                    mma16816(acc[1], a1[1][kt], bl);
                }
                int nbase = c * 64 + ntl * 8 + kq;
                float b0 = sb1[nbase], b1 = sb1[nbase + 1];
                #pragma unroll
                for (int rt = 0; rt < 2; rt++) {
                    float f0 = fmaxf(acc[rt][0] + b0, 0.f);
                    float f1 = fmaxf(acc[rt][1] + b1, 0.f);
                    float f2 = fmaxf(acc[rt][2] + b0, 0.f);
                    float f3 = fmaxf(acc[rt][3] + b1, 0.f);
                    afr[rt][2 * half]     = cvt2(f0, f1);
                    afr[rt][2 * half + 1] = cvt2(f2, f3);
                }
            }
            int ktl = nh * 2 + ktl2;
            a2b[((rg * 2 + 0) * 4 + ktl) * 32 + lane] =
                make_uint4(afr[0][0], afr[0][1], afr[0][2], afr[0][3]);
            a2b[((rg * 2 + 1) * 4 + ktl) * 32 + lane] =
                make_uint4(afr[1][0], afr[1][1], afr[1][2], afr[1][3]);
        }
        __syncthreads();

        // ---- GEMM2: all 4 ktl fragments (both halves) x this warp's 4 n-tiles ----
        #pragma unroll
        for (int ktl = 0; ktl < 4; ktl++) {
            uint4 v0 = a2b[((rg * 2 + 0) * 4 + ktl) * 32 + lane];
            uint4 v1 = a2b[((rg * 2 + 1) * 4 + ktl) * 32 + lane];
            uint32_t a2r0[4] = {v0.x, v0.y, v0.z, v0.w};
            uint32_t a2r1[4] = {v1.x, v1.y, v1.z, v1.w};
            int kt = c * 4 + ktl;
            #pragma unroll
            for (int ntp = 0; ntp < 4; ntp++) {
                int nt = nh * 4 + ntp;
                uint4 w = g_w2f4[(nt * 32 + kt) * 32 + lane];
                uint32_t bh[2] = {w.x, w.y}, bl[2] = {w.z, w.w};
                mma16816(acc2[0][ntp], a2r0, bh);
                mma16816(acc2[0][ntp], a2r0, bl);
                mma16816(acc2[1][ntp], a2r1, bh);
                mma16816(acc2[1][ntp], a2r1, bl);
            }
        }
        __syncthreads();
    }

    // ---- write y into transposed smem [patch][col][node] (each warp owns its block) ----
    #pragma unroll
    for (int rt = 0; rt < 2; rt++) {
        int r1 = m0 + rt * 16 + rl, r2 = r1 + 8;
        int p1 = r1 >> 6, i1 = r1 & 63, p2 = r2 >> 6, i2 = r2 & 63;
        #pragma unroll
        for (int ntp = 0; ntp < 4; ntp++) {
            int n = (nh * 4 + ntp) * 8 + kq;
            yt[(p1 * ROD + n) * 66 + i1]       = acc2[rt][ntp][0];
            yt[(p1 * ROD + n + 1) * 66 + i1]   = acc2[rt][ntp][1];
            yt[(p2 * ROD + n) * 66 + i2]       = acc2[rt][ntp][2];
            yt[(p2 * ROD + n + 1) * 66 + i2]   = acc2[rt][ntp][3];
        }
    }
    __syncthreads();

    // layer-2 aggregation + bias + relu + partial node-sum
    {
        int pl = tid >> 7, rest = tid & 127;
        int d = rest & 63, g = rest >> 6;
        float bb = b2p[d];
        float part = 0.f;
        for (int n = g * 25; n < g * 25 + 25; n++) {
            int b0 = eo[n], e0 = eo[n + 1];
            float s = 0.f;
            for (int q = b0; q < e0; q++)
                s += yt[(pl * ROD + d) * 66 + gs[q]] * gc[pl][q];
            part += fmaxf(sni[pl][n] * s + bb, 0.f);
        }
        sb1[tid] = part;
    }
    __syncthreads();
    if (tid < 128) {
        int pl = tid >> 6, d = tid & 63;
        float s = sb1[pl * 128 + d] + sb1[pl * 128 + 64 + d];
        g_readout[(2 * b + pl) * ROD + d] = s * (1.f / NN);
    }
}

// ---------------- mesh stage ----------------
__global__ void k_mcount(const float* __restrict__ mew, const int* __restrict__ med) {
    int e = blockIdx.x * 256 + threadIdx.x;
    if (e < NEM) {
        int s = med[2 * e], d = med[2 * e + 1];
        float w = mew[e];
        atomicAdd(&g_mcnt[d], 1);
        atomicAdd(&g_degi[d], w);
        atomicAdd(&g_dego[s], w);
    }
}

__global__ void k_scan_norm() {
    __shared__ int sp[256];
    int t = threadIdx.x, base = t * 16;
    int s = 0;
    #pragma unroll
    for (int i = 0; i < 16; i++) s += g_mcnt[base + i];
    sp[t] = s; __syncthreads();
    if (t == 0) { int run = 0; for (int i = 0; i < 256; i++) { int v = sp[i]; sp[i] = run; run += v; } }
    __syncthreads();
    int run = sp[t];
    #pragma unroll
    for (int i = 0; i < 16; i++) {
        int v = g_mcnt[base + i];
        g_moff[base + i] = run; g_mcnt[base + i] = run; run += v;
    }
    if (t == 255) g_moff[NP] = NEM;
    #pragma unroll
    for (int i = 0; i < 16; i++) {
        int idx = base + i;
        float a = g_degi[idx], b = g_dego[idx];
        g_nim[idx] = (a > 0.f) ? rsqrtf(a) : 1.f;
        g_nom[idx] = (b > 0.f) ? rsqrtf(b) : 1.f;
    }
}

__global__ void k_mscatter_prep(const float* __restrict__ mew, const int* __restrict__ med) {
    int e = blockIdx.x * 256 + threadIdx.x;
    if (e < NEM) {
        int s = med[2 * e], d = med[2 * e + 1];
        int pos = atomicAdd(&g_mcnt[d], 1);
        g_msrc[pos]  = s;
        g_mcoef[pos] = mew[e] * g_nom[s];
    }
}

// 512 CTAs x 8 rows
__global__ void k_mgc1(const float* __restrict__ W1m, const float* __restrict__ b1m) {
    extern __shared__ float smf[];
    float* sW = smf;                 // 64*256
    float* sA = smf + ROD * HIDD;    // 8*64
    int tid = threadIdx.x, p0 = blockIdx.x * 8;
    for (int i = tid; i < ROD * HIDD; i += 256) sW[i] = W1m[i];
    for (int i = tid; i < 8 * ROD; i += 256) sA[i] = 0.f;
    __syncthreads();
    int d = tid & 63, qo = tid >> 6;
    for (int r = 0; r < 8; r++) {
        int t = p0 + r;
        int b = g_moff[t], en = g_moff[t + 1];
        float acc = 0.f;
        for (int q = b + qo; q < en; q += 4)
            acc += g_readout[g_msrc[q] * ROD + d] * g_mcoef[q];
        atomicAdd(&sA[r * ROD + d], acc);
    }
    __syncthreads();
    for (int i = tid; i < 8 * ROD; i += 256) sA[i] *= g_nim[p0 + (i >> 6)];
    __syncthreads();
    float acc[8];
    #pragma unroll
    for (int r = 0; r < 8; r++) acc[r] = 0.f;
    #pragma unroll 2
    for (int k = 0; k < ROD; k++) {
        float wv = sW[k * HIDD + tid];
        #pragma unroll
        for (int r = 0; r < 8; r++) acc[r] = fmaf(sA[r * ROD + k], wv, acc[r]);
    }
    float bb = b1m[tid];
    #pragma unroll
    for (int r = 0; r < 8; r++)
        g_h1m[(p0 + r) * HIDD + tid] = fmaxf(acc[r] + bb, 0.f);
}

// 512 threads
__global__ void k_mgc2(const float* __restrict__ W2m, const float* __restrict__ b2m,
                       const float* __restrict__ Wu1, const float* __restrict__ bu1) {
    extern __shared__ float smf[];
    float* sA = smf;              // 16*256
    float* sH = smf + 16 * HIDD;  // 16*256
    int tid = threadIdx.x, p0 = blockIdx.x * 16;
    int f = tid & 255, rg = tid >> 8;

    #pragma unroll
    for (int r8 = 0; r8 < 8; r8++) {
        int r = rg * 8 + r8, t = p0 + r;
        int b = g_moff[t], en = g_moff[t + 1];
        float acc = 0.f;
        #pragma unroll 2
        for (int q = b; q < en; q++)
            acc += g_h1m[g_msrc[q] * HIDD + f] * g_mcoef[q];
        sA[r * HIDD + f] = acc * g_nim[t];
    }
    __syncthreads();
    {
        float acc[8];
        #pragma unroll
        for (int r = 0; r < 8; r++) acc[r] = 0.f;
        #pragma unroll 2
        for (int k = 0; k < HIDD; k++) {
            float wv = __ldg(&W2m[k * HIDD + f]);
            #pragma unroll
            for (int r = 0; r < 8; r++)
                acc[r] = fmaf(sA[(rg * 8 + r) * HIDD + k], wv, acc[r]);
        }
        float bb = b2m[f];
        #pragma unroll
        for (int r = 0; r < 8; r++)
            sH[(rg * 8 + r) * HIDD + f] = fmaxf(acc[r] + bb, 0.f);
    }
    __syncthreads();
    {
        int m = tid & 127, grp = tid >> 7;
        float acc[4];
        #pragma unroll
        for (int r = 0; r < 4; r++) acc[r] = 0.f;
        #pragma unroll 2
        for (int k = 0; k < HIDD; k++) {
            float wv = __ldg(&Wu1[k * RHD + m]);
            #pragma unroll
            for (int r = 0; r < 4; r++)
                acc[r] = fmaf(sH[(grp * 4 + r) * HIDD + k], wv, acc[r]);
        }
        float bb = bu1[m];
        float s = 0.f;
        #pragma unroll
        for (int r = 0; r < 4; r++) s += fmaxf(acc[r] + bb, 0.f);
        atomicAdd(&g_r[m], s);
    }
}

__global__ void k_final(const float* __restrict__ Wout, const float* __restrict__ bout,
                        float* __restrict__ out) {
    int o = threadIdx.x;
    if (o < OUTD) {
        float s = bout[o];
        for (int j = 0; j < RHD; j++) s = fmaf(g_r[j], Wout[j * OUTD + o], s);
        out[o] = s;
    }
}

// ---------------- launch ----------------
extern "C" void kernel_launch(void* const* d_in, const int* in_sizes, int n_in,
                              void* d_out, int out_size) {
    const float* feats = (const float*)d_in[0];
    const float* pew   = (const float*)d_in[1];
    const float* mew   = (const float*)d_in[2];
    const float* W1p   = (const float*)d_in[3];
    const float* b1p   = (const float*)d_in[4];
    const float* W2p   = (const float*)d_in[5];
    const float* b2p   = (const float*)d_in[6];
    const float* W1m   = (const float*)d_in[7];
    const float* b1m   = (const float*)d_in[8];
    const float* W2m   = (const float*)d_in[9];
    const float* b2m   = (const float*)d_in[10];
    const float* Wu1   = (const float*)d_in[11];
    const float* bu1   = (const float*)d_in[12];
    const float* Wout  = (const float*)d_in[13];
    const float* bout  = (const float*)d_in[14];
    const int*   pedg  = (const int*)d_in[15];
    const int*   medg  = (const int*)d_in[16];

    cudaFuncSetAttribute(k_mgc1, cudaFuncAttributeMaxDynamicSharedMemorySize, 67584);

    k_csr<<<1, 256>>>(pedg);
    k_wprep<<<64, 256>>>(W1p, W2p);
    k_mcount<<<NEM / 256, 256>>>(mew, medg);
    k_mlp<<<NP / 2, 256>>>(feats, pew, pedg, b1p, b2p);   // ncu capture slot (#4)
    k_scan_norm<<<1, 256>>>();
    k_mscatter_prep<<<NEM / 256, 256>>>(mew, medg);
    k_mgc1<<<NP / 8, 256, 67584>>>(W1m, b1m);
    k_mgc2<<<NP / 16, 512, 32768>>>(W2m, b2m, Wu1, bu1);
    k_final<<<1, 32>>>(Wout, bout, (float*)d_out);
}